// round 1
// baseline (speedup 1.0000x reference)
#include <cuda_runtime.h>

#define DM 256
#define KI 32
#define HN 4
#define DK 64
#define ZB 2
#define NN 2048
#define ZN (ZB*NN)          /* 4096  */
#define ETOT (ZN*KI)        /* 131072 */
#define TILE 32

// ---------------- scratch (static device globals: no runtime allocation) ----
__device__ float g_Q[(size_t)ZN * DM];        // 4 MB
__device__ float g_K[(size_t)ETOT * DM];      // 134 MB
__device__ float g_V[(size_t)ETOT * DM];      // 134 MB
__device__ float g_attn[(size_t)ZN * DM];     // 4 MB
__device__ float g_WoT[DM * DM];
__device__ int   g_mflag;

#define FMA_ROW(ACCI, A, W0, W1) \
    do { \
        (ACCI)[0] += (A)*(W0).x; (ACCI)[1] += (A)*(W0).y; \
        (ACCI)[2] += (A)*(W0).z; (ACCI)[3] += (A)*(W0).w; \
        (ACCI)[4] += (A)*(W1).x; (ACCI)[5] += (A)*(W1).y; \
        (ACCI)[6] += (A)*(W1).z; (ACCI)[7] += (A)*(W1).w; \
    } while (0)

// ---------------- mask dtype detection (bool8 / int32 / float32) ------------
__global__ void detect_mask_kernel(const void* mask, int count) {
    if (threadIdx.x != 0 || blockIdx.x != 0) return;
    const unsigned int* u  = (const unsigned int*)mask;
    const float*        fp = (const float*)mask;
    int words = count / 4;               // safe bound for any of the 3 dtypes
    int lim = words < 1024 ? words : 1024;
    bool int_ok = true, int_one = false, flt_ok = true, flt_one = false;
    for (int i = 0; i < lim; i++) {
        unsigned int v = u[i];
        if (v > 1u)  int_ok = false;
        if (v == 1u) int_one = true;
        float fv = fp[i];
        if (fv != 0.0f && fv != 1.0f) flt_ok = false;
        if (fv == 1.0f) flt_one = true;
    }
    int flag;
    if (int_ok && int_one)      flag = 1;   // int32 {0,1}
    else if (flt_ok && flt_one) flag = 0;   // float32 {0.0,1.0}
    else                        flag = 2;   // bool8 (1 byte per element)
    g_mflag = flag;
}

// ---------------- out_W transpose: g_WoT[c][d] = out_W[d][c] ----------------
__global__ void transpose_w_kernel(const float* __restrict__ W) {
    int idx = blockIdx.x * blockDim.x + threadIdx.x;
    if (idx < DM * DM) {
        int d = idx >> 8;
        int c = idx & (DM - 1);
        g_WoT[c * DM + d] = W[idx];
    }
}

// ---------------- Q projection: g_Q[zn][h*64+e] = nodes_i @ q_proj + qb -----
__global__ __launch_bounds__(256) void qproj_kernel(
    const float* __restrict__ x, const float* __restrict__ qp,
    const float* __restrict__ qb)
{
    __shared__ float s_x[TILE * DM];
    const int tid = threadIdx.x;
    const int tx = tid & 31, ty = tid >> 5;
    const int c0 = tx * 8, r0 = ty * 4;
    const size_t rbase = (size_t)blockIdx.x * TILE;
    {
        const float4* xg = (const float4*)(x + rbase * DM);
        float4* sx = (float4*)s_x;
        #pragma unroll
        for (int i = 0; i < 8; i++) sx[tid + i * 256] = xg[tid + i * 256];
    }
    __syncthreads();

    float acc[4][8];
    #pragma unroll
    for (int i = 0; i < 4; i++)
        #pragma unroll
        for (int j = 0; j < 8; j++) acc[i][j] = 0.f;

    const int head = c0 >> 6, e0 = c0 & 63;
    const float* Wh = qp + head * DM * DK + e0;
    for (int k = 0; k < DM; k += 4) {
        float4 av[4];
        #pragma unroll
        for (int i = 0; i < 4; i++)
            av[i] = *(const float4*)(s_x + (r0 + i) * DM + k);
        #pragma unroll
        for (int kk = 0; kk < 4; kk++) {
            float4 w0 = *(const float4*)(Wh + (size_t)(k + kk) * DK);
            float4 w1 = *(const float4*)(Wh + (size_t)(k + kk) * DK + 4);
            #pragma unroll
            for (int i = 0; i < 4; i++) {
                float a = (&av[i].x)[kk];
                FMA_ROW(acc[i], a, w0, w1);
            }
        }
    }
    #pragma unroll
    for (int i = 0; i < 4; i++) {
        float4 o0 = make_float4(acc[i][0] + qb[c0 + 0], acc[i][1] + qb[c0 + 1],
                                acc[i][2] + qb[c0 + 2], acc[i][3] + qb[c0 + 3]);
        float4 o1 = make_float4(acc[i][4] + qb[c0 + 4], acc[i][5] + qb[c0 + 5],
                                acc[i][6] + qb[c0 + 6], acc[i][7] + qb[c0 + 7]);
        *(float4*)(g_Q + (rbase + r0 + i) * DM + c0)     = o0;
        *(float4*)(g_Q + (rbase + r0 + i) * DM + c0 + 4) = o1;
    }
}

// ---------------- fused FiLM (K and V) + K/V head projections ---------------
__global__ __launch_bounds__(256, 1) void film_kv_kernel(
    const float* __restrict__ edges, const float* __restrict__ nodesj,
    const float* __restrict__ fkW1, const float* __restrict__ fkb1,
    const float* __restrict__ fkW2, const float* __restrict__ fkb2,
    const float* __restrict__ fvW1, const float* __restrict__ fvb1,
    const float* __restrict__ fvW2, const float* __restrict__ fvb2,
    const float* __restrict__ kproj, const float* __restrict__ kbias,
    const float* __restrict__ vproj, const float* __restrict__ vbias)
{
    extern __shared__ float sm[];
    float* s_e  = sm;                 // [32][256] edge tile
    float* s_nj = sm + TILE * DM;     // [32][256] nodes_j tile
    float* s_h  = sm + 2 * TILE * DM; // [32][256] hidden
    float* s_ki = sm + 3 * TILE * DM; // [32][256] film output

    const int tid = threadIdx.x;
    const int tx = tid & 31, ty = tid >> 5;
    const int c0 = tx * 8, r0 = ty * 4;
    const size_t ebase = (size_t)blockIdx.x * TILE;

    {
        const float4* eg = (const float4*)(edges + ebase * DM);
        const float4* ng = (const float4*)(nodesj + ebase * DM);
        float4* se = (float4*)s_e;
        float4* sn = (float4*)s_nj;
        #pragma unroll
        for (int i = 0; i < 8; i++) {
            se[tid + i * 256] = eg[tid + i * 256];
            sn[tid + i * 256] = ng[tid + i * 256];
        }
    }
    __syncthreads();

    #pragma unroll 1
    for (int f = 0; f < 2; f++) {
        const float* W1 = f ? fvW1 : fkW1;
        const float* b1 = f ? fvb1 : fkb1;
        const float* W2 = f ? fvW2 : fkW2;
        const float* b2 = f ? fvb2 : fkb2;
        const float* Wp = f ? vproj : kproj;
        const float* bp = f ? vbias : kbias;
        float* gout = f ? g_V : g_K;

        // ---- stage 1: h = silu(e @ W1 + b1) ----
        {
            float acc[4][8];
            #pragma unroll
            for (int i = 0; i < 4; i++)
                #pragma unroll
                for (int j = 0; j < 8; j++) acc[i][j] = 0.f;

            for (int k = 0; k < DM; k += 4) {
                float4 av[4];
                #pragma unroll
                for (int i = 0; i < 4; i++)
                    av[i] = *(const float4*)(s_e + (r0 + i) * DM + k);
                #pragma unroll
                for (int kk = 0; kk < 4; kk++) {
                    float4 w0 = *(const float4*)(W1 + (size_t)(k + kk) * DM + c0);
                    float4 w1 = *(const float4*)(W1 + (size_t)(k + kk) * DM + c0 + 4);
                    #pragma unroll
                    for (int i = 0; i < 4; i++) {
                        float a = (&av[i].x)[kk];
                        FMA_ROW(acc[i], a, w0, w1);
                    }
                }
            }
            #pragma unroll
            for (int i = 0; i < 4; i++)
                #pragma unroll
                for (int j = 0; j < 8; j++) {
                    float xv = acc[i][j] + b1[c0 + j];
                    s_h[(r0 + i) * DM + c0 + j] = xv / (1.0f + __expf(-xv));
                }
        }
        __syncthreads();

        // ---- stage 2: gb = h @ W2 + b2;  k_in = gamma * nj + beta ----
        {
            float ag[4][8], ab[4][8];
            #pragma unroll
            for (int i = 0; i < 4; i++)
                #pragma unroll
                for (int j = 0; j < 8; j++) { ag[i][j] = 0.f; ab[i][j] = 0.f; }

            for (int k = 0; k < DM; k += 4) {
                float4 av[4];
                #pragma unroll
                for (int i = 0; i < 4; i++)
                    av[i] = *(const float4*)(s_h + (r0 + i) * DM + k);
                #pragma unroll
                for (int kk = 0; kk < 4; kk++) {
                    const float* w2r = W2 + (size_t)(k + kk) * 2 * DM;
                    float4 g0 = *(const float4*)(w2r + c0);
                    float4 g1 = *(const float4*)(w2r + c0 + 4);
                    float4 e0v = *(const float4*)(w2r + DM + c0);
                    float4 e1v = *(const float4*)(w2r + DM + c0 + 4);
                    #pragma unroll
                    for (int i = 0; i < 4; i++) {
                        float a = (&av[i].x)[kk];
                        FMA_ROW(ag[i], a, g0, g1);
                        FMA_ROW(ab[i], a, e0v, e1v);
                    }
                }
            }
            #pragma unroll
            for (int i = 0; i < 4; i++)
                #pragma unroll
                for (int j = 0; j < 8; j++) {
                    float gamma = ag[i][j] + b2[c0 + j];
                    float beta  = ab[i][j] + b2[DM + c0 + j];
                    s_ki[(r0 + i) * DM + c0 + j] =
                        gamma * s_nj[(r0 + i) * DM + c0 + j] + beta;
                }
        }
        __syncthreads();

        // ---- stage 3: KV = k_in @ Wp + bp  (per-head dense 256->256) ----
        {
            float acc[4][8];
            #pragma unroll
            for (int i = 0; i < 4; i++)
                #pragma unroll
                for (int j = 0; j < 8; j++) acc[i][j] = 0.f;

            const int head = c0 >> 6, e0 = c0 & 63;
            const float* Wph = Wp + (size_t)head * DM * DK + e0;
            for (int k = 0; k < DM; k += 4) {
                float4 av[4];
                #pragma unroll
                for (int i = 0; i < 4; i++)
                    av[i] = *(const float4*)(s_ki + (r0 + i) * DM + k);
                #pragma unroll
                for (int kk = 0; kk < 4; kk++) {
                    float4 w0 = *(const float4*)(Wph + (size_t)(k + kk) * DK);
                    float4 w1 = *(const float4*)(Wph + (size_t)(k + kk) * DK + 4);
                    #pragma unroll
                    for (int i = 0; i < 4; i++) {
                        float a = (&av[i].x)[kk];
                        FMA_ROW(acc[i], a, w0, w1);
                    }
                }
            }
            #pragma unroll
            for (int i = 0; i < 4; i++) {
                float4 o0 = make_float4(acc[i][0] + bp[c0 + 0], acc[i][1] + bp[c0 + 1],
                                        acc[i][2] + bp[c0 + 2], acc[i][3] + bp[c0 + 3]);
                float4 o1 = make_float4(acc[i][4] + bp[c0 + 4], acc[i][5] + bp[c0 + 5],
                                        acc[i][6] + bp[c0 + 6], acc[i][7] + bp[c0 + 7]);
                *(float4*)(gout + (ebase + r0 + i) * DM + c0)     = o0;
                *(float4*)(gout + (ebase + r0 + i) * DM + c0 + 4) = o1;
            }
        }
        __syncthreads();
    }
}

// ---------------- attention over 32 neighbors per (z,n), one warp per head --
__global__ __launch_bounds__(128) void attn_kernel(const void* __restrict__ mask) {
    const int zn = blockIdx.x;
    const int tid = threadIdx.x;
    const int h = tid >> 5;
    const int lane = tid & 31;
    __shared__ float q_s[DM];
    q_s[tid]       = g_Q[(size_t)zn * DM + tid];
    q_s[tid + 128] = g_Q[(size_t)zn * DM + tid + 128];
    __syncthreads();

    // scores: lane = neighbor index
    const float* krow = g_K + ((size_t)zn * KI + lane) * DM + h * DK;
    float s = 0.f;
    #pragma unroll
    for (int e = 0; e < DK; e += 4) {
        float4 kv = *(const float4*)(krow + e);
        s += q_s[h * DK + e]     * kv.x + q_s[h * DK + e + 1] * kv.y
           + q_s[h * DK + e + 2] * kv.z + q_s[h * DK + e + 3] * kv.w;
    }
    s *= 0.125f;   // 1/sqrt(64)

    // mask: -inf for non-neighbors unless whole row masked
    int flag = g_mflag;
    size_t midx = (size_t)zn * KI + lane;
    bool mv;
    if (flag == 2)      mv = ((const unsigned char*)mask)[midx] != 0;
    else if (flag == 1) mv = ((const int*)mask)[midx] != 0;
    else                mv = ((const float*)mask)[midx] != 0.0f;
    bool inv = !mv;
    unsigned bal = __ballot_sync(0xffffffffu, inv);
    if (inv && bal != 0xffffffffu) s = __int_as_float(0xff800000); // -inf

    // warp softmax over the 32 neighbors
    float mx = s;
    #pragma unroll
    for (int o = 16; o > 0; o >>= 1)
        mx = fmaxf(mx, __shfl_xor_sync(0xffffffffu, mx, o));
    float p = __expf(s - mx);
    float ps = p;
    #pragma unroll
    for (int o = 16; o > 0; o >>= 1)
        ps += __shfl_xor_sync(0xffffffffu, ps, o);
    p /= ps;

    // out[e] = sum_l p[l] * V[l][e];  lane owns dims (2*lane, 2*lane+1)
    const float* vbase = g_V + (size_t)zn * KI * DM + h * DK;
    float o0 = 0.f, o1 = 0.f;
    const int e = lane * 2;
    #pragma unroll 8
    for (int l2 = 0; l2 < KI; l2++) {
        float pv = __shfl_sync(0xffffffffu, p, l2);
        float2 vv = *(const float2*)(vbase + l2 * DM + e);
        o0 += pv * vv.x;
        o1 += pv * vv.y;
    }
    // output layout before final proj: index = dk*H + h (torch permute/reshape)
    g_attn[(size_t)zn * DM + (e    ) * HN + h] = o0;
    g_attn[(size_t)zn * DM + (e + 1) * HN + h] = o1;
}

// ---------------- final projection: y = attn @ out_W.T ----------------------
__global__ __launch_bounds__(256) void outproj_kernel(float* __restrict__ out) {
    __shared__ float s_x[TILE * DM];
    const int tid = threadIdx.x;
    const int tx = tid & 31, ty = tid >> 5;
    const int c0 = tx * 8, r0 = ty * 4;
    const size_t rbase = (size_t)blockIdx.x * TILE;
    {
        const float4* xg = (const float4*)(g_attn + rbase * DM);
        float4* sx = (float4*)s_x;
        #pragma unroll
        for (int i = 0; i < 8; i++) sx[tid + i * 256] = xg[tid + i * 256];
    }
    __syncthreads();

    float acc[4][8];
    #pragma unroll
    for (int i = 0; i < 4; i++)
        #pragma unroll
        for (int j = 0; j < 8; j++) acc[i][j] = 0.f;

    for (int k = 0; k < DM; k += 4) {
        float4 av[4];
        #pragma unroll
        for (int i = 0; i < 4; i++)
            av[i] = *(const float4*)(s_x + (r0 + i) * DM + k);
        #pragma unroll
        for (int kk = 0; kk < 4; kk++) {
            float4 w0 = *(const float4*)(g_WoT + (size_t)(k + kk) * DM + c0);
            float4 w1 = *(const float4*)(g_WoT + (size_t)(k + kk) * DM + c0 + 4);
            #pragma unroll
            for (int i = 0; i < 4; i++) {
                float a = (&av[i].x)[kk];
                FMA_ROW(acc[i], a, w0, w1);
            }
        }
    }
    #pragma unroll
    for (int i = 0; i < 4; i++) {
        float4 o0 = make_float4(acc[i][0], acc[i][1], acc[i][2], acc[i][3]);
        float4 o1 = make_float4(acc[i][4], acc[i][5], acc[i][6], acc[i][7]);
        *(float4*)(out + (rbase + r0 + i) * DM + c0)     = o0;
        *(float4*)(out + (rbase + r0 + i) * DM + c0 + 4) = o1;
    }
}

// ---------------------------------------------------------------------------
extern "C" void kernel_launch(void* const* d_in, const int* in_sizes, int n_in,
                              void* d_out, int out_size)
{
    const float* nodes_i = (const float*)d_in[0];
    const float* edges   = (const float*)d_in[1];
    const float* nodes_j = (const float*)d_in[2];
    const void*  nmask   = d_in[3];
    const float* fkW1 = (const float*)d_in[4];
    const float* fkb1 = (const float*)d_in[5];
    const float* fkW2 = (const float*)d_in[6];
    const float* fkb2 = (const float*)d_in[7];
    const float* fvW1 = (const float*)d_in[8];
    const float* fvb1 = (const float*)d_in[9];
    const float* fvW2 = (const float*)d_in[10];
    const float* fvb2 = (const float*)d_in[11];
    const float* qproj = (const float*)d_in[12];
    const float* kproj = (const float*)d_in[13];
    const float* vproj = (const float*)d_in[14];
    const float* qbias = (const float*)d_in[15];
    const float* kbias = (const float*)d_in[16];
    const float* vbias = (const float*)d_in[17];
    const float* outW  = (const float*)d_in[18];

    const int smem_bytes = 4 * TILE * DM * (int)sizeof(float);  // 131072
    cudaFuncSetAttribute(film_kv_kernel,
                         cudaFuncAttributeMaxDynamicSharedMemorySize, smem_bytes);

    detect_mask_kernel<<<1, 1>>>(nmask, in_sizes[3]);
    transpose_w_kernel<<<(DM * DM) / 256, 256>>>(outW);
    qproj_kernel<<<ZN / TILE, 256>>>(nodes_i, qproj, qbias);
    film_kv_kernel<<<ETOT / TILE, 256, smem_bytes>>>(
        edges, nodes_j,
        fkW1, fkb1, fkW2, fkb2,
        fvW1, fvb1, fvW2, fvb2,
        kproj, kbias, vproj, vbias);
    attn_kernel<<<ZN, 128>>>(nmask);
    outproj_kernel<<<ZN / TILE, 256>>>((float*)d_out);
}

// round 2
// speedup vs baseline: 1.0030x; 1.0030x over previous
#include <cuda_runtime.h>

#define DM 256
#define KI 32
#define HN 4
#define DK 64
#define ZB 2
#define NN 2048
#define ZN (ZB*NN)          /* 4096  */
#define ETOT (ZN*KI)        /* 131072 */
#define TILE 32

// ---------------- scratch (static device globals: no runtime allocation) ----
__device__ float g_Q[(size_t)ZN * DM];        // 4 MB
__device__ float g_K[(size_t)ETOT * DM];      // 134 MB
__device__ float g_V[(size_t)ETOT * DM];      // 134 MB
__device__ float g_attn[(size_t)ZN * DM];     // 4 MB
__device__ float g_WoT[DM * DM];
__device__ int   g_mflag;

#define FMA_ROW(ACCI, A, W0, W1) \
    do { \
        (ACCI)[0] += (A)*(W0).x; (ACCI)[1] += (A)*(W0).y; \
        (ACCI)[2] += (A)*(W0).z; (ACCI)[3] += (A)*(W0).w; \
        (ACCI)[4] += (A)*(W1).x; (ACCI)[5] += (A)*(W1).y; \
        (ACCI)[6] += (A)*(W1).z; (ACCI)[7] += (A)*(W1).w; \
    } while (0)

// ---------------- mask dtype detection (bool8 / int32 / float32) ------------
__global__ void detect_mask_kernel(const void* mask, int count) {
    if (threadIdx.x != 0 || blockIdx.x != 0) return;
    const unsigned int* u  = (const unsigned int*)mask;
    const float*        fp = (const float*)mask;
    int words = count / 4;               // safe bound for any of the 3 dtypes
    int lim = words < 1024 ? words : 1024;
    bool int_ok = true, int_one = false, flt_ok = true, flt_one = false;
    for (int i = 0; i < lim; i++) {
        unsigned int v = u[i];
        if (v > 1u)  int_ok = false;
        if (v == 1u) int_one = true;
        float fv = fp[i];
        if (fv != 0.0f && fv != 1.0f) flt_ok = false;
        if (fv == 1.0f) flt_one = true;
    }
    int flag;
    if (int_ok && int_one)      flag = 1;   // int32 {0,1}
    else if (flt_ok && flt_one) flag = 0;   // float32 {0.0,1.0}
    else                        flag = 2;   // bool8 (1 byte per element)
    g_mflag = flag;
}

// ---------------- out_W transpose: g_WoT[c][d] = out_W[d][c] ----------------
__global__ void transpose_w_kernel(const float* __restrict__ W) {
    int idx = blockIdx.x * blockDim.x + threadIdx.x;
    if (idx < DM * DM) {
        int d = idx >> 8;
        int c = idx & (DM - 1);
        g_WoT[c * DM + d] = W[idx];
    }
}

// ---------------- Q projection: g_Q[zn][h*64+e] = nodes_i @ q_proj + qb -----
__global__ __launch_bounds__(256) void qproj_kernel(
    const float* __restrict__ x, const float* __restrict__ qp,
    const float* __restrict__ qb)
{
    __shared__ float s_x[TILE * DM];
    const int tid = threadIdx.x;
    const int tx = tid & 31, ty = tid >> 5;
    const int c0 = tx * 8, r0 = ty * 4;
    const size_t rbase = (size_t)blockIdx.x * TILE;
    {
        const float4* xg = (const float4*)(x + rbase * DM);
        float4* sx = (float4*)s_x;
        #pragma unroll
        for (int i = 0; i < 8; i++) sx[tid + i * 256] = xg[tid + i * 256];
    }
    __syncthreads();

    float acc[4][8];
    #pragma unroll
    for (int i = 0; i < 4; i++)
        #pragma unroll
        for (int j = 0; j < 8; j++) acc[i][j] = 0.f;

    const int head = c0 >> 6, e0 = c0 & 63;
    const float* Wh = qp + head * DM * DK + e0;
    for (int k = 0; k < DM; k += 4) {
        float4 av[4];
        #pragma unroll
        for (int i = 0; i < 4; i++)
            av[i] = *(const float4*)(s_x + (r0 + i) * DM + k);
        #pragma unroll
        for (int kk = 0; kk < 4; kk++) {
            float4 w0 = *(const float4*)(Wh + (size_t)(k + kk) * DK);
            float4 w1 = *(const float4*)(Wh + (size_t)(k + kk) * DK + 4);
            #pragma unroll
            for (int i = 0; i < 4; i++) {
                float a = (&av[i].x)[kk];
                FMA_ROW(acc[i], a, w0, w1);
            }
        }
    }
    #pragma unroll
    for (int i = 0; i < 4; i++) {
        float4 o0 = make_float4(acc[i][0] + qb[c0 + 0], acc[i][1] + qb[c0 + 1],
                                acc[i][2] + qb[c0 + 2], acc[i][3] + qb[c0 + 3]);
        float4 o1 = make_float4(acc[i][4] + qb[c0 + 4], acc[i][5] + qb[c0 + 5],
                                acc[i][6] + qb[c0 + 6], acc[i][7] + qb[c0 + 7]);
        *(float4*)(g_Q + (rbase + r0 + i) * DM + c0)     = o0;
        *(float4*)(g_Q + (rbase + r0 + i) * DM + c0 + 4) = o1;
    }
}

// ---------------- fused FiLM (K and V) + K/V head projections ---------------
__global__ __launch_bounds__(256, 1) void film_kv_kernel(
    const float* __restrict__ edges, const float* __restrict__ nodesj,
    const float* __restrict__ fkW1, const float* __restrict__ fkb1,
    const float* __restrict__ fkW2, const float* __restrict__ fkb2,
    const float* __restrict__ fvW1, const float* __restrict__ fvb1,
    const float* __restrict__ fvW2, const float* __restrict__ fvb2,
    const float* __restrict__ kproj, const float* __restrict__ kbias,
    const float* __restrict__ vproj, const float* __restrict__ vbias)
{
    extern __shared__ float sm[];
    float* s_e  = sm;                 // [32][256] edge tile
    float* s_nj = sm + TILE * DM;     // [32][256] nodes_j tile
    float* s_h  = sm + 2 * TILE * DM; // [32][256] hidden
    float* s_ki = sm + 3 * TILE * DM; // [32][256] film output

    const int tid = threadIdx.x;
    const int tx = tid & 31, ty = tid >> 5;
    const int c0 = tx * 8, r0 = ty * 4;
    const size_t ebase = (size_t)blockIdx.x * TILE;

    {
        const float4* eg = (const float4*)(edges + ebase * DM);
        const float4* ng = (const float4*)(nodesj + ebase * DM);
        float4* se = (float4*)s_e;
        float4* sn = (float4*)s_nj;
        #pragma unroll
        for (int i = 0; i < 8; i++) {
            se[tid + i * 256] = eg[tid + i * 256];
            sn[tid + i * 256] = ng[tid + i * 256];
        }
    }
    __syncthreads();

    #pragma unroll 1
    for (int f = 0; f < 2; f++) {
        const float* W1 = f ? fvW1 : fkW1;
        const float* b1 = f ? fvb1 : fkb1;
        const float* W2 = f ? fvW2 : fkW2;
        const float* b2 = f ? fvb2 : fkb2;
        const float* Wp = f ? vproj : kproj;
        const float* bp = f ? vbias : kbias;
        float* gout = f ? g_V : g_K;

        // ---- stage 1: h = silu(e @ W1 + b1) ----
        {
            float acc[4][8];
            #pragma unroll
            for (int i = 0; i < 4; i++)
                #pragma unroll
                for (int j = 0; j < 8; j++) acc[i][j] = 0.f;

            for (int k = 0; k < DM; k += 4) {
                float4 av[4];
                #pragma unroll
                for (int i = 0; i < 4; i++)
                    av[i] = *(const float4*)(s_e + (r0 + i) * DM + k);
                #pragma unroll
                for (int kk = 0; kk < 4; kk++) {
                    float4 w0 = *(const float4*)(W1 + (size_t)(k + kk) * DM + c0);
                    float4 w1 = *(const float4*)(W1 + (size_t)(k + kk) * DM + c0 + 4);
                    #pragma unroll
                    for (int i = 0; i < 4; i++) {
                        float a = (&av[i].x)[kk];
                        FMA_ROW(acc[i], a, w0, w1);
                    }
                }
            }
            #pragma unroll
            for (int i = 0; i < 4; i++)
                #pragma unroll
                for (int j = 0; j < 8; j++) {
                    float xv = acc[i][j] + b1[c0 + j];
                    s_h[(r0 + i) * DM + c0 + j] = xv / (1.0f + __expf(-xv));
                }
        }
        __syncthreads();

        // ---- stage 2: gb = h @ W2 + b2;  k_in = gamma * nj + beta ----
        {
            float ag[4][8], ab[4][8];
            #pragma unroll
            for (int i = 0; i < 4; i++)
                #pragma unroll
                for (int j = 0; j < 8; j++) { ag[i][j] = 0.f; ab[i][j] = 0.f; }

            for (int k = 0; k < DM; k += 4) {
                float4 av[4];
                #pragma unroll
                for (int i = 0; i < 4; i++)
                    av[i] = *(const float4*)(s_h + (r0 + i) * DM + k);
                #pragma unroll
                for (int kk = 0; kk < 4; kk++) {
                    const float* w2r = W2 + (size_t)(k + kk) * 2 * DM;
                    float4 g0 = *(const float4*)(w2r + c0);
                    float4 g1 = *(const float4*)(w2r + c0 + 4);
                    float4 e0v = *(const float4*)(w2r + DM + c0);
                    float4 e1v = *(const float4*)(w2r + DM + c0 + 4);
                    #pragma unroll
                    for (int i = 0; i < 4; i++) {
                        float a = (&av[i].x)[kk];
                        FMA_ROW(ag[i], a, g0, g1);
                        FMA_ROW(ab[i], a, e0v, e1v);
                    }
                }
            }
            #pragma unroll
            for (int i = 0; i < 4; i++)
                #pragma unroll
                for (int j = 0; j < 8; j++) {
                    float gamma = ag[i][j] + b2[c0 + j];
                    float beta  = ab[i][j] + b2[DM + c0 + j];
                    s_ki[(r0 + i) * DM + c0 + j] =
                        gamma * s_nj[(r0 + i) * DM + c0 + j] + beta;
                }
        }
        __syncthreads();

        // ---- stage 3: KV = k_in @ Wp + bp  (per-head dense 256->256) ----
        {
            float acc[4][8];
            #pragma unroll
            for (int i = 0; i < 4; i++)
                #pragma unroll
                for (int j = 0; j < 8; j++) acc[i][j] = 0.f;

            const int head = c0 >> 6, e0 = c0 & 63;
            const float* Wph = Wp + (size_t)head * DM * DK + e0;
            for (int k = 0; k < DM; k += 4) {
                float4 av[4];
                #pragma unroll
                for (int i = 0; i < 4; i++)
                    av[i] = *(const float4*)(s_ki + (r0 + i) * DM + k);
                #pragma unroll
                for (int kk = 0; kk < 4; kk++) {
                    float4 w0 = *(const float4*)(Wph + (size_t)(k + kk) * DK);
                    float4 w1 = *(const float4*)(Wph + (size_t)(k + kk) * DK + 4);
                    #pragma unroll
                    for (int i = 0; i < 4; i++) {
                        float a = (&av[i].x)[kk];
                        FMA_ROW(acc[i], a, w0, w1);
                    }
                }
            }
            #pragma unroll
            for (int i = 0; i < 4; i++) {
                float4 o0 = make_float4(acc[i][0] + bp[c0 + 0], acc[i][1] + bp[c0 + 1],
                                        acc[i][2] + bp[c0 + 2], acc[i][3] + bp[c0 + 3]);
                float4 o1 = make_float4(acc[i][4] + bp[c0 + 4], acc[i][5] + bp[c0 + 5],
                                        acc[i][6] + bp[c0 + 6], acc[i][7] + bp[c0 + 7]);
                *(float4*)(gout + (ebase + r0 + i) * DM + c0)     = o0;
                *(float4*)(gout + (ebase + r0 + i) * DM + c0 + 4) = o1;
            }
        }
        __syncthreads();
    }
}

// ---------------- attention over 32 neighbors per (z,n), one warp per head --
__global__ __launch_bounds__(128) void attn_kernel(const void* __restrict__ mask) {
    const int zn = blockIdx.x;
    const int tid = threadIdx.x;
    const int h = tid >> 5;
    const int lane = tid & 31;
    __shared__ float q_s[DM];
    q_s[tid]       = g_Q[(size_t)zn * DM + tid];
    q_s[tid + 128] = g_Q[(size_t)zn * DM + tid + 128];
    __syncthreads();

    // scores: lane = neighbor index
    const float* krow = g_K + ((size_t)zn * KI + lane) * DM + h * DK;
    float s = 0.f;
    #pragma unroll
    for (int e = 0; e < DK; e += 4) {
        float4 kv = *(const float4*)(krow + e);
        s += q_s[h * DK + e]     * kv.x + q_s[h * DK + e + 1] * kv.y
           + q_s[h * DK + e + 2] * kv.z + q_s[h * DK + e + 3] * kv.w;
    }
    s *= 0.125f;   // 1/sqrt(64)

    // mask: -inf for non-neighbors unless whole row masked
    int flag = g_mflag;
    size_t midx = (size_t)zn * KI + lane;
    bool mv;
    if (flag == 2)      mv = ((const unsigned char*)mask)[midx] != 0;
    else if (flag == 1) mv = ((const int*)mask)[midx] != 0;
    else                mv = ((const float*)mask)[midx] != 0.0f;
    bool inv = !mv;
    unsigned bal = __ballot_sync(0xffffffffu, inv);
    if (inv && bal != 0xffffffffu) s = __int_as_float(0xff800000); // -inf

    // warp softmax over the 32 neighbors
    float mx = s;
    #pragma unroll
    for (int o = 16; o > 0; o >>= 1)
        mx = fmaxf(mx, __shfl_xor_sync(0xffffffffu, mx, o));
    float p = __expf(s - mx);
    float ps = p;
    #pragma unroll
    for (int o = 16; o > 0; o >>= 1)
        ps += __shfl_xor_sync(0xffffffffu, ps, o);
    p /= ps;

    // out[e] = sum_l p[l] * V[l][e];  lane owns dims (2*lane, 2*lane+1)
    const float* vbase = g_V + (size_t)zn * KI * DM + h * DK;
    float o0 = 0.f, o1 = 0.f;
    const int e = lane * 2;
    #pragma unroll 8
    for (int l2 = 0; l2 < KI; l2++) {
        float pv = __shfl_sync(0xffffffffu, p, l2);
        float2 vv = *(const float2*)(vbase + l2 * DM + e);
        o0 += pv * vv.x;
        o1 += pv * vv.y;
    }
    // output layout before final proj: index = dk*H + h (torch permute/reshape)
    g_attn[(size_t)zn * DM + (e    ) * HN + h] = o0;
    g_attn[(size_t)zn * DM + (e + 1) * HN + h] = o1;
}

// ---------------- final projection: y = attn @ out_W.T ----------------------
__global__ __launch_bounds__(256) void outproj_kernel(float* __restrict__ out) {
    __shared__ float s_x[TILE * DM];
    const int tid = threadIdx.x;
    const int tx = tid & 31, ty = tid >> 5;
    const int c0 = tx * 8, r0 = ty * 4;
    const size_t rbase = (size_t)blockIdx.x * TILE;
    {
        const float4* xg = (const float4*)(g_attn + rbase * DM);
        float4* sx = (float4*)s_x;
        #pragma unroll
        for (int i = 0; i < 8; i++) sx[tid + i * 256] = xg[tid + i * 256];
    }
    __syncthreads();

    float acc[4][8];
    #pragma unroll
    for (int i = 0; i < 4; i++)
        #pragma unroll
        for (int j = 0; j < 8; j++) acc[i][j] = 0.f;

    for (int k = 0; k < DM; k += 4) {
        float4 av[4];
        #pragma unroll
        for (int i = 0; i < 4; i++)
            av[i] = *(const float4*)(s_x + (r0 + i) * DM + k);
        #pragma unroll
        for (int kk = 0; kk < 4; kk++) {
            float4 w0 = *(const float4*)(g_WoT + (size_t)(k + kk) * DM + c0);
            float4 w1 = *(const float4*)(g_WoT + (size_t)(k + kk) * DM + c0 + 4);
            #pragma unroll
            for (int i = 0; i < 4; i++) {
                float a = (&av[i].x)[kk];
                FMA_ROW(acc[i], a, w0, w1);
            }
        }
    }
    #pragma unroll
    for (int i = 0; i < 4; i++) {
        float4 o0 = make_float4(acc[i][0], acc[i][1], acc[i][2], acc[i][3]);
        float4 o1 = make_float4(acc[i][4], acc[i][5], acc[i][6], acc[i][7]);
        *(float4*)(out + (rbase + r0 + i) * DM + c0)     = o0;
        *(float4*)(out + (rbase + r0 + i) * DM + c0 + 4) = o1;
    }
}

// ---------------------------------------------------------------------------
extern "C" void kernel_launch(void* const* d_in, const int* in_sizes, int n_in,
                              void* d_out, int out_size)
{
    const float* nodes_i = (const float*)d_in[0];
    const float* edges   = (const float*)d_in[1];
    const float* nodes_j = (const float*)d_in[2];
    const void*  nmask   = d_in[3];
    const float* fkW1 = (const float*)d_in[4];
    const float* fkb1 = (const float*)d_in[5];
    const float* fkW2 = (const float*)d_in[6];
    const float* fkb2 = (const float*)d_in[7];
    const float* fvW1 = (const float*)d_in[8];
    const float* fvb1 = (const float*)d_in[9];
    const float* fvW2 = (const float*)d_in[10];
    const float* fvb2 = (const float*)d_in[11];
    const float* qproj = (const float*)d_in[12];
    const float* kproj = (const float*)d_in[13];
    const float* vproj = (const float*)d_in[14];
    const float* qbias = (const float*)d_in[15];
    const float* kbias = (const float*)d_in[16];
    const float* vbias = (const float*)d_in[17];
    const float* outW  = (const float*)d_in[18];

    const int smem_bytes = 4 * TILE * DM * (int)sizeof(float);  // 131072
    cudaFuncSetAttribute(film_kv_kernel,
                         cudaFuncAttributeMaxDynamicSharedMemorySize, smem_bytes);

    detect_mask_kernel<<<1, 1>>>(nmask, in_sizes[3]);
    transpose_w_kernel<<<(DM * DM) / 256, 256>>>(outW);
    qproj_kernel<<<ZN / TILE, 256>>>(nodes_i, qproj, qbias);
    film_kv_kernel<<<ETOT / TILE, 256, smem_bytes>>>(
        edges, nodes_j,
        fkW1, fkb1, fkW2, fkb2,
        fvW1, fvb1, fvW2, fvb2,
        kproj, kbias, vproj, vbias);
    attn_kernel<<<ZN, 128>>>(nmask);
    outproj_kernel<<<ZN / TILE, 256>>>((float*)d_out);
}

// round 4
// speedup vs baseline: 3.0140x; 3.0051x over previous
#include <cuda_runtime.h>
#include <cuda_bf16.h>
#include <cstdint>

#define DM 256
#define KI 32
#define HN 4
#define DK 64
#define ZN 4096             /* Z*N   */
#define ETOT 131072         /* edges */
#define TILE 32
#define MB 128              /* rows per film block */
#define NB (ETOT/MB)        /* 1024 film blocks */

// film smem layout (bytes)
#define A_HI 0
#define A_LO 65536
#define W_HI 131072
#define W_LO 163840
#define SMEM_TC 196608
#define WCH 65536           /* packed W chunk: hi 32KB + lo 32KB */

// ---------------- device scratch --------------------------------------------
__device__ float g_Q[(size_t)ZN * DM];
__device__ float g_K[(size_t)ETOT * DM];
__device__ float g_V[(size_t)ETOT * DM];
__device__ float g_H[(size_t)ETOT * DM];      // inter-stage activations
__device__ float g_attn[(size_t)ZN * DM];
__device__ float g_WoT[DM * DM];
__device__ int   g_mflag;
__device__ unsigned char g_Wp[32 * WCH];      // packed, swizzled bf16 weights (2MB)

// ---------------- asm helpers -----------------------------------------------
__device__ __forceinline__ uint32_t smem_u32(const void* p) {
    uint32_t a;
    asm("{ .reg .u64 t; cvta.to.shared.u64 t, %1; cvt.u32.u64 %0, t; }" : "=r"(a) : "l"(p));
    return a;
}
__device__ __forceinline__ void cpasync16(uint32_t d, const void* s) {
    asm volatile("cp.async.cg.shared.global [%0], [%1], 16;" :: "r"(d), "l"(s) : "memory");
}
#define CP_COMMIT() asm volatile("cp.async.commit_group;" ::: "memory")
__device__ __forceinline__ void cp_wait(int n) {
    switch (n) {
    case 0: asm volatile("cp.async.wait_group 0;" ::: "memory"); break;
    case 1: asm volatile("cp.async.wait_group 1;" ::: "memory"); break;
    case 2: asm volatile("cp.async.wait_group 2;" ::: "memory"); break;
    case 3: asm volatile("cp.async.wait_group 3;" ::: "memory"); break;
    case 4: asm volatile("cp.async.wait_group 4;" ::: "memory"); break;
    case 5: asm volatile("cp.async.wait_group 5;" ::: "memory"); break;
    case 6: asm volatile("cp.async.wait_group 6;" ::: "memory"); break;
    default: asm volatile("cp.async.wait_group 7;" ::: "memory"); break;
    }
}
__device__ __forceinline__ void ldsm4(uint32_t* r, uint32_t addr) {
    asm volatile("ldmatrix.sync.aligned.m8n8.x4.shared.b16 {%0,%1,%2,%3}, [%4];"
        : "=r"(r[0]), "=r"(r[1]), "=r"(r[2]), "=r"(r[3]) : "r"(addr));
}
__device__ __forceinline__ void ldsm4t(uint32_t* r, uint32_t addr) {
    asm volatile("ldmatrix.sync.aligned.m8n8.x4.trans.shared.b16 {%0,%1,%2,%3}, [%4];"
        : "=r"(r[0]), "=r"(r[1]), "=r"(r[2]), "=r"(r[3]) : "r"(addr));
}
__device__ __forceinline__ void mma16816(float* d, const uint32_t* a, const uint32_t* b) {
    asm volatile("mma.sync.aligned.m16n8k16.row.col.f32.bf16.bf16.f32 "
        "{%0,%1,%2,%3}, {%4,%5,%6,%7}, {%8,%9}, {%0,%1,%2,%3};"
        : "+f"(d[0]), "+f"(d[1]), "+f"(d[2]), "+f"(d[3])
        : "r"(a[0]), "r"(a[1]), "r"(a[2]), "r"(a[3]), "r"(b[0]), "r"(b[1]));
}
__device__ __forceinline__ uint32_t pack_bf2(__nv_bfloat16 a, __nv_bfloat16 b) {
    return ((uint32_t)__bfloat16_as_ushort(b) << 16) | __bfloat16_as_ushort(a);
}
// A smem swizzle: [r<128][c<256] bf16, row 512B, XOR bits[6:4] with r&7
__device__ __forceinline__ uint32_t a_off(int r, int c) {
    uint32_t o = ((uint32_t)r << 9) + ((uint32_t)c << 1);
    return o ^ (((uint32_t)r & 7u) << 4);
}
// W smem swizzle: [k<256][n<64] bf16, row 128B, XOR bits[6:4] with k&7
__device__ __forceinline__ uint32_t w_off(int k, int n) {
    uint32_t o = ((uint32_t)k << 7) + ((uint32_t)n << 1);
    return o ^ (((uint32_t)k & 7u) << 4);
}
__device__ __forceinline__ void split2(char* smem, int r, int c, float x0, float x1) {
    __nv_bfloat16 h0 = __float2bfloat16(x0), h1 = __float2bfloat16(x1);
    __nv_bfloat16 l0 = __float2bfloat16(x0 - __bfloat162float(h0));
    __nv_bfloat16 l1 = __float2bfloat16(x1 - __bfloat162float(h1));
    uint32_t off = a_off(r, c);
    *(uint32_t*)(smem + A_HI + off) = pack_bf2(h0, h1);
    *(uint32_t*)(smem + A_LO + off) = pack_bf2(l0, l1);
}
__device__ __forceinline__ void load_split_A(const float* __restrict__ src,
                                             char* smem, int tid) {
    #pragma unroll 1
    for (int i = 0; i < 32; i++) {
        int fi = tid + i * 256;              // 8192 float4 total
        int r  = fi >> 6;
        int c  = (fi & 63) << 2;
        float4 v = *(const float4*)(src + ((size_t)fi << 2));
        split2(smem, r, c,     v.x, v.y);
        split2(smem, r, c + 2, v.z, v.w);
    }
}

// ---------------- setup kernels ---------------------------------------------
__global__ void detect_mask_kernel(const void* mask, int count) {
    if (threadIdx.x != 0 || blockIdx.x != 0) return;
    const unsigned int* u  = (const unsigned int*)mask;
    const float*        fp = (const float*)mask;
    int words = count / 4;
    int lim = words < 1024 ? words : 1024;
    bool int_ok = true, int_one = false, flt_ok = true, flt_one = false;
    for (int i = 0; i < lim; i++) {
        unsigned int v = u[i];
        if (v > 1u)  int_ok = false;
        if (v == 1u) int_one = true;
        float fv = fp[i];
        if (fv != 0.0f && fv != 1.0f) flt_ok = false;
        if (fv == 1.0f) flt_one = true;
    }
    g_mflag = (int_ok && int_one) ? 1 : (flt_ok && flt_one) ? 0 : 2;
}
__global__ void transpose_w_kernel(const float* __restrict__ W) {
    int idx = blockIdx.x * blockDim.x + threadIdx.x;
    if (idx < DM * DM) g_WoT[(idx & 255) * DM + (idx >> 8)] = W[idx];
}

// pack weights into swizzled bf16 hi/lo chunk images (exact smem layout).
// 32 chunks of [k=256][n=64]: path p = ch>>4; r = ch&15:
//   r<4  : W1, cols n = r*64 + j
//   r<12 : W2, gamma/beta interleaved at 8-col granularity:
//          gcol = (r-4)*32 + ((j>>4)<<3) + (j&7); col = ((j>>3)&1)? 256+gcol : gcol
//   else : head proj, n = (r-12)*64 + j; proj[head=n>>6][k][n&63]
__global__ __launch_bounds__(256) void pack_w_kernel(
    const float* __restrict__ fkW1, const float* __restrict__ fkW2,
    const float* __restrict__ kproj,
    const float* __restrict__ fvW1, const float* __restrict__ fvW2,
    const float* __restrict__ vproj)
{
    int idx = blockIdx.x * 256 + threadIdx.x;   // 524288 total
    int ch = idx >> 14;
    int e  = idx & 16383;
    int k  = e >> 6, j = e & 63;
    int p = ch >> 4, r = ch & 15;
    float w;
    if (r < 4) {
        const float* W1 = p ? fvW1 : fkW1;
        w = W1[k * 256 + r * 64 + j];
    } else if (r < 12) {
        const float* W2 = p ? fvW2 : fkW2;
        int gc = (r - 4) * 32 + ((j >> 4) << 3) + (j & 7);
        int col = ((j >> 3) & 1) ? 256 + gc : gc;
        w = W2[k * 512 + col];
    } else {
        const float* P = p ? vproj : kproj;
        int n = (r - 12) * 64 + j;
        w = P[(n >> 6) * 16384 + k * 64 + (n & 63)];
    }
    __nv_bfloat16 hi = __float2bfloat16(w);
    __nv_bfloat16 lo = __float2bfloat16(w - __bfloat162float(hi));
    uint32_t off = w_off(k, j);
    size_t base = (size_t)ch * WCH;
    *(unsigned short*)(g_Wp + base + off)         = __bfloat16_as_ushort(hi);
    *(unsigned short*)(g_Wp + base + 32768 + off) = __bfloat16_as_ushort(lo);
}

// ---------------- warp-MMA FiLM + K/V projections ---------------------------
__global__ __launch_bounds__(256, 1) void film_mma_kernel(
    const float* __restrict__ edges, const float* __restrict__ nodesj,
    const float* __restrict__ fkb1, const float* __restrict__ fkb2,
    const float* __restrict__ kbias,
    const float* __restrict__ fvb1, const float* __restrict__ fvb2,
    const float* __restrict__ vbias)
{
    extern __shared__ char smem[];
    const uint32_t sb = smem_u32(smem);
    const int tid  = threadIdx.x;
    const int wid  = tid >> 5, lane = tid & 31;
    const int mw   = wid & 3, nwi = wid >> 2;      // warp tile: rows mw*32, cols nwi*32
    const int g    = lane >> 2, tig = lane & 3;
    const size_t ebase = (size_t)blockIdx.x * MB;

    // per-lane ldmatrix address components
    const int amr = lane & 15;            // A: row-in-frag
    const int akb = (lane >> 4) << 3;     // A: k offset 0/8
    const int bkr = lane & 15;            // B: k-in-frag
    const int bnb = (lane >> 4) << 3;     // B: n offset 0/8

    #pragma unroll 1
    for (int f = 0; f < 2; f++) {
        const float* b1 = f ? fvb1 : fkb1;
        const float* b2 = f ? fvb2 : fkb2;
        const float* bp = f ? vbias : kbias;
        float* gout = f ? g_V : g_K;

        #pragma unroll 1
        for (int s = 0; s < 3; s++) {
            const int nc  = (s == 1) ? 8 : 4;
            const int chb = f * 16 + (s == 0 ? 0 : (s == 1 ? 4 : 12));

            #pragma unroll 1
            for (int c = 0; c < nc; c++) {
                __syncthreads();   // everyone done with previous W / A phase

                // issue W chunk as 8 pipelined k-slices (4KB hi + 4KB lo each)
                {
                    const unsigned char* wsrc = g_Wp + (size_t)(chb + c) * WCH;
                    #pragma unroll
                    for (int sl = 0; sl < 8; sl++) {
                        cpasync16(sb + W_HI + sl * 4096 + tid * 16,
                                  wsrc + sl * 4096 + tid * 16);
                        cpasync16(sb + W_LO + sl * 4096 + tid * 16,
                                  wsrc + 32768 + sl * 4096 + tid * 16);
                        CP_COMMIT();
                    }
                }
                // first chunk of a stage: load + split A while W streams in
                if (c == 0) {
                    const float* asrc = (s == 0) ? (edges + ebase * DM)
                                                 : (g_H + ebase * DM);
                    load_split_A(asrc, smem, tid);
                }

                // ---- GEMM: acc[2 mfrag][4 nfrag][4] ----
                float acc[2][4][4];
                #pragma unroll
                for (int i = 0; i < 2; i++)
                    #pragma unroll
                    for (int jj = 0; jj < 4; jj++)
                        #pragma unroll
                        for (int q = 0; q < 4; q++) acc[i][jj][q] = 0.f;

                #pragma unroll 1
                for (int sl = 0; sl < 8; sl++) {
                    cp_wait(7 - sl);
                    __syncthreads();
                    #pragma unroll
                    for (int ki = 0; ki < 2; ki++) {
                        const int k0 = sl * 32 + ki * 16;
                        uint32_t Ah[2][4], Al[2][4], Bh[2][4], Bl[2][4];
                        #pragma unroll
                        for (int im = 0; im < 2; im++) {
                            int r = mw * 32 + im * 16 + amr;
                            uint32_t off = a_off(r, k0 + akb);
                            ldsm4(Ah[im], sb + A_HI + off);
                            ldsm4(Al[im], sb + A_LO + off);
                        }
                        #pragma unroll
                        for (int jb = 0; jb < 2; jb++) {
                            int kk = k0 + bkr;
                            int nn = nwi * 32 + jb * 16 + bnb;
                            uint32_t off = w_off(kk, nn);
                            ldsm4t(Bh[jb], sb + W_HI + off);
                            ldsm4t(Bl[jb], sb + W_LO + off);
                        }
                        #pragma unroll
                        for (int im = 0; im < 2; im++)
                            #pragma unroll
                            for (int jn = 0; jn < 4; jn++) {
                                const uint32_t* bh = &Bh[jn >> 1][(jn & 1) << 1];
                                const uint32_t* bl = &Bl[jn >> 1][(jn & 1) << 1];
                                mma16816(acc[im][jn], Ah[im], bh);
                                mma16816(acc[im][jn], Al[im], bh);
                                mma16816(acc[im][jn], Ah[im], bl);
                            }
                    }
                }

                // ---- register epilogue ----
                if (s == 0) {            // h = silu(D + b1) -> g_H
                    #pragma unroll
                    for (int im = 0; im < 2; im++) {
                        int rb = mw * 32 + im * 16 + g;
                        #pragma unroll
                        for (int jn = 0; jn < 4; jn++) {
                            int col = c * 64 + nwi * 32 + jn * 8 + 2 * tig;
                            float bb0 = b1[col], bb1 = b1[col + 1];
                            #pragma unroll
                            for (int hf = 0; hf < 2; hf++) {
                                size_t row = ebase + rb + hf * 8;
                                float x0 = acc[im][jn][hf * 2]     + bb0;
                                float x1 = acc[im][jn][hf * 2 + 1] + bb1;
                                x0 = x0 / (1.0f + __expf(-x0));
                                x1 = x1 / (1.0f + __expf(-x1));
                                *(float2*)(g_H + row * DM + col) = make_float2(x0, x1);
                            }
                        }
                    }
                } else if (s == 1) {     // k_in = (g+b2g)*nj + (b+b2b) -> g_H
                    #pragma unroll
                    for (int im = 0; im < 2; im++) {
                        int rb = mw * 32 + im * 16 + g;
                        #pragma unroll
                        for (int pi = 0; pi < 2; pi++) {
                            int gc = c * 32 + (nwi * 2 + pi) * 8 + 2 * tig;
                            float bg0 = b2[gc], bg1 = b2[gc + 1];
                            float bb0 = b2[256 + gc], bb1 = b2[256 + gc + 1];
                            #pragma unroll
                            for (int hf = 0; hf < 2; hf++) {
                                size_t row = ebase + rb + hf * 8;
                                float2 nj = *(const float2*)(nodesj + row * DM + gc);
                                float ga0 = acc[im][pi * 2][hf * 2]         + bg0;
                                float ga1 = acc[im][pi * 2][hf * 2 + 1]     + bg1;
                                float be0 = acc[im][pi * 2 + 1][hf * 2]     + bb0;
                                float be1 = acc[im][pi * 2 + 1][hf * 2 + 1] + bb1;
                                *(float2*)(g_H + row * DM + gc) =
                                    make_float2(ga0 * nj.x + be0, ga1 * nj.y + be1);
                            }
                        }
                    }
                } else {                 // KV = D + bp -> g_K / g_V
                    #pragma unroll
                    for (int im = 0; im < 2; im++) {
                        int rb = mw * 32 + im * 16 + g;
                        #pragma unroll
                        for (int jn = 0; jn < 4; jn++) {
                            int col = c * 64 + nwi * 32 + jn * 8 + 2 * tig;
                            float bb0 = bp[col], bb1 = bp[col + 1];
                            #pragma unroll
                            for (int hf = 0; hf < 2; hf++) {
                                size_t row = ebase + rb + hf * 8;
                                *(float2*)(gout + row * DM + col) =
                                    make_float2(acc[im][jn][hf * 2]     + bb0,
                                                acc[im][jn][hf * 2 + 1] + bb1);
                            }
                        }
                    }
                }
            }
        }
    }
}

// ---------------- Q projection (fp32, tiny) ---------------------------------
#define FMA_ROW(ACCI, A, W0, W1) \
    do { \
        (ACCI)[0] += (A)*(W0).x; (ACCI)[1] += (A)*(W0).y; \
        (ACCI)[2] += (A)*(W0).z; (ACCI)[3] += (A)*(W0).w; \
        (ACCI)[4] += (A)*(W1).x; (ACCI)[5] += (A)*(W1).y; \
        (ACCI)[6] += (A)*(W1).z; (ACCI)[7] += (A)*(W1).w; \
    } while (0)

__global__ __launch_bounds__(256) void qproj_kernel(
    const float* __restrict__ x, const float* __restrict__ qp,
    const float* __restrict__ qb)
{
    __shared__ float s_x[TILE * DM];
    const int tid = threadIdx.x;
    const int tx = tid & 31, ty = tid >> 5;
    const int c0 = tx * 8, r0 = ty * 4;
    const size_t rbase = (size_t)blockIdx.x * TILE;
    {
        const float4* xg = (const float4*)(x + rbase * DM);
        float4* sx = (float4*)s_x;
        #pragma unroll
        for (int i = 0; i < 8; i++) sx[tid + i * 256] = xg[tid + i * 256];
    }
    __syncthreads();
    float acc[4][8];
    #pragma unroll
    for (int i = 0; i < 4; i++)
        #pragma unroll
        for (int j = 0; j < 8; j++) acc[i][j] = 0.f;
    const int head = c0 >> 6, e0 = c0 & 63;
    const float* Wh = qp + head * DM * DK + e0;
    for (int k = 0; k < DM; k += 4) {
        float4 av[4];
        #pragma unroll
        for (int i = 0; i < 4; i++)
            av[i] = *(const float4*)(s_x + (r0 + i) * DM + k);
        #pragma unroll
        for (int kk = 0; kk < 4; kk++) {
            float4 w0 = *(const float4*)(Wh + (size_t)(k + kk) * DK);
            float4 w1 = *(const float4*)(Wh + (size_t)(k + kk) * DK + 4);
            #pragma unroll
            for (int i = 0; i < 4; i++) {
                float a = (&av[i].x)[kk];
                FMA_ROW(acc[i], a, w0, w1);
            }
        }
    }
    #pragma unroll
    for (int i = 0; i < 4; i++) {
        *(float4*)(g_Q + (rbase + r0 + i) * DM + c0) =
            make_float4(acc[i][0] + qb[c0 + 0], acc[i][1] + qb[c0 + 1],
                        acc[i][2] + qb[c0 + 2], acc[i][3] + qb[c0 + 3]);
        *(float4*)(g_Q + (rbase + r0 + i) * DM + c0 + 4) =
            make_float4(acc[i][4] + qb[c0 + 4], acc[i][5] + qb[c0 + 5],
                        acc[i][6] + qb[c0 + 6], acc[i][7] + qb[c0 + 7]);
    }
}

// ---------------- attention over 32 neighbors, one warp per head ------------
__global__ __launch_bounds__(128) void attn_kernel(const void* __restrict__ mask) {
    const int zn = blockIdx.x;
    const int tid = threadIdx.x;
    const int h = tid >> 5;
    const int lane = tid & 31;
    __shared__ float q_s[DM];
    q_s[tid]       = g_Q[(size_t)zn * DM + tid];
    q_s[tid + 128] = g_Q[(size_t)zn * DM + tid + 128];
    __syncthreads();

    const float* krow = g_K + ((size_t)zn * KI + lane) * DM + h * DK;
    float s = 0.f;
    #pragma unroll
    for (int e = 0; e < DK; e += 4) {
        float4 kv = *(const float4*)(krow + e);
        s += q_s[h * DK + e]     * kv.x + q_s[h * DK + e + 1] * kv.y
           + q_s[h * DK + e + 2] * kv.z + q_s[h * DK + e + 3] * kv.w;
    }
    s *= 0.125f;

    int flag = g_mflag;
    size_t midx = (size_t)zn * KI + lane;
    bool mv;
    if (flag == 2)      mv = ((const unsigned char*)mask)[midx] != 0;
    else if (flag == 1) mv = ((const int*)mask)[midx] != 0;
    else                mv = ((const float*)mask)[midx] != 0.0f;
    bool inv = !mv;
    unsigned bal = __ballot_sync(0xffffffffu, inv);
    if (inv && bal != 0xffffffffu) s = __int_as_float(0xff800000);

    float mx = s;
    #pragma unroll
    for (int o = 16; o > 0; o >>= 1)
        mx = fmaxf(mx, __shfl_xor_sync(0xffffffffu, mx, o));
    float p = __expf(s - mx);
    float ps = p;
    #pragma unroll
    for (int o = 16; o > 0; o >>= 1)
        ps += __shfl_xor_sync(0xffffffffu, ps, o);
    p /= ps;

    const float* vbase = g_V + (size_t)zn * KI * DM + h * DK;
    float o0 = 0.f, o1 = 0.f;
    const int e = lane * 2;
    #pragma unroll 8
    for (int l2 = 0; l2 < KI; l2++) {
        float pv = __shfl_sync(0xffffffffu, p, l2);
        float2 vv = *(const float2*)(vbase + l2 * DM + e);
        o0 += pv * vv.x;
        o1 += pv * vv.y;
    }
    g_attn[(size_t)zn * DM + (e    ) * HN + h] = o0;
    g_attn[(size_t)zn * DM + (e + 1) * HN + h] = o1;
}

// ---------------- final projection ------------------------------------------
__global__ __launch_bounds__(256) void outproj_kernel(float* __restrict__ out) {
    __shared__ float s_x[TILE * DM];
    const int tid = threadIdx.x;
    const int tx = tid & 31, ty = tid >> 5;
    const int c0 = tx * 8, r0 = ty * 4;
    const size_t rbase = (size_t)blockIdx.x * TILE;
    {
        const float4* xg = (const float4*)(g_attn + rbase * DM);
        float4* sx = (float4*)s_x;
        #pragma unroll
        for (int i = 0; i < 8; i++) sx[tid + i * 256] = xg[tid + i * 256];
    }
    __syncthreads();
    float acc[4][8];
    #pragma unroll
    for (int i = 0; i < 4; i++)
        #pragma unroll
        for (int j = 0; j < 8; j++) acc[i][j] = 0.f;
    for (int k = 0; k < DM; k += 4) {
        float4 av[4];
        #pragma unroll
        for (int i = 0; i < 4; i++)
            av[i] = *(const float4*)(s_x + (r0 + i) * DM + k);
        #pragma unroll
        for (int kk = 0; kk < 4; kk++) {
            float4 w0 = *(const float4*)(g_WoT + (size_t)(k + kk) * DM + c0);
            float4 w1 = *(const float4*)(g_WoT + (size_t)(k + kk) * DM + c0 + 4);
            #pragma unroll
            for (int i = 0; i < 4; i++) {
                float a = (&av[i].x)[kk];
                FMA_ROW(acc[i], a, w0, w1);
            }
        }
    }
    #pragma unroll
    for (int i = 0; i < 4; i++) {
        *(float4*)(out + (rbase + r0 + i) * DM + c0) =
            make_float4(acc[i][0], acc[i][1], acc[i][2], acc[i][3]);
        *(float4*)(out + (rbase + r0 + i) * DM + c0 + 4) =
            make_float4(acc[i][4], acc[i][5], acc[i][6], acc[i][7]);
    }
}

// ---------------------------------------------------------------------------
extern "C" void kernel_launch(void* const* d_in, const int* in_sizes, int n_in,
                              void* d_out, int out_size)
{
    const float* nodes_i = (const float*)d_in[0];
    const float* edges   = (const float*)d_in[1];
    const float* nodes_j = (const float*)d_in[2];
    const void*  nmask   = d_in[3];
    const float* fkW1 = (const float*)d_in[4];
    const float* fkb1 = (const float*)d_in[5];
    const float* fkW2 = (const float*)d_in[6];
    const float* fkb2 = (const float*)d_in[7];
    const float* fvW1 = (const float*)d_in[8];
    const float* fvb1 = (const float*)d_in[9];
    const float* fvW2 = (const float*)d_in[10];
    const float* fvb2 = (const float*)d_in[11];
    const float* qproj = (const float*)d_in[12];
    const float* kproj = (const float*)d_in[13];
    const float* vproj = (const float*)d_in[14];
    const float* qbias = (const float*)d_in[15];
    const float* kbias = (const float*)d_in[16];
    const float* vbias = (const float*)d_in[17];
    const float* outW  = (const float*)d_in[18];

    static int configured = 0;
    if (!configured) {
        cudaFuncSetAttribute(film_mma_kernel,
                             cudaFuncAttributeMaxDynamicSharedMemorySize, SMEM_TC);
        configured = 1;
    }

    detect_mask_kernel<<<1, 1>>>(nmask, in_sizes[3]);
    transpose_w_kernel<<<(DM * DM) / 256, 256>>>(outW);
    pack_w_kernel<<<(32 * 16384) / 256, 256>>>(fkW1, fkW2, kproj, fvW1, fvW2, vproj);
    qproj_kernel<<<ZN / TILE, 256>>>(nodes_i, qproj, qbias);
    film_mma_kernel<<<NB, 256, SMEM_TC>>>(
        edges, nodes_j, fkb1, fkb2, kbias, fvb1, fvb2, vbias);
    attn_kernel<<<ZN, 128>>>(nmask);
    outproj_kernel<<<ZN / TILE, 256>>>((float*)d_out);
}

// round 5
// speedup vs baseline: 3.2358x; 1.0736x over previous
#include <cuda_runtime.h>
#include <cuda_bf16.h>
#include <cstdint>

#define DM 256
#define KI 32
#define HN 4
#define DK 64
#define ZN 4096             /* Z*N   */
#define ETOT 131072         /* edges */
#define TILE 32
#define QT 8                /* rows per qproj block */
#define MB 64               /* rows per film block */
#define NB (ETOT/MB)        /* 2048 film blocks */

// film smem layout (bytes): X/Y activation ping-pong + W chunk
#define X_HI 0
#define X_LO 32768
#define Y_HI 65536
#define Y_LO 98304
#define W_HI 131072
#define W_LO 163840
#define SMEM_TC 196608
#define WCH 65536           /* packed W chunk: hi 32KB + lo 32KB */

// ---------------- device scratch --------------------------------------------
__device__ float g_Q[(size_t)ZN * DM];
__device__ float g_K[(size_t)ETOT * DM];
__device__ float g_V[(size_t)ETOT * DM];
__device__ float g_attn[(size_t)ZN * DM];
__device__ float g_WoT[DM * DM];
__device__ int   g_mflag;
__device__ unsigned char g_Wp[32 * WCH];      // packed, swizzled bf16 weights (2MB)

// ---------------- asm helpers -----------------------------------------------
__device__ __forceinline__ uint32_t smem_u32(const void* p) {
    uint32_t a;
    asm("{ .reg .u64 t; cvta.to.shared.u64 t, %1; cvt.u32.u64 %0, t; }" : "=r"(a) : "l"(p));
    return a;
}
__device__ __forceinline__ void cpasync16(uint32_t d, const void* s) {
    asm volatile("cp.async.cg.shared.global [%0], [%1], 16;" :: "r"(d), "l"(s) : "memory");
}
#define CP_COMMIT() asm volatile("cp.async.commit_group;" ::: "memory")
__device__ __forceinline__ void cp_wait(int n) {
    switch (n) {
    case 0: asm volatile("cp.async.wait_group 0;" ::: "memory"); break;
    case 1: asm volatile("cp.async.wait_group 1;" ::: "memory"); break;
    case 2: asm volatile("cp.async.wait_group 2;" ::: "memory"); break;
    default: asm volatile("cp.async.wait_group 3;" ::: "memory"); break;
    }
}
__device__ __forceinline__ void ldsm4(uint32_t* r, uint32_t addr) {
    asm volatile("ldmatrix.sync.aligned.m8n8.x4.shared.b16 {%0,%1,%2,%3}, [%4];"
        : "=r"(r[0]), "=r"(r[1]), "=r"(r[2]), "=r"(r[3]) : "r"(addr));
}
__device__ __forceinline__ void ldsm4t(uint32_t* r, uint32_t addr) {
    asm volatile("ldmatrix.sync.aligned.m8n8.x4.trans.shared.b16 {%0,%1,%2,%3}, [%4];"
        : "=r"(r[0]), "=r"(r[1]), "=r"(r[2]), "=r"(r[3]) : "r"(addr));
}
__device__ __forceinline__ void mma16816(float* d, const uint32_t* a, const uint32_t* b) {
    asm volatile("mma.sync.aligned.m16n8k16.row.col.f32.bf16.bf16.f32 "
        "{%0,%1,%2,%3}, {%4,%5,%6,%7}, {%8,%9}, {%0,%1,%2,%3};"
        : "+f"(d[0]), "+f"(d[1]), "+f"(d[2]), "+f"(d[3])
        : "r"(a[0]), "r"(a[1]), "r"(a[2]), "r"(a[3]), "r"(b[0]), "r"(b[1]));
}
__device__ __forceinline__ uint32_t pack_bf2(__nv_bfloat16 a, __nv_bfloat16 b) {
    return ((uint32_t)__bfloat16_as_ushort(b) << 16) | __bfloat16_as_ushort(a);
}
// A smem swizzle: [r<64][c<256] bf16, row 512B, XOR bits[6:4] with r&7
__device__ __forceinline__ uint32_t a_off(int r, int c) {
    uint32_t o = ((uint32_t)r << 9) + ((uint32_t)c << 1);
    return o ^ (((uint32_t)r & 7u) << 4);
}
// W smem swizzle: [k<256][n<64] bf16, row 128B, XOR bits[6:4] with k&7
__device__ __forceinline__ uint32_t w_off(int k, int n) {
    uint32_t o = ((uint32_t)k << 7) + ((uint32_t)n << 1);
    return o ^ (((uint32_t)k & 7u) << 4);
}
__device__ __forceinline__ void split2b(char* smem, int hib, int lob,
                                        int r, int c, float x0, float x1) {
    __nv_bfloat16 h0 = __float2bfloat16(x0), h1 = __float2bfloat16(x1);
    __nv_bfloat16 l0 = __float2bfloat16(x0 - __bfloat162float(h0));
    __nv_bfloat16 l1 = __float2bfloat16(x1 - __bfloat162float(h1));
    uint32_t off = a_off(r, c);
    *(uint32_t*)(smem + hib + off) = pack_bf2(h0, h1);
    *(uint32_t*)(smem + lob + off) = pack_bf2(l0, l1);
}

// ---------------- setup kernels ---------------------------------------------
__global__ void detect_mask_kernel(const void* mask, int count) {
    if (threadIdx.x != 0 || blockIdx.x != 0) return;
    const unsigned int* u  = (const unsigned int*)mask;
    const float*        fp = (const float*)mask;
    int words = count / 4;
    int lim = words < 1024 ? words : 1024;
    bool int_ok = true, int_one = false, flt_ok = true, flt_one = false;
    for (int i = 0; i < lim; i++) {
        unsigned int v = u[i];
        if (v > 1u)  int_ok = false;
        if (v == 1u) int_one = true;
        float fv = fp[i];
        if (fv != 0.0f && fv != 1.0f) flt_ok = false;
        if (fv == 1.0f) flt_one = true;
    }
    g_mflag = (int_ok && int_one) ? 1 : (flt_ok && flt_one) ? 0 : 2;
}
__global__ void transpose_w_kernel(const float* __restrict__ W) {
    int idx = blockIdx.x * blockDim.x + threadIdx.x;
    if (idx < DM * DM) g_WoT[(idx & 255) * DM + (idx >> 8)] = W[idx];
}

// pack weights into swizzled bf16 hi/lo chunk images (exact smem layout).
// 32 chunks of [k=256][n=64]: path p = ch>>4; r = ch&15:
//   r<4  : W1, cols n = r*64 + j
//   r<12 : W2, gamma/beta interleaved at 8-col granularity
//   else : head proj
__global__ __launch_bounds__(256) void pack_w_kernel(
    const float* __restrict__ fkW1, const float* __restrict__ fkW2,
    const float* __restrict__ kproj,
    const float* __restrict__ fvW1, const float* __restrict__ fvW2,
    const float* __restrict__ vproj)
{
    int idx = blockIdx.x * 256 + threadIdx.x;   // 524288 total
    int ch = idx >> 14;
    int e  = idx & 16383;
    int k  = e >> 6, j = e & 63;
    int p = ch >> 4, r = ch & 15;
    float w;
    if (r < 4) {
        const float* W1 = p ? fvW1 : fkW1;
        w = W1[k * 256 + r * 64 + j];
    } else if (r < 12) {
        const float* W2 = p ? fvW2 : fkW2;
        int gc = (r - 4) * 32 + ((j >> 4) << 3) + (j & 7);
        int col = ((j >> 3) & 1) ? 256 + gc : gc;
        w = W2[k * 512 + col];
    } else {
        const float* P = p ? vproj : kproj;
        int n = (r - 12) * 64 + j;
        w = P[(n >> 6) * 16384 + k * 64 + (n & 63)];
    }
    __nv_bfloat16 hi = __float2bfloat16(w);
    __nv_bfloat16 lo = __float2bfloat16(w - __bfloat162float(hi));
    uint32_t off = w_off(k, j);
    size_t base = (size_t)ch * WCH;
    *(unsigned short*)(g_Wp + base + off)         = __bfloat16_as_ushort(hi);
    *(unsigned short*)(g_Wp + base + 32768 + off) = __bfloat16_as_ushort(lo);
}

// ---------------- warp-MMA FiLM + K/V projections (in-smem chained) ---------
__global__ __launch_bounds__(256, 1) void film_mma_kernel(
    const float* __restrict__ edges, const float* __restrict__ nodesj,
    const float* __restrict__ fkb1, const float* __restrict__ fkb2,
    const float* __restrict__ kbias,
    const float* __restrict__ fvb1, const float* __restrict__ fvb2,
    const float* __restrict__ vbias)
{
    extern __shared__ char smem[];
    const uint32_t sb = smem_u32(smem);
    const int tid  = threadIdx.x;
    const int wid  = tid >> 5, lane = tid & 31;
    const int mw   = wid & 1, nwi = wid >> 1;    // warp tile: rows mw*32, cols nwi*16
    const int g    = lane >> 2, tig = lane & 3;
    const size_t ebase = (size_t)blockIdx.x * MB;

    const int amr = lane & 15;            // A ldmatrix row
    const int akb = (lane >> 4) << 3;     // A k offset 0/8
    const int bkr = lane & 15;            // B k row
    const int bnb = (lane >> 4) << 3;     // B n offset 0/8

    #pragma unroll 1
    for (int f = 0; f < 2; f++) {
        const float* b1 = f ? fvb1 : fkb1;
        const float* b2 = f ? fvb2 : fkb2;
        const float* bp = f ? vbias : kbias;
        float* gout = f ? g_V : g_K;

        #pragma unroll 1
        for (int s = 0; s < 3; s++) {
            const int nc  = (s == 1) ? 8 : 4;
            const int chb = f * 16 + (s == 0 ? 0 : (s == 1 ? 4 : 12));
            const int in_hi  = (s == 1) ? Y_HI : X_HI;
            const int in_lo  = (s == 1) ? Y_LO : X_LO;
            const int out_hi = (s == 0) ? Y_HI : X_HI;
            const int out_lo = (s == 0) ? Y_LO : X_LO;

            #pragma unroll 1
            for (int c = 0; c < nc; c++) {
                __syncthreads();   // W buffer free, A buffers stable

                // issue W chunk as 4 pipelined 16KB k-slices
                {
                    const unsigned char* wsrc = g_Wp + (size_t)(chb + c) * WCH;
                    #pragma unroll
                    for (int sl = 0; sl < 4; sl++) {
                        uint32_t so = (uint32_t)sl * 8192 + (uint32_t)tid * 16;
                        cpasync16(sb + W_HI + so,        wsrc + so);
                        cpasync16(sb + W_HI + so + 4096, wsrc + so + 4096);
                        cpasync16(sb + W_LO + so,        wsrc + 32768 + so);
                        cpasync16(sb + W_LO + so + 4096, wsrc + 32768 + so + 4096);
                        CP_COMMIT();
                    }
                }
                // first chunk of stage 0: split edges into X while W streams
                if (s == 0 && c == 0) {
                    const float* asrc = edges + ebase * DM;
                    #pragma unroll 1
                    for (int i = 0; i < 16; i++) {
                        int fi = tid + i * 256;          // 4096 float4
                        int r  = fi >> 6;
                        int cc = (fi & 63) << 2;
                        float4 v = *(const float4*)(asrc + ((size_t)fi << 2));
                        split2b(smem, X_HI, X_LO, r, cc,     v.x, v.y);
                        split2b(smem, X_HI, X_LO, r, cc + 2, v.z, v.w);
                    }
                }

                // ---- GEMM: acc[2 mfrag][2 nfrag][4] ----
                float acc[2][2][4];
                #pragma unroll
                for (int i = 0; i < 2; i++)
                    #pragma unroll
                    for (int jj = 0; jj < 2; jj++)
                        #pragma unroll
                        for (int q = 0; q < 4; q++) acc[i][jj][q] = 0.f;

                #pragma unroll 1
                for (int sl = 0; sl < 4; sl++) {
                    cp_wait(3 - sl);
                    __syncthreads();
                    #pragma unroll
                    for (int ki = 0; ki < 4; ki++) {
                        const int k0 = sl * 64 + ki * 16;
                        uint32_t Ah[2][4], Al[2][4], Bh[4], Bl[4];
                        #pragma unroll
                        for (int im = 0; im < 2; im++) {
                            uint32_t off = a_off(mw * 32 + im * 16 + amr, k0 + akb);
                            ldsm4(Ah[im], sb + in_hi + off);
                            ldsm4(Al[im], sb + in_lo + off);
                        }
                        {
                            uint32_t off = w_off(k0 + bkr, nwi * 16 + bnb);
                            ldsm4t(Bh, sb + W_HI + off);
                            ldsm4t(Bl, sb + W_LO + off);
                        }
                        // term-interleaved issue: same-acc MMAs spaced by 4
                        #pragma unroll
                        for (int im = 0; im < 2; im++)
                            #pragma unroll
                            for (int jb = 0; jb < 2; jb++)
                                mma16816(acc[im][jb], Ah[im], &Bh[jb * 2]);
                        #pragma unroll
                        for (int im = 0; im < 2; im++)
                            #pragma unroll
                            for (int jb = 0; jb < 2; jb++)
                                mma16816(acc[im][jb], Al[im], &Bh[jb * 2]);
                        #pragma unroll
                        for (int im = 0; im < 2; im++)
                            #pragma unroll
                            for (int jb = 0; jb < 2; jb++)
                                mma16816(acc[im][jb], Ah[im], &Bl[jb * 2]);
                    }
                }

                // ---- epilogue ----
                if (s == 0) {            // h = silu(D + b1) -> Y (smem split)
                    #pragma unroll
                    for (int im = 0; im < 2; im++) {
                        int rb = mw * 32 + im * 16 + g;
                        #pragma unroll
                        for (int jb = 0; jb < 2; jb++) {
                            int col = c * 64 + nwi * 16 + jb * 8 + 2 * tig;
                            float bb0 = b1[col], bb1 = b1[col + 1];
                            #pragma unroll
                            for (int hf = 0; hf < 2; hf++) {
                                float x0 = acc[im][jb][hf * 2]     + bb0;
                                float x1 = acc[im][jb][hf * 2 + 1] + bb1;
                                x0 = x0 / (1.0f + __expf(-x0));
                                x1 = x1 / (1.0f + __expf(-x1));
                                split2b(smem, out_hi, out_lo, rb + hf * 8, col, x0, x1);
                            }
                        }
                    }
                } else if (s == 1) {     // k_in = (g+b2g)*nj + (b+b2b) -> X
                    #pragma unroll
                    for (int im = 0; im < 2; im++) {
                        int rb = mw * 32 + im * 16 + g;
                        int gc = c * 32 + nwi * 8 + 2 * tig;
                        float bg0 = b2[gc], bg1 = b2[gc + 1];
                        float bb0 = b2[256 + gc], bb1 = b2[256 + gc + 1];
                        #pragma unroll
                        for (int hf = 0; hf < 2; hf++) {
                            int r = rb + hf * 8;
                            float2 nj = *(const float2*)(nodesj + (ebase + r) * DM + gc);
                            float ga0 = acc[im][0][hf * 2]     + bg0;
                            float ga1 = acc[im][0][hf * 2 + 1] + bg1;
                            float be0 = acc[im][1][hf * 2]     + bb0;
                            float be1 = acc[im][1][hf * 2 + 1] + bb1;
                            split2b(smem, out_hi, out_lo, r, gc,
                                    ga0 * nj.x + be0, ga1 * nj.y + be1);
                        }
                    }
                } else {                 // KV = D + bp -> g_K / g_V
                    #pragma unroll
                    for (int im = 0; im < 2; im++) {
                        int rb = mw * 32 + im * 16 + g;
                        #pragma unroll
                        for (int jb = 0; jb < 2; jb++) {
                            int col = c * 64 + nwi * 16 + jb * 8 + 2 * tig;
                            float bb0 = bp[col], bb1 = bp[col + 1];
                            #pragma unroll
                            for (int hf = 0; hf < 2; hf++) {
                                size_t row = ebase + rb + hf * 8;
                                *(float2*)(gout + row * DM + col) =
                                    make_float2(acc[im][jb][hf * 2]     + bb0,
                                                acc[im][jb][hf * 2 + 1] + bb1);
                            }
                        }
                    }
                }
            }
        }
    }
}

// ---------------- Q projection: 512 blocks x 8 rows, col-per-thread ---------
__global__ __launch_bounds__(256) void qproj_kernel(
    const float* __restrict__ x, const float* __restrict__ qp,
    const float* __restrict__ qb)
{
    __shared__ float s_x[QT * DM];
    const int tid = threadIdx.x;
    const size_t rbase = (size_t)blockIdx.x * QT;
    {
        const float4* xg = (const float4*)(x + rbase * DM);
        float4* sx = (float4*)s_x;
        sx[tid]       = xg[tid];
        sx[tid + 256] = xg[tid + 256];
    }
    __syncthreads();
    const int c = tid;
    const int h = c >> 6, e = c & 63;
    const float* W = qp + (size_t)h * DM * DK + e;
    float acc[QT];
    #pragma unroll
    for (int r = 0; r < QT; r++) acc[r] = 0.f;
    #pragma unroll 4
    for (int k = 0; k < DM; k++) {
        float w = W[(size_t)k * DK];
        #pragma unroll
        for (int r = 0; r < QT; r++) acc[r] += s_x[r * DM + k] * w;
    }
    float bb = qb[c];
    #pragma unroll
    for (int r = 0; r < QT; r++)
        g_Q[(rbase + r) * DM + c] = acc[r] + bb;
}

// ---------------- attention over 32 neighbors, one warp per head ------------
__global__ __launch_bounds__(128) void attn_kernel(const void* __restrict__ mask) {
    const int zn = blockIdx.x;
    const int tid = threadIdx.x;
    const int h = tid >> 5;
    const int lane = tid & 31;
    __shared__ float q_s[DM];
    q_s[tid]       = g_Q[(size_t)zn * DM + tid];
    q_s[tid + 128] = g_Q[(size_t)zn * DM + tid + 128];
    __syncthreads();

    const float* krow = g_K + ((size_t)zn * KI + lane) * DM + h * DK;
    float s = 0.f;
    #pragma unroll
    for (int e = 0; e < DK; e += 4) {
        float4 kv = *(const float4*)(krow + e);
        s += q_s[h * DK + e]     * kv.x + q_s[h * DK + e + 1] * kv.y
           + q_s[h * DK + e + 2] * kv.z + q_s[h * DK + e + 3] * kv.w;
    }
    s *= 0.125f;

    int flag = g_mflag;
    size_t midx = (size_t)zn * KI + lane;
    bool mv;
    if (flag == 2)      mv = ((const unsigned char*)mask)[midx] != 0;
    else if (flag == 1) mv = ((const int*)mask)[midx] != 0;
    else                mv = ((const float*)mask)[midx] != 0.0f;
    bool inv = !mv;
    unsigned bal = __ballot_sync(0xffffffffu, inv);
    if (inv && bal != 0xffffffffu) s = __int_as_float(0xff800000);

    float mx = s;
    #pragma unroll
    for (int o = 16; o > 0; o >>= 1)
        mx = fmaxf(mx, __shfl_xor_sync(0xffffffffu, mx, o));
    float p = __expf(s - mx);
    float ps = p;
    #pragma unroll
    for (int o = 16; o > 0; o >>= 1)
        ps += __shfl_xor_sync(0xffffffffu, ps, o);
    p /= ps;

    const float* vbase = g_V + (size_t)zn * KI * DM + h * DK;
    float o0 = 0.f, o1 = 0.f;
    const int e = lane * 2;
    #pragma unroll 8
    for (int l2 = 0; l2 < KI; l2++) {
        float pv = __shfl_sync(0xffffffffu, p, l2);
        float2 vv = *(const float2*)(vbase + l2 * DM + e);
        o0 += pv * vv.x;
        o1 += pv * vv.y;
    }
    g_attn[(size_t)zn * DM + (e    ) * HN + h] = o0;
    g_attn[(size_t)zn * DM + (e + 1) * HN + h] = o1;
}

// ---------------- final projection ------------------------------------------
#define FMA_ROW(ACCI, A, W0, W1) \
    do { \
        (ACCI)[0] += (A)*(W0).x; (ACCI)[1] += (A)*(W0).y; \
        (ACCI)[2] += (A)*(W0).z; (ACCI)[3] += (A)*(W0).w; \
        (ACCI)[4] += (A)*(W1).x; (ACCI)[5] += (A)*(W1).y; \
        (ACCI)[6] += (A)*(W1).z; (ACCI)[7] += (A)*(W1).w; \
    } while (0)

__global__ __launch_bounds__(256) void outproj_kernel(float* __restrict__ out) {
    __shared__ float s_x[TILE * DM];
    const int tid = threadIdx.x;
    const int tx = tid & 31, ty = tid >> 5;
    const int c0 = tx * 8, r0 = ty * 4;
    const size_t rbase = (size_t)blockIdx.x * TILE;
    {
        const float4* xg = (const float4*)(g_attn + rbase * DM);
        float4* sx = (float4*)s_x;
        #pragma unroll
        for (int i = 0; i < 8; i++) sx[tid + i * 256] = xg[tid + i * 256];
    }
    __syncthreads();
    float acc[4][8];
    #pragma unroll
    for (int i = 0; i < 4; i++)
        #pragma unroll
        for (int j = 0; j < 8; j++) acc[i][j] = 0.f;
    for (int k = 0; k < DM; k += 4) {
        float4 av[4];
        #pragma unroll
        for (int i = 0; i < 4; i++)
            av[i] = *(const float4*)(s_x + (r0 + i) * DM + k);
        #pragma unroll
        for (int kk = 0; kk < 4; kk++) {
            float4 w0 = *(const float4*)(g_WoT + (size_t)(k + kk) * DM + c0);
            float4 w1 = *(const float4*)(g_WoT + (size_t)(k + kk) * DM + c0 + 4);
            #pragma unroll
            for (int i = 0; i < 4; i++) {
                float a = (&av[i].x)[kk];
                FMA_ROW(acc[i], a, w0, w1);
            }
        }
    }
    #pragma unroll
    for (int i = 0; i < 4; i++) {
        *(float4*)(out + (rbase + r0 + i) * DM + c0) =
            make_float4(acc[i][0], acc[i][1], acc[i][2], acc[i][3]);
        *(float4*)(out + (rbase + r0 + i) * DM + c0 + 4) =
            make_float4(acc[i][4], acc[i][5], acc[i][6], acc[i][7]);
    }
}

// ---------------------------------------------------------------------------
extern "C" void kernel_launch(void* const* d_in, const int* in_sizes, int n_in,
                              void* d_out, int out_size)
{
    const float* nodes_i = (const float*)d_in[0];
    const float* edges   = (const float*)d_in[1];
    const float* nodes_j = (const float*)d_in[2];
    const void*  nmask   = d_in[3];
    const float* fkW1 = (const float*)d_in[4];
    const float* fkb1 = (const float*)d_in[5];
    const float* fkW2 = (const float*)d_in[6];
    const float* fkb2 = (const float*)d_in[7];
    const float* fvW1 = (const float*)d_in[8];
    const float* fvb1 = (const float*)d_in[9];
    const float* fvW2 = (const float*)d_in[10];
    const float* fvb2 = (const float*)d_in[11];
    const float* qproj = (const float*)d_in[12];
    const float* kproj = (const float*)d_in[13];
    const float* vproj = (const float*)d_in[14];
    const float* qbias = (const float*)d_in[15];
    const float* kbias = (const float*)d_in[16];
    const float* vbias = (const float*)d_in[17];
    const float* outW  = (const float*)d_in[18];

    static int configured = 0;
    if (!configured) {
        cudaFuncSetAttribute(film_mma_kernel,
                             cudaFuncAttributeMaxDynamicSharedMemorySize, SMEM_TC);
        configured = 1;
    }

    detect_mask_kernel<<<1, 1>>>(nmask, in_sizes[3]);
    transpose_w_kernel<<<(DM * DM) / 256, 256>>>(outW);
    pack_w_kernel<<<(32 * 16384) / 256, 256>>>(fkW1, fkW2, kproj, fvW1, fvW2, vproj);
    qproj_kernel<<<ZN / QT, 256>>>(nodes_i, qproj, qbias);
    film_mma_kernel<<<NB, 256, SMEM_TC>>>(
        edges, nodes_j, fkb1, fkb2, kbias, fvb1, fvb2, vbias);
    attn_kernel<<<ZN, 128>>>(nmask);
    outproj_kernel<<<ZN / TILE, 256>>>((float*)d_out);
}

// round 6
// speedup vs baseline: 3.7673x; 1.1643x over previous
#include <cuda_runtime.h>
#include <cuda_bf16.h>
#include <cstdint>

#define DM 256
#define KI 32
#define HN 4
#define DK 64
#define ZN 4096             /* Z*N   */
#define ETOT 131072         /* edges */
#define TILE 32
#define QT 8
#define MB 64               /* rows per film block */
#define NB (ETOT/MB)        /* 2048 film blocks */

// film smem layout (bytes)
#define X_HI 0
#define X_LO 32768
#define Y_HI 65536
#define Y_LO 98304
#define WB0  131072         /* W slice buffers: 2 x 32KB (hi 16K + lo 16K) */
#define SMEM_TC 196608

// packed W: per path (1MB): s0 @0 (8 slices), s1 @256KB (16), s2 @768KB (8)
#define PATH_STRIDE 1048576
#define S1_OFF 262144
#define S2_OFF 786432

// ---------------- device scratch --------------------------------------------
__device__ float g_Q[(size_t)ZN * DM];
__device__ float g_K[(size_t)ETOT * DM];
__device__ float g_V[(size_t)ETOT * DM];
__device__ float g_attn[(size_t)ZN * DM];
__device__ float g_WoT[DM * DM];
__device__ int   g_mflag;
__device__ unsigned char g_Wp[2 * PATH_STRIDE];   // 2MB packed weights

// ---------------- asm helpers -----------------------------------------------
__device__ __forceinline__ uint32_t smem_u32(const void* p) {
    uint32_t a;
    asm("{ .reg .u64 t; cvta.to.shared.u64 t, %1; cvt.u32.u64 %0, t; }" : "=r"(a) : "l"(p));
    return a;
}
__device__ __forceinline__ void cpasync16(uint32_t d, const void* s) {
    asm volatile("cp.async.cg.shared.global [%0], [%1], 16;" :: "r"(d), "l"(s) : "memory");
}
#define CP_COMMIT() asm volatile("cp.async.commit_group;" ::: "memory")
#define CP_WAIT0()  asm volatile("cp.async.wait_group 0;" ::: "memory")
__device__ __forceinline__ void ldsm4(uint32_t* r, uint32_t addr) {
    asm volatile("ldmatrix.sync.aligned.m8n8.x4.shared.b16 {%0,%1,%2,%3}, [%4];"
        : "=r"(r[0]), "=r"(r[1]), "=r"(r[2]), "=r"(r[3]) : "r"(addr));
}
__device__ __forceinline__ void ldsm4t(uint32_t* r, uint32_t addr) {
    asm volatile("ldmatrix.sync.aligned.m8n8.x4.trans.shared.b16 {%0,%1,%2,%3}, [%4];"
        : "=r"(r[0]), "=r"(r[1]), "=r"(r[2]), "=r"(r[3]) : "r"(addr));
}
__device__ __forceinline__ void mma16816(float* d, const uint32_t* a, const uint32_t* b) {
    asm volatile("mma.sync.aligned.m16n8k16.row.col.f32.bf16.bf16.f32 "
        "{%0,%1,%2,%3}, {%4,%5,%6,%7}, {%8,%9}, {%0,%1,%2,%3};"
        : "+f"(d[0]), "+f"(d[1]), "+f"(d[2]), "+f"(d[3])
        : "r"(a[0]), "r"(a[1]), "r"(a[2]), "r"(a[3]), "r"(b[0]), "r"(b[1]));
}
__device__ __forceinline__ uint32_t pack_bf2(__nv_bfloat16 a, __nv_bfloat16 b) {
    return ((uint32_t)__bfloat16_as_ushort(b) << 16) | __bfloat16_as_ushort(a);
}
// A smem: [r<64][c<256] bf16, row 512B, XOR bits[6:4] with r&7
__device__ __forceinline__ uint32_t a_off(int r, int c) {
    uint32_t o = ((uint32_t)r << 9) + ((uint32_t)c << 1);
    return o ^ (((uint32_t)r & 7u) << 4);
}
// W slice: [k<KS][n<Nst] bf16, row RB bytes, XOR bits[6:4] with k&7
__device__ __forceinline__ uint32_t wsw(uint32_t o, int k) {
    return o ^ (((uint32_t)k & 7u) << 4);
}
__device__ __forceinline__ void split2b(char* smem, int hib, int lob,
                                        int r, int c, float x0, float x1) {
    __nv_bfloat16 h0 = __float2bfloat16(x0), h1 = __float2bfloat16(x1);
    __nv_bfloat16 l0 = __float2bfloat16(x0 - __bfloat162float(h0));
    __nv_bfloat16 l1 = __float2bfloat16(x1 - __bfloat162float(h1));
    uint32_t off = a_off(r, c);
    *(uint32_t*)(smem + hib + off) = pack_bf2(h0, h1);
    *(uint32_t*)(smem + lob + off) = pack_bf2(l0, l1);
}

// ---------------- setup kernels ---------------------------------------------
__global__ void detect_mask_kernel(const void* mask, int count) {
    if (threadIdx.x != 0 || blockIdx.x != 0) return;
    const unsigned int* u  = (const unsigned int*)mask;
    const float*        fp = (const float*)mask;
    int words = count / 4;
    int lim = words < 1024 ? words : 1024;
    bool int_ok = true, int_one = false, flt_ok = true, flt_one = false;
    for (int i = 0; i < lim; i++) {
        unsigned int v = u[i];
        if (v > 1u)  int_ok = false;
        if (v == 1u) int_one = true;
        float fv = fp[i];
        if (fv != 0.0f && fv != 1.0f) flt_ok = false;
        if (fv == 1.0f) flt_one = true;
    }
    g_mflag = (int_ok && int_one) ? 1 : (flt_ok && flt_one) ? 0 : 2;
}
__global__ void transpose_w_kernel(const float* __restrict__ W) {
    int idx = blockIdx.x * blockDim.x + threadIdx.x;
    if (idx < DM * DM) g_WoT[(idx & 255) * DM + (idx >> 8)] = W[idx];
}

// pack weights: per path, per stage, k-slice images (hi 16KB + lo 16KB).
// s0: N=256 KS=32 RB=512 ; s1: N=512 KS=16 RB=1024 (gamma/beta interleaved);
// s2: N=256 KS=32 RB=512 (head-major cols).
__global__ __launch_bounds__(256) void pack_w_kernel(
    const float* __restrict__ fkW1, const float* __restrict__ fkW2,
    const float* __restrict__ kproj,
    const float* __restrict__ fvW1, const float* __restrict__ fvW2,
    const float* __restrict__ vproj)
{
    int idx = blockIdx.x * 256 + threadIdx.x;   // 524288 total
    int f = idx >> 18;
    int r = idx & 262143;
    float w;
    size_t dst;
    if (r < 65536) {                       // s0: W1
        int k = r >> 8, n = r & 255;
        const float* W1 = f ? fvW1 : fkW1;
        w = W1[k * 256 + n];
        int q = k >> 5, kk = k & 31;
        dst = (size_t)f * PATH_STRIDE + (size_t)q * 32768
            + wsw((uint32_t)kk * 512 + (uint32_t)n * 2, kk);
    } else if (r < 196608) {               // s1: W2 gamma/beta interleave
        int e = r - 65536;
        int k = e >> 9, n = e & 511;
        int wg = n >> 6, j = n & 63;
        int gc = wg * 32 + ((j >> 4) << 3) + (j & 7);
        int src = ((j >> 3) & 1) ? 256 + gc : gc;
        const float* W2 = f ? fvW2 : fkW2;
        w = W2[k * 512 + src];
        int q = k >> 4, kk = k & 15;
        dst = (size_t)f * PATH_STRIDE + S1_OFF + (size_t)q * 32768
            + wsw((uint32_t)kk * 1024 + (uint32_t)n * 2, kk);
    } else {                               // s2: head proj
        int e = r - 196608;
        int k = e >> 8, n = e & 255;
        const float* P = f ? vproj : kproj;
        w = P[(n >> 6) * 16384 + k * 64 + (n & 63)];
        int q = k >> 5, kk = k & 31;
        dst = (size_t)f * PATH_STRIDE + S2_OFF + (size_t)q * 32768
            + wsw((uint32_t)kk * 512 + (uint32_t)n * 2, kk);
    }
    __nv_bfloat16 hi = __float2bfloat16(w);
    __nv_bfloat16 lo = __float2bfloat16(w - __bfloat162float(hi));
    *(unsigned short*)(g_Wp + dst)         = __bfloat16_as_ushort(hi);
    *(unsigned short*)(g_Wp + dst + 16384) = __bfloat16_as_ushort(lo);
}

// ---------------- warp-MMA FiLM + K/V (K-streaming, full-N accumulators) ----
__global__ __launch_bounds__(256, 1) void film_mma_kernel(
    const float* __restrict__ edges, const float* __restrict__ nodesj,
    const float* __restrict__ fkb1, const float* __restrict__ fkb2,
    const float* __restrict__ kbias,
    const float* __restrict__ fvb1, const float* __restrict__ fvb2,
    const float* __restrict__ vbias)
{
    extern __shared__ char smem[];
    const uint32_t sb = smem_u32(smem);
    const int tid  = threadIdx.x;
    const int wid  = tid >> 5, lane = tid & 31;
    const int g    = lane >> 2, tig = lane & 3;
    const size_t ebase = (size_t)blockIdx.x * MB;

    const int amr = lane & 15;            // A ldmatrix row
    const int akb = (lane >> 4) << 3;     // A k offset 0/8
    const int bkr = lane & 15;            // B k row
    const int bnb = (lane >> 4) << 3;     // B n offset 0/8

    #pragma unroll 1
    for (int f = 0; f < 2; f++) {
        const float* b1 = f ? fvb1 : fkb1;
        const float* b2 = f ? fvb2 : fkb2;
        const float* bp = f ? vbias : kbias;
        float* gout = f ? g_V : g_K;
        const unsigned char* pbase = g_Wp + (size_t)f * PATH_STRIDE;

        // ================= stage 0: h = silu(edges @ W1 + b1) =================
        {
            __syncthreads();
            const unsigned char* wsrc = pbase;
            #pragma unroll
            for (int i = 0; i < 8; i++)
                cpasync16(sb + WB0 + tid * 16 + i * 4096, wsrc + tid * 16 + i * 4096);
            CP_COMMIT();

            // split edges -> X while W streams
            {
                const float* asrc = edges + ebase * DM;
                #pragma unroll 1
                for (int i = 0; i < 16; i++) {
                    int fi = tid + i * 256;
                    int rr = fi >> 6;
                    int cc = (fi & 63) << 2;
                    float4 v = *(const float4*)(asrc + ((size_t)fi << 2));
                    split2b(smem, X_HI, X_LO, rr, cc,     v.x, v.y);
                    split2b(smem, X_HI, X_LO, rr, cc + 2, v.z, v.w);
                }
            }

            float acc[4][4][4];
            #pragma unroll
            for (int a = 0; a < 4; a++)
                #pragma unroll
                for (int b = 0; b < 4; b++)
                    #pragma unroll
                    for (int c = 0; c < 4; c++) acc[a][b][c] = 0.f;

            #pragma unroll 1
            for (int q = 0; q < 8; q++) {
                CP_WAIT0();
                __syncthreads();
                if (q + 1 < 8) {
                    const unsigned char* ns = wsrc + (size_t)(q + 1) * 32768;
                    uint32_t nd = sb + WB0 + ((q + 1) & 1) * 32768;
                    #pragma unroll
                    for (int i = 0; i < 8; i++)
                        cpasync16(nd + tid * 16 + i * 4096, ns + tid * 16 + i * 4096);
                    CP_COMMIT();
                }
                uint32_t wb = sb + WB0 + (q & 1) * 32768;
                #pragma unroll
                for (int ki = 0; ki < 2; ki++) {
                    int kc = q * 32 + ki * 16;
                    int ks = ki * 16;
                    uint32_t Ah[4][4], Al[4][4], Bh[2][4], Bl[2][4];
                    #pragma unroll
                    for (int im = 0; im < 4; im++) {
                        uint32_t off = a_off(im * 16 + amr, kc + akb);
                        ldsm4(Ah[im], sb + X_HI + off);
                        ldsm4(Al[im], sb + X_LO + off);
                    }
                    #pragma unroll
                    for (int nb = 0; nb < 2; nb++) {
                        int kr = ks + bkr;
                        uint32_t off = wsw((uint32_t)kr * 512 +
                                           (uint32_t)(wid * 32 + nb * 16 + bnb) * 2, kr);
                        ldsm4t(Bh[nb], wb + off);
                        ldsm4t(Bl[nb], wb + 16384 + off);
                    }
                    #pragma unroll
                    for (int im = 0; im < 4; im++)
                        #pragma unroll
                        for (int jn = 0; jn < 4; jn++)
                            mma16816(acc[im][jn], Ah[im], &Bh[jn >> 1][(jn & 1) * 2]);
                    #pragma unroll
                    for (int im = 0; im < 4; im++)
                        #pragma unroll
                        for (int jn = 0; jn < 4; jn++)
                            mma16816(acc[im][jn], Al[im], &Bh[jn >> 1][(jn & 1) * 2]);
                    #pragma unroll
                    for (int im = 0; im < 4; im++)
                        #pragma unroll
                        for (int jn = 0; jn < 4; jn++)
                            mma16816(acc[im][jn], Ah[im], &Bl[jn >> 1][(jn & 1) * 2]);
                }
            }
            // epilogue: silu -> Y
            #pragma unroll
            for (int im = 0; im < 4; im++)
                #pragma unroll
                for (int jn = 0; jn < 4; jn++) {
                    int col = wid * 32 + jn * 8 + 2 * tig;
                    float bb0 = b1[col], bb1 = b1[col + 1];
                    #pragma unroll
                    for (int hf = 0; hf < 2; hf++) {
                        int rr = im * 16 + g + hf * 8;
                        float x0 = acc[im][jn][hf * 2]     + bb0;
                        float x1 = acc[im][jn][hf * 2 + 1] + bb1;
                        x0 = x0 / (1.0f + __expf(-x0));
                        x1 = x1 / (1.0f + __expf(-x1));
                        split2b(smem, Y_HI, Y_LO, rr, col, x0, x1);
                    }
                }
        }

        // ================= stage 1: gb = h @ W2; film -> X =====================
        {
            __syncthreads();
            const unsigned char* wsrc = pbase + S1_OFF;
            #pragma unroll
            for (int i = 0; i < 8; i++)
                cpasync16(sb + WB0 + tid * 16 + i * 4096, wsrc + tid * 16 + i * 4096);
            CP_COMMIT();

            float acc[4][8][4];
            #pragma unroll
            for (int a = 0; a < 4; a++)
                #pragma unroll
                for (int b = 0; b < 8; b++)
                    #pragma unroll
                    for (int c = 0; c < 4; c++) acc[a][b][c] = 0.f;

            #pragma unroll 1
            for (int q = 0; q < 16; q++) {
                CP_WAIT0();
                __syncthreads();
                if (q + 1 < 16) {
                    const unsigned char* ns = wsrc + (size_t)(q + 1) * 32768;
                    uint32_t nd = sb + WB0 + ((q + 1) & 1) * 32768;
                    #pragma unroll
                    for (int i = 0; i < 8; i++)
                        cpasync16(nd + tid * 16 + i * 4096, ns + tid * 16 + i * 4096);
                    CP_COMMIT();
                }
                uint32_t wb = sb + WB0 + (q & 1) * 32768;
                int kc = q * 16;
                uint32_t Ah[4][4], Al[4][4];
                #pragma unroll
                for (int im = 0; im < 4; im++) {
                    uint32_t off = a_off(im * 16 + amr, kc + akb);
                    ldsm4(Ah[im], sb + Y_HI + off);
                    ldsm4(Al[im], sb + Y_LO + off);
                }
                #pragma unroll
                for (int jg = 0; jg < 4; jg++) {
                    uint32_t Bh[4], Bl[4];
                    uint32_t off = wsw((uint32_t)bkr * 1024 +
                                       (uint32_t)(wid * 64 + jg * 16 + bnb) * 2, bkr);
                    ldsm4t(Bh, wb + off);
                    ldsm4t(Bl, wb + 16384 + off);
                    #pragma unroll
                    for (int im = 0; im < 4; im++) {
                        mma16816(acc[im][jg * 2],     Ah[im], &Bh[0]);
                        mma16816(acc[im][jg * 2 + 1], Ah[im], &Bh[2]);
                    }
                    #pragma unroll
                    for (int im = 0; im < 4; im++) {
                        mma16816(acc[im][jg * 2],     Al[im], &Bh[0]);
                        mma16816(acc[im][jg * 2 + 1], Al[im], &Bh[2]);
                    }
                    #pragma unroll
                    for (int im = 0; im < 4; im++) {
                        mma16816(acc[im][jg * 2],     Ah[im], &Bl[0]);
                        mma16816(acc[im][jg * 2 + 1], Ah[im], &Bl[2]);
                    }
                }
            }
            // epilogue: (gamma+bg)*nj + (beta+bb) -> X
            #pragma unroll
            for (int im = 0; im < 4; im++)
                #pragma unroll
                for (int t = 0; t < 4; t++) {
                    int gc = wid * 32 + t * 8 + 2 * tig;
                    float bg0 = b2[gc],       bg1 = b2[gc + 1];
                    float bb0 = b2[256 + gc], bb1 = b2[256 + gc + 1];
                    #pragma unroll
                    for (int hf = 0; hf < 2; hf++) {
                        int rr = im * 16 + g + hf * 8;
                        float2 nj = *(const float2*)(nodesj + (ebase + rr) * DM + gc);
                        float ga0 = acc[im][t * 2][hf * 2]         + bg0;
                        float ga1 = acc[im][t * 2][hf * 2 + 1]     + bg1;
                        float be0 = acc[im][t * 2 + 1][hf * 2]     + bb0;
                        float be1 = acc[im][t * 2 + 1][hf * 2 + 1] + bb1;
                        split2b(smem, X_HI, X_LO, rr, gc,
                                ga0 * nj.x + be0, ga1 * nj.y + be1);
                    }
                }
        }

        // ================= stage 2: KV = k_in @ proj + bias -> global =========
        {
            __syncthreads();
            const unsigned char* wsrc = pbase + S2_OFF;
            #pragma unroll
            for (int i = 0; i < 8; i++)
                cpasync16(sb + WB0 + tid * 16 + i * 4096, wsrc + tid * 16 + i * 4096);
            CP_COMMIT();

            float acc[4][4][4];
            #pragma unroll
            for (int a = 0; a < 4; a++)
                #pragma unroll
                for (int b = 0; b < 4; b++)
                    #pragma unroll
                    for (int c = 0; c < 4; c++) acc[a][b][c] = 0.f;

            #pragma unroll 1
            for (int q = 0; q < 8; q++) {
                CP_WAIT0();
                __syncthreads();
                if (q + 1 < 8) {
                    const unsigned char* ns = wsrc + (size_t)(q + 1) * 32768;
                    uint32_t nd = sb + WB0 + ((q + 1) & 1) * 32768;
                    #pragma unroll
                    for (int i = 0; i < 8; i++)
                        cpasync16(nd + tid * 16 + i * 4096, ns + tid * 16 + i * 4096);
                    CP_COMMIT();
                }
                uint32_t wb = sb + WB0 + (q & 1) * 32768;
                #pragma unroll
                for (int ki = 0; ki < 2; ki++) {
                    int kc = q * 32 + ki * 16;
                    int ks = ki * 16;
                    uint32_t Ah[4][4], Al[4][4], Bh[2][4], Bl[2][4];
                    #pragma unroll
                    for (int im = 0; im < 4; im++) {
                        uint32_t off = a_off(im * 16 + amr, kc + akb);
                        ldsm4(Ah[im], sb + X_HI + off);
                        ldsm4(Al[im], sb + X_LO + off);
                    }
                    #pragma unroll
                    for (int nb = 0; nb < 2; nb++) {
                        int kr = ks + bkr;
                        uint32_t off = wsw((uint32_t)kr * 512 +
                                           (uint32_t)(wid * 32 + nb * 16 + bnb) * 2, kr);
                        ldsm4t(Bh[nb], wb + off);
                        ldsm4t(Bl[nb], wb + 16384 + off);
                    }
                    #pragma unroll
                    for (int im = 0; im < 4; im++)
                        #pragma unroll
                        for (int jn = 0; jn < 4; jn++)
                            mma16816(acc[im][jn], Ah[im], &Bh[jn >> 1][(jn & 1) * 2]);
                    #pragma unroll
                    for (int im = 0; im < 4; im++)
                        #pragma unroll
                        for (int jn = 0; jn < 4; jn++)
                            mma16816(acc[im][jn], Al[im], &Bh[jn >> 1][(jn & 1) * 2]);
                    #pragma unroll
                    for (int im = 0; im < 4; im++)
                        #pragma unroll
                        for (int jn = 0; jn < 4; jn++)
                            mma16816(acc[im][jn], Ah[im], &Bl[jn >> 1][(jn & 1) * 2]);
                }
            }
            // epilogue: + bias -> g_K / g_V
            #pragma unroll
            for (int im = 0; im < 4; im++)
                #pragma unroll
                for (int jn = 0; jn < 4; jn++) {
                    int col = wid * 32 + jn * 8 + 2 * tig;
                    float bb0 = bp[col], bb1 = bp[col + 1];
                    #pragma unroll
                    for (int hf = 0; hf < 2; hf++) {
                        size_t row = ebase + im * 16 + g + hf * 8;
                        *(float2*)(gout + row * DM + col) =
                            make_float2(acc[im][jn][hf * 2]     + bb0,
                                        acc[im][jn][hf * 2 + 1] + bb1);
                    }
                }
        }
    }
}

// ---------------- Q projection ----------------------------------------------
__global__ __launch_bounds__(256) void qproj_kernel(
    const float* __restrict__ x, const float* __restrict__ qp,
    const float* __restrict__ qb)
{
    __shared__ float s_x[QT * DM];
    const int tid = threadIdx.x;
    const size_t rbase = (size_t)blockIdx.x * QT;
    {
        const float4* xg = (const float4*)(x + rbase * DM);
        float4* sx = (float4*)s_x;
        sx[tid]       = xg[tid];
        sx[tid + 256] = xg[tid + 256];
    }
    __syncthreads();
    const int c = tid;
    const int h = c >> 6, e = c & 63;
    const float* W = qp + (size_t)h * DM * DK + e;
    float acc[QT];
    #pragma unroll
    for (int r = 0; r < QT; r++) acc[r] = 0.f;
    #pragma unroll 4
    for (int k = 0; k < DM; k++) {
        float w = W[(size_t)k * DK];
        #pragma unroll
        for (int r = 0; r < QT; r++) acc[r] += s_x[r * DM + k] * w;
    }
    float bb = qb[c];
    #pragma unroll
    for (int r = 0; r < QT; r++)
        g_Q[(rbase + r) * DM + c] = acc[r] + bb;
}

// ---------------- attention over 32 neighbors, one warp per head ------------
__global__ __launch_bounds__(128) void attn_kernel(const void* __restrict__ mask) {
    const int zn = blockIdx.x;
    const int tid = threadIdx.x;
    const int h = tid >> 5;
    const int lane = tid & 31;
    __shared__ float q_s[DM];
    q_s[tid]       = g_Q[(size_t)zn * DM + tid];
    q_s[tid + 128] = g_Q[(size_t)zn * DM + tid + 128];
    __syncthreads();

    const float* krow = g_K + ((size_t)zn * KI + lane) * DM + h * DK;
    float s = 0.f;
    #pragma unroll
    for (int e = 0; e < DK; e += 4) {
        float4 kv = *(const float4*)(krow + e);
        s += q_s[h * DK + e]     * kv.x + q_s[h * DK + e + 1] * kv.y
           + q_s[h * DK + e + 2] * kv.z + q_s[h * DK + e + 3] * kv.w;
    }
    s *= 0.125f;

    int flag = g_mflag;
    size_t midx = (size_t)zn * KI + lane;
    bool mv;
    if (flag == 2)      mv = ((const unsigned char*)mask)[midx] != 0;
    else if (flag == 1) mv = ((const int*)mask)[midx] != 0;
    else                mv = ((const float*)mask)[midx] != 0.0f;
    bool inv = !mv;
    unsigned bal = __ballot_sync(0xffffffffu, inv);
    if (inv && bal != 0xffffffffu) s = __int_as_float(0xff800000);

    float mx = s;
    #pragma unroll
    for (int o = 16; o > 0; o >>= 1)
        mx = fmaxf(mx, __shfl_xor_sync(0xffffffffu, mx, o));
    float p = __expf(s - mx);
    float ps = p;
    #pragma unroll
    for (int o = 16; o > 0; o >>= 1)
        ps += __shfl_xor_sync(0xffffffffu, ps, o);
    p /= ps;

    const float* vbase = g_V + (size_t)zn * KI * DM + h * DK;
    float o0 = 0.f, o1 = 0.f;
    const int e = lane * 2;
    #pragma unroll 8
    for (int l2 = 0; l2 < KI; l2++) {
        float pv = __shfl_sync(0xffffffffu, p, l2);
        float2 vv = *(const float2*)(vbase + l2 * DM + e);
        o0 += pv * vv.x;
        o1 += pv * vv.y;
    }
    g_attn[(size_t)zn * DM + (e    ) * HN + h] = o0;
    g_attn[(size_t)zn * DM + (e + 1) * HN + h] = o1;
}

// ---------------- final projection ------------------------------------------
#define FMA_ROW(ACCI, A, W0, W1) \
    do { \
        (ACCI)[0] += (A)*(W0).x; (ACCI)[1] += (A)*(W0).y; \
        (ACCI)[2] += (A)*(W0).z; (ACCI)[3] += (A)*(W0).w; \
        (ACCI)[4] += (A)*(W1).x; (ACCI)[5] += (A)*(W1).y; \
        (ACCI)[6] += (A)*(W1).z; (ACCI)[7] += (A)*(W1).w; \
    } while (0)

__global__ __launch_bounds__(256) void outproj_kernel(float* __restrict__ out) {
    __shared__ float s_x[TILE * DM];
    const int tid = threadIdx.x;
    const int tx = tid & 31, ty = tid >> 5;
    const int c0 = tx * 8, r0 = ty * 4;
    const size_t rbase = (size_t)blockIdx.x * TILE;
    {
        const float4* xg = (const float4*)(g_attn + rbase * DM);
        float4* sx = (float4*)s_x;
        #pragma unroll
        for (int i = 0; i < 8; i++) sx[tid + i * 256] = xg[tid + i * 256];
    }
    __syncthreads();
    float acc[4][8];
    #pragma unroll
    for (int i = 0; i < 4; i++)
        #pragma unroll
        for (int j = 0; j < 8; j++) acc[i][j] = 0.f;
    for (int k = 0; k < DM; k += 4) {
        float4 av[4];
        #pragma unroll
        for (int i = 0; i < 4; i++)
            av[i] = *(const float4*)(s_x + (r0 + i) * DM + k);
        #pragma unroll
        for (int kk = 0; kk < 4; kk++) {
            float4 w0 = *(const float4*)(g_WoT + (size_t)(k + kk) * DM + c0);
            float4 w1 = *(const float4*)(g_WoT + (size_t)(k + kk) * DM + c0 + 4);
            #pragma unroll
            for (int i = 0; i < 4; i++) {
                float a = (&av[i].x)[kk];
                FMA_ROW(acc[i], a, w0, w1);
            }
        }
    }
    #pragma unroll
    for (int i = 0; i < 4; i++) {
        *(float4*)(out + (rbase + r0 + i) * DM + c0) =
            make_float4(acc[i][0], acc[i][1], acc[i][2], acc[i][3]);
        *(float4*)(out + (rbase + r0 + i) * DM + c0 + 4) =
            make_float4(acc[i][4], acc[i][5], acc[i][6], acc[i][7]);
    }
}

// ---------------------------------------------------------------------------
extern "C" void kernel_launch(void* const* d_in, const int* in_sizes, int n_in,
                              void* d_out, int out_size)
{
    const float* nodes_i = (const float*)d_in[0];
    const float* edges   = (const float*)d_in[1];
    const float* nodes_j = (const float*)d_in[2];
    const void*  nmask   = d_in[3];
    const float* fkW1 = (const float*)d_in[4];
    const float* fkb1 = (const float*)d_in[5];
    const float* fkW2 = (const float*)d_in[6];
    const float* fkb2 = (const float*)d_in[7];
    const float* fvW1 = (const float*)d_in[8];
    const float* fvb1 = (const float*)d_in[9];
    const float* fvW2 = (const float*)d_in[10];
    const float* fvb2 = (const float*)d_in[11];
    const float* qproj = (const float*)d_in[12];
    const float* kproj = (const float*)d_in[13];
    const float* vproj = (const float*)d_in[14];
    const float* qbias = (const float*)d_in[15];
    const float* kbias = (const float*)d_in[16];
    const float* vbias = (const float*)d_in[17];
    const float* outW  = (const float*)d_in[18];

    static int configured = 0;
    if (!configured) {
        cudaFuncSetAttribute(film_mma_kernel,
                             cudaFuncAttributeMaxDynamicSharedMemorySize, SMEM_TC);
        configured = 1;
    }

    detect_mask_kernel<<<1, 1>>>(nmask, in_sizes[3]);
    transpose_w_kernel<<<(DM * DM) / 256, 256>>>(outW);
    pack_w_kernel<<<524288 / 256, 256>>>(fkW1, fkW2, kproj, fvW1, fvW2, vproj);
    qproj_kernel<<<ZN / QT, 256>>>(nodes_i, qproj, qbias);
    film_mma_kernel<<<NB, 256, SMEM_TC>>>(
        edges, nodes_j, fkb1, fkb2, kbias, fvb1, fvb2, vbias);
    attn_kernel<<<ZN, 128>>>(nmask);
    outproj_kernel<<<ZN / TILE, 256>>>((float*)d_out);
}

// round 7
// speedup vs baseline: 4.1973x; 1.1141x over previous
#include <cuda_runtime.h>
#include <cuda_bf16.h>
#include <cstdint>

#define DM 256
#define KI 32
#define HN 4
#define DK 64
#define ZN 4096             /* Z*N   */
#define ETOT 131072         /* edges */
#define TILE 32
#define QT 16
#define MB 64               /* rows per film block */
#define NB (ETOT/MB)        /* 2048 film blocks */
#define FTH 512             /* film threads */

// film smem layout (bytes)
#define X_HI 0
#define X_LO 32768
#define Y_HI 65536
#define Y_LO 98304
#define WB0  131072         /* W slice buffers: 2 x 32KB (hi 16K + lo 16K) */
#define SMEM_TC 196608

// packed W: per path (1MB): s0 @0 (8 slices), s1 @256KB (16), s2 @768KB (8)
#define PATH_STRIDE 1048576
#define S1_OFF 262144
#define S2_OFF 786432

// ---------------- device scratch --------------------------------------------
__device__ float g_Q[(size_t)ZN * DM];
__device__ float g_K[(size_t)ETOT * DM];
__device__ float g_V[(size_t)ETOT * DM];
__device__ float g_attn[(size_t)ZN * DM];
__device__ float g_WoT[DM * DM];
__device__ int   g_mflag;
__device__ unsigned char g_Wp[2 * PATH_STRIDE];   // 2MB packed weights

// ---------------- asm helpers -----------------------------------------------
__device__ __forceinline__ uint32_t smem_u32(const void* p) {
    uint32_t a;
    asm("{ .reg .u64 t; cvta.to.shared.u64 t, %1; cvt.u32.u64 %0, t; }" : "=r"(a) : "l"(p));
    return a;
}
__device__ __forceinline__ void cpasync16(uint32_t d, const void* s) {
    asm volatile("cp.async.cg.shared.global [%0], [%1], 16;" :: "r"(d), "l"(s) : "memory");
}
#define CP_COMMIT() asm volatile("cp.async.commit_group;" ::: "memory")
#define CP_WAIT0()  asm volatile("cp.async.wait_group 0;" ::: "memory")
__device__ __forceinline__ void ldsm4(uint32_t* r, uint32_t addr) {
    asm volatile("ldmatrix.sync.aligned.m8n8.x4.shared.b16 {%0,%1,%2,%3}, [%4];"
        : "=r"(r[0]), "=r"(r[1]), "=r"(r[2]), "=r"(r[3]) : "r"(addr));
}
__device__ __forceinline__ void ldsm4t(uint32_t* r, uint32_t addr) {
    asm volatile("ldmatrix.sync.aligned.m8n8.x4.trans.shared.b16 {%0,%1,%2,%3}, [%4];"
        : "=r"(r[0]), "=r"(r[1]), "=r"(r[2]), "=r"(r[3]) : "r"(addr));
}
__device__ __forceinline__ void mma16816(float* d, const uint32_t* a, const uint32_t* b) {
    asm volatile("mma.sync.aligned.m16n8k16.row.col.f32.bf16.bf16.f32 "
        "{%0,%1,%2,%3}, {%4,%5,%6,%7}, {%8,%9}, {%0,%1,%2,%3};"
        : "+f"(d[0]), "+f"(d[1]), "+f"(d[2]), "+f"(d[3])
        : "r"(a[0]), "r"(a[1]), "r"(a[2]), "r"(a[3]), "r"(b[0]), "r"(b[1]));
}
__device__ __forceinline__ uint32_t pack_bf2(__nv_bfloat16 a, __nv_bfloat16 b) {
    return ((uint32_t)__bfloat16_as_ushort(b) << 16) | __bfloat16_as_ushort(a);
}
// A smem: [r<64][c<256] bf16, row 512B, XOR bits[6:4] with r&7
__device__ __forceinline__ uint32_t a_off(int r, int c) {
    uint32_t o = ((uint32_t)r << 9) + ((uint32_t)c << 1);
    return o ^ (((uint32_t)r & 7u) << 4);
}
// W slice swizzle
__device__ __forceinline__ uint32_t wsw(uint32_t o, int k) {
    return o ^ (((uint32_t)k & 7u) << 4);
}
__device__ __forceinline__ void split2b(char* smem, int hib, int lob,
                                        int r, int c, float x0, float x1) {
    __nv_bfloat16 h0 = __float2bfloat16(x0), h1 = __float2bfloat16(x1);
    __nv_bfloat16 l0 = __float2bfloat16(x0 - __bfloat162float(h0));
    __nv_bfloat16 l1 = __float2bfloat16(x1 - __bfloat162float(h1));
    uint32_t off = a_off(r, c);
    *(uint32_t*)(smem + hib + off) = pack_bf2(h0, h1);
    *(uint32_t*)(smem + lob + off) = pack_bf2(l0, l1);
}

// ---------------- setup kernels ---------------------------------------------
__global__ void detect_mask_kernel(const void* mask, int count) {
    if (threadIdx.x != 0 || blockIdx.x != 0) return;
    const unsigned int* u  = (const unsigned int*)mask;
    const float*        fp = (const float*)mask;
    int words = count / 4;
    int lim = words < 1024 ? words : 1024;
    bool int_ok = true, int_one = false, flt_ok = true, flt_one = false;
    for (int i = 0; i < lim; i++) {
        unsigned int v = u[i];
        if (v > 1u)  int_ok = false;
        if (v == 1u) int_one = true;
        float fv = fp[i];
        if (fv != 0.0f && fv != 1.0f) flt_ok = false;
        if (fv == 1.0f) flt_one = true;
    }
    g_mflag = (int_ok && int_one) ? 1 : (flt_ok && flt_one) ? 0 : 2;
}
__global__ void transpose_w_kernel(const float* __restrict__ W) {
    int idx = blockIdx.x * blockDim.x + threadIdx.x;
    if (idx < DM * DM) g_WoT[(idx & 255) * DM + (idx >> 8)] = W[idx];
}

// pack weights: per path, per stage, k-slice images (hi 16KB + lo 16KB).
__global__ __launch_bounds__(256) void pack_w_kernel(
    const float* __restrict__ fkW1, const float* __restrict__ fkW2,
    const float* __restrict__ kproj,
    const float* __restrict__ fvW1, const float* __restrict__ fvW2,
    const float* __restrict__ vproj)
{
    int idx = blockIdx.x * 256 + threadIdx.x;   // 524288 total
    int f = idx >> 18;
    int r = idx & 262143;
    float w;
    size_t dst;
    if (r < 65536) {                       // s0: W1, KS=32, N=256
        int k = r >> 8, n = r & 255;
        const float* W1 = f ? fvW1 : fkW1;
        w = W1[k * 256 + n];
        int q = k >> 5, kk = k & 31;
        dst = (size_t)f * PATH_STRIDE + (size_t)q * 32768
            + wsw((uint32_t)kk * 512 + (uint32_t)n * 2, kk);
    } else if (r < 196608) {               // s1: W2 gamma/beta interleave, KS=16, N=512
        int e = r - 65536;
        int k = e >> 9, n = e & 511;
        int wg = n >> 6, j = n & 63;
        int gc = wg * 32 + ((j >> 4) << 3) + (j & 7);
        int src = ((j >> 3) & 1) ? 256 + gc : gc;
        const float* W2 = f ? fvW2 : fkW2;
        w = W2[k * 512 + src];
        int q = k >> 4, kk = k & 15;
        dst = (size_t)f * PATH_STRIDE + S1_OFF + (size_t)q * 32768
            + wsw((uint32_t)kk * 1024 + (uint32_t)n * 2, kk);
    } else {                               // s2: head proj, KS=32, N=256
        int e = r - 196608;
        int k = e >> 8, n = e & 255;
        const float* P = f ? vproj : kproj;
        w = P[(n >> 6) * 16384 + k * 64 + (n & 63)];
        int q = k >> 5, kk = k & 31;
        dst = (size_t)f * PATH_STRIDE + S2_OFF + (size_t)q * 32768
            + wsw((uint32_t)kk * 512 + (uint32_t)n * 2, kk);
    }
    __nv_bfloat16 hi = __float2bfloat16(w);
    __nv_bfloat16 lo = __float2bfloat16(w - __bfloat162float(hi));
    *(unsigned short*)(g_Wp + dst)         = __bfloat16_as_ushort(hi);
    *(unsigned short*)(g_Wp + dst + 16384) = __bfloat16_as_ushort(lo);
}

// ---------------- warp-MMA FiLM + K/V (512 threads, 4 warps/SMSP) -----------
__global__ __launch_bounds__(FTH, 1) void film_mma_kernel(
    const float* __restrict__ edges, const float* __restrict__ nodesj,
    const float* __restrict__ fkb1, const float* __restrict__ fkb2,
    const float* __restrict__ kbias,
    const float* __restrict__ fvb1, const float* __restrict__ fvb2,
    const float* __restrict__ vbias)
{
    extern __shared__ char smem[];
    const uint32_t sb = smem_u32(smem);
    const int tid  = threadIdx.x;
    const int wid  = tid >> 5, lane = tid & 31;
    const int mw   = wid & 1, nw = wid >> 1;     // 2 M-groups x 8 N-groups
    const int g    = lane >> 2, tig = lane & 3;
    const size_t ebase = (size_t)blockIdx.x * MB;

    const int amr = lane & 15;
    const int akb = (lane >> 4) << 3;
    const int bkr = lane & 15;
    const int bnb = (lane >> 4) << 3;

    #pragma unroll 1
    for (int f = 0; f < 2; f++) {
        const float* b1 = f ? fvb1 : fkb1;
        const float* b2 = f ? fvb2 : fkb2;
        const float* bp = f ? vbias : kbias;
        float* gout = f ? g_V : g_K;
        const unsigned char* pbase = g_Wp + (size_t)f * PATH_STRIDE;

        // ================= stage 0: h = silu(edges @ W1 + b1) =================
        {
            __syncthreads();
            const unsigned char* wsrc = pbase;
            #pragma unroll
            for (int i = 0; i < 4; i++)
                cpasync16(sb + WB0 + tid * 16 + i * 8192, wsrc + tid * 16 + i * 8192);
            CP_COMMIT();

            {
                const float* asrc = edges + ebase * DM;
                #pragma unroll 1
                for (int i = 0; i < 8; i++) {
                    int fi = tid + i * FTH;
                    int rr = fi >> 6;
                    int cc = (fi & 63) << 2;
                    float4 v = *(const float4*)(asrc + ((size_t)fi << 2));
                    split2b(smem, X_HI, X_LO, rr, cc,     v.x, v.y);
                    split2b(smem, X_HI, X_LO, rr, cc + 2, v.z, v.w);
                }
            }

            float acc[2][4][4];
            #pragma unroll
            for (int a = 0; a < 2; a++)
                #pragma unroll
                for (int b = 0; b < 4; b++)
                    #pragma unroll
                    for (int c = 0; c < 4; c++) acc[a][b][c] = 0.f;

            #pragma unroll 1
            for (int q = 0; q < 8; q++) {
                CP_WAIT0();
                __syncthreads();
                if (q + 1 < 8) {
                    const unsigned char* ns = wsrc + (size_t)(q + 1) * 32768;
                    uint32_t nd = sb + WB0 + ((q + 1) & 1) * 32768;
                    #pragma unroll
                    for (int i = 0; i < 4; i++)
                        cpasync16(nd + tid * 16 + i * 8192, ns + tid * 16 + i * 8192);
                    CP_COMMIT();
                }
                uint32_t wb = sb + WB0 + (q & 1) * 32768;
                #pragma unroll
                for (int ki = 0; ki < 2; ki++) {
                    int kc = q * 32 + ki * 16;
                    int ks = ki * 16;
                    uint32_t Ah[2][4], Al[2][4], Bh[2][4], Bl[2][4];
                    #pragma unroll
                    for (int im = 0; im < 2; im++) {
                        uint32_t off = a_off(mw * 32 + im * 16 + amr, kc + akb);
                        ldsm4(Ah[im], sb + X_HI + off);
                        ldsm4(Al[im], sb + X_LO + off);
                    }
                    #pragma unroll
                    for (int nb = 0; nb < 2; nb++) {
                        int kr = ks + bkr;
                        uint32_t off = wsw((uint32_t)kr * 512 +
                                           (uint32_t)(nw * 32 + nb * 16 + bnb) * 2, kr);
                        ldsm4t(Bh[nb], wb + off);
                        ldsm4t(Bl[nb], wb + 16384 + off);
                    }
                    #pragma unroll
                    for (int im = 0; im < 2; im++)
                        #pragma unroll
                        for (int jn = 0; jn < 4; jn++)
                            mma16816(acc[im][jn], Ah[im], &Bh[jn >> 1][(jn & 1) * 2]);
                    #pragma unroll
                    for (int im = 0; im < 2; im++)
                        #pragma unroll
                        for (int jn = 0; jn < 4; jn++)
                            mma16816(acc[im][jn], Al[im], &Bh[jn >> 1][(jn & 1) * 2]);
                    #pragma unroll
                    for (int im = 0; im < 2; im++)
                        #pragma unroll
                        for (int jn = 0; jn < 4; jn++)
                            mma16816(acc[im][jn], Ah[im], &Bl[jn >> 1][(jn & 1) * 2]);
                }
            }
            #pragma unroll
            for (int im = 0; im < 2; im++)
                #pragma unroll
                for (int jn = 0; jn < 4; jn++) {
                    int col = nw * 32 + jn * 8 + 2 * tig;
                    float bb0 = b1[col], bb1 = b1[col + 1];
                    #pragma unroll
                    for (int hf = 0; hf < 2; hf++) {
                        int rr = mw * 32 + im * 16 + g + hf * 8;
                        float x0 = acc[im][jn][hf * 2]     + bb0;
                        float x1 = acc[im][jn][hf * 2 + 1] + bb1;
                        x0 = x0 / (1.0f + __expf(-x0));
                        x1 = x1 / (1.0f + __expf(-x1));
                        split2b(smem, Y_HI, Y_LO, rr, col, x0, x1);
                    }
                }
        }

        // ================= stage 1: gb = h @ W2; film -> X =====================
        {
            __syncthreads();
            const unsigned char* wsrc = pbase + S1_OFF;
            #pragma unroll
            for (int i = 0; i < 4; i++)
                cpasync16(sb + WB0 + tid * 16 + i * 8192, wsrc + tid * 16 + i * 8192);
            CP_COMMIT();

            float acc[2][8][4];
            #pragma unroll
            for (int a = 0; a < 2; a++)
                #pragma unroll
                for (int b = 0; b < 8; b++)
                    #pragma unroll
                    for (int c = 0; c < 4; c++) acc[a][b][c] = 0.f;

            #pragma unroll 1
            for (int q = 0; q < 16; q++) {
                CP_WAIT0();
                __syncthreads();
                if (q + 1 < 16) {
                    const unsigned char* ns = wsrc + (size_t)(q + 1) * 32768;
                    uint32_t nd = sb + WB0 + ((q + 1) & 1) * 32768;
                    #pragma unroll
                    for (int i = 0; i < 4; i++)
                        cpasync16(nd + tid * 16 + i * 8192, ns + tid * 16 + i * 8192);
                    CP_COMMIT();
                }
                uint32_t wb = sb + WB0 + (q & 1) * 32768;
                int kc = q * 16;
                uint32_t Ah[2][4], Al[2][4];
                #pragma unroll
                for (int im = 0; im < 2; im++) {
                    uint32_t off = a_off(mw * 32 + im * 16 + amr, kc + akb);
                    ldsm4(Ah[im], sb + Y_HI + off);
                    ldsm4(Al[im], sb + Y_LO + off);
                }
                #pragma unroll
                for (int jg = 0; jg < 4; jg++) {
                    uint32_t Bh[4], Bl[4];
                    uint32_t off = wsw((uint32_t)bkr * 1024 +
                                       (uint32_t)(nw * 64 + jg * 16 + bnb) * 2, bkr);
                    ldsm4t(Bh, wb + off);
                    ldsm4t(Bl, wb + 16384 + off);
                    #pragma unroll
                    for (int im = 0; im < 2; im++) {
                        mma16816(acc[im][jg * 2],     Ah[im], &Bh[0]);
                        mma16816(acc[im][jg * 2 + 1], Ah[im], &Bh[2]);
                    }
                    #pragma unroll
                    for (int im = 0; im < 2; im++) {
                        mma16816(acc[im][jg * 2],     Al[im], &Bh[0]);
                        mma16816(acc[im][jg * 2 + 1], Al[im], &Bh[2]);
                    }
                    #pragma unroll
                    for (int im = 0; im < 2; im++) {
                        mma16816(acc[im][jg * 2],     Ah[im], &Bl[0]);
                        mma16816(acc[im][jg * 2 + 1], Ah[im], &Bl[2]);
                    }
                }
            }
            #pragma unroll
            for (int im = 0; im < 2; im++)
                #pragma unroll
                for (int t = 0; t < 4; t++) {
                    int gc = nw * 32 + t * 8 + 2 * tig;
                    float bg0 = b2[gc],       bg1 = b2[gc + 1];
                    float bb0 = b2[256 + gc], bb1 = b2[256 + gc + 1];
                    #pragma unroll
                    for (int hf = 0; hf < 2; hf++) {
                        int rr = mw * 32 + im * 16 + g + hf * 8;
                        float2 nj = *(const float2*)(nodesj + (ebase + rr) * DM + gc);
                        float ga0 = acc[im][t * 2][hf * 2]         + bg0;
                        float ga1 = acc[im][t * 2][hf * 2 + 1]     + bg1;
                        float be0 = acc[im][t * 2 + 1][hf * 2]     + bb0;
                        float be1 = acc[im][t * 2 + 1][hf * 2 + 1] + bb1;
                        split2b(smem, X_HI, X_LO, rr, gc,
                                ga0 * nj.x + be0, ga1 * nj.y + be1);
                    }
                }
        }

        // ================= stage 2: KV = k_in @ proj + bias -> global =========
        {
            __syncthreads();
            const unsigned char* wsrc = pbase + S2_OFF;
            #pragma unroll
            for (int i = 0; i < 4; i++)
                cpasync16(sb + WB0 + tid * 16 + i * 8192, wsrc + tid * 16 + i * 8192);
            CP_COMMIT();

            float acc[2][4][4];
            #pragma unroll
            for (int a = 0; a < 2; a++)
                #pragma unroll
                for (int b = 0; b < 4; b++)
                    #pragma unroll
                    for (int c = 0; c < 4; c++) acc[a][b][c] = 0.f;

            #pragma unroll 1
            for (int q = 0; q < 8; q++) {
                CP_WAIT0();
                __syncthreads();
                if (q + 1 < 8) {
                    const unsigned char* ns = wsrc + (size_t)(q + 1) * 32768;
                    uint32_t nd = sb + WB0 + ((q + 1) & 1) * 32768;
                    #pragma unroll
                    for (int i = 0; i < 4; i++)
                        cpasync16(nd + tid * 16 + i * 8192, ns + tid * 16 + i * 8192);
                    CP_COMMIT();
                }
                uint32_t wb = sb + WB0 + (q & 1) * 32768;
                #pragma unroll
                for (int ki = 0; ki < 2; ki++) {
                    int kc = q * 32 + ki * 16;
                    int ks = ki * 16;
                    uint32_t Ah[2][4], Al[2][4], Bh[2][4], Bl[2][4];
                    #pragma unroll
                    for (int im = 0; im < 2; im++) {
                        uint32_t off = a_off(mw * 32 + im * 16 + amr, kc + akb);
                        ldsm4(Ah[im], sb + X_HI + off);
                        ldsm4(Al[im], sb + X_LO + off);
                    }
                    #pragma unroll
                    for (int nb = 0; nb < 2; nb++) {
                        int kr = ks + bkr;
                        uint32_t off = wsw((uint32_t)kr * 512 +
                                           (uint32_t)(nw * 32 + nb * 16 + bnb) * 2, kr);
                        ldsm4t(Bh[nb], wb + off);
                        ldsm4t(Bl[nb], wb + 16384 + off);
                    }
                    #pragma unroll
                    for (int im = 0; im < 2; im++)
                        #pragma unroll
                        for (int jn = 0; jn < 4; jn++)
                            mma16816(acc[im][jn], Ah[im], &Bh[jn >> 1][(jn & 1) * 2]);
                    #pragma unroll
                    for (int im = 0; im < 2; im++)
                        #pragma unroll
                        for (int jn = 0; jn < 4; jn++)
                            mma16816(acc[im][jn], Al[im], &Bh[jn >> 1][(jn & 1) * 2]);
                    #pragma unroll
                    for (int im = 0; im < 2; im++)
                        #pragma unroll
                        for (int jn = 0; jn < 4; jn++)
                            mma16816(acc[im][jn], Ah[im], &Bl[jn >> 1][(jn & 1) * 2]);
                }
            }
            #pragma unroll
            for (int im = 0; im < 2; im++)
                #pragma unroll
                for (int jn = 0; jn < 4; jn++) {
                    int col = nw * 32 + jn * 8 + 2 * tig;
                    float bb0 = bp[col], bb1 = bp[col + 1];
                    #pragma unroll
                    for (int hf = 0; hf < 2; hf++) {
                        size_t row = ebase + mw * 32 + im * 16 + g + hf * 8;
                        *(float2*)(gout + row * DM + col) =
                            make_float2(acc[im][jn][hf * 2]     + bb0,
                                        acc[im][jn][hf * 2 + 1] + bb1);
                    }
                }
        }
    }
}

// ---------------- Q projection: 256 blocks x 16 rows -------------------------
__global__ __launch_bounds__(256) void qproj_kernel(
    const float* __restrict__ x, const float* __restrict__ qp,
    const float* __restrict__ qb)
{
    __shared__ float s_x[QT * DM];
    const int tid = threadIdx.x;
    const size_t rbase = (size_t)blockIdx.x * QT;
    {
        const float4* xg = (const float4*)(x + rbase * DM);
        float4* sx = (float4*)s_x;
        #pragma unroll
        for (int i = 0; i < 4; i++) sx[tid + i * 256] = xg[tid + i * 256];
    }
    __syncthreads();
    const int c = tid;
    const int h = c >> 6, e = c & 63;
    const float* W = qp + (size_t)h * DM * DK + e;
    float acc[QT];
    #pragma unroll
    for (int r = 0; r < QT; r++) acc[r] = 0.f;
    #pragma unroll 2
    for (int k = 0; k < DM; k += 4) {
        float w0 = W[(size_t)(k + 0) * DK];
        float w1 = W[(size_t)(k + 1) * DK];
        float w2 = W[(size_t)(k + 2) * DK];
        float w3 = W[(size_t)(k + 3) * DK];
        #pragma unroll
        for (int r = 0; r < QT; r++) {
            float4 xv = *(const float4*)(s_x + r * DM + k);
            acc[r] += xv.x * w0 + xv.y * w1 + xv.z * w2 + xv.w * w3;
        }
    }
    float bb = qb[c];
    #pragma unroll
    for (int r = 0; r < QT; r++)
        g_Q[(rbase + r) * DM + c] = acc[r] + bb;
}

// ---------------- attention over 32 neighbors, one warp per head ------------
__global__ __launch_bounds__(128) void attn_kernel(const void* __restrict__ mask) {
    const int zn = blockIdx.x;
    const int tid = threadIdx.x;
    const int h = tid >> 5;
    const int lane = tid & 31;
    __shared__ float q_s[DM];
    q_s[tid]       = g_Q[(size_t)zn * DM + tid];
    q_s[tid + 128] = g_Q[(size_t)zn * DM + tid + 128];
    __syncthreads();

    const float* krow = g_K + ((size_t)zn * KI + lane) * DM + h * DK;
    float s = 0.f;
    #pragma unroll
    for (int e = 0; e < DK; e += 4) {
        float4 kv = *(const float4*)(krow + e);
        s += q_s[h * DK + e]     * kv.x + q_s[h * DK + e + 1] * kv.y
           + q_s[h * DK + e + 2] * kv.z + q_s[h * DK + e + 3] * kv.w;
    }
    s *= 0.125f;

    int flag = g_mflag;
    size_t midx = (size_t)zn * KI + lane;
    bool mv;
    if (flag == 2)      mv = ((const unsigned char*)mask)[midx] != 0;
    else if (flag == 1) mv = ((const int*)mask)[midx] != 0;
    else                mv = ((const float*)mask)[midx] != 0.0f;
    bool inv = !mv;
    unsigned bal = __ballot_sync(0xffffffffu, inv);
    if (inv && bal != 0xffffffffu) s = __int_as_float(0xff800000);

    float mx = s;
    #pragma unroll
    for (int o = 16; o > 0; o >>= 1)
        mx = fmaxf(mx, __shfl_xor_sync(0xffffffffu, mx, o));
    float p = __expf(s - mx);
    float ps = p;
    #pragma unroll
    for (int o = 16; o > 0; o >>= 1)
        ps += __shfl_xor_sync(0xffffffffu, ps, o);
    p /= ps;

    const float* vbase = g_V + (size_t)zn * KI * DM + h * DK;
    float o0 = 0.f, o1 = 0.f;
    const int e = lane * 2;
    #pragma unroll 8
    for (int l2 = 0; l2 < KI; l2++) {
        float pv = __shfl_sync(0xffffffffu, p, l2);
        float2 vv = *(const float2*)(vbase + l2 * DM + e);
        o0 += pv * vv.x;
        o1 += pv * vv.y;
    }
    g_attn[(size_t)zn * DM + (e    ) * HN + h] = o0;
    g_attn[(size_t)zn * DM + (e + 1) * HN + h] = o1;
}

// ---------------- final projection ------------------------------------------
#define FMA_ROW(ACCI, A, W0, W1) \
    do { \
        (ACCI)[0] += (A)*(W0).x; (ACCI)[1] += (A)*(W0).y; \
        (ACCI)[2] += (A)*(W0).z; (ACCI)[3] += (A)*(W0).w; \
        (ACCI)[4] += (A)*(W1).x; (ACCI)[5] += (A)*(W1).y; \
        (ACCI)[6] += (A)*(W1).z; (ACCI)[7] += (A)*(W1).w; \
    } while (0)

__global__ __launch_bounds__(256) void outproj_kernel(float* __restrict__ out) {
    __shared__ float s_x[TILE * DM];
    const int tid = threadIdx.x;
    const int tx = tid & 31, ty = tid >> 5;
    const int c0 = tx * 8, r0 = ty * 4;
    const size_t rbase = (size_t)blockIdx.x * TILE;
    {
        const float4* xg = (const float4*)(g_attn + rbase * DM);
        float4* sx = (float4*)s_x;
        #pragma unroll
        for (int i = 0; i < 8; i++) sx[tid + i * 256] = xg[tid + i * 256];
    }
    __syncthreads();
    float acc[4][8];
    #pragma unroll
    for (int i = 0; i < 4; i++)
        #pragma unroll
        for (int j = 0; j < 8; j++) acc[i][j] = 0.f;
    for (int k = 0; k < DM; k += 4) {
        float4 av[4];
        #pragma unroll
        for (int i = 0; i < 4; i++)
            av[i] = *(const float4*)(s_x + (r0 + i) * DM + k);
        #pragma unroll
        for (int kk = 0; kk < 4; kk++) {
            float4 w0 = *(const float4*)(g_WoT + (size_t)(k + kk) * DM + c0);
            float4 w1 = *(const float4*)(g_WoT + (size_t)(k + kk) * DM + c0 + 4);
            #pragma unroll
            for (int i = 0; i < 4; i++) {
                float a = (&av[i].x)[kk];
                FMA_ROW(acc[i], a, w0, w1);
            }
        }
    }
    #pragma unroll
    for (int i = 0; i < 4; i++) {
        *(float4*)(out + (rbase + r0 + i) * DM + c0) =
            make_float4(acc[i][0], acc[i][1], acc[i][2], acc[i][3]);
        *(float4*)(out + (rbase + r0 + i) * DM + c0 + 4) =
            make_float4(acc[i][4], acc[i][5], acc[i][6], acc[i][7]);
    }
}

// ---------------------------------------------------------------------------
extern "C" void kernel_launch(void* const* d_in, const int* in_sizes, int n_in,
                              void* d_out, int out_size)
{
    const float* nodes_i = (const float*)d_in[0];
    const float* edges   = (const float*)d_in[1];
    const float* nodes_j = (const float*)d_in[2];
    const void*  nmask   = d_in[3];
    const float* fkW1 = (const float*)d_in[4];
    const float* fkb1 = (const float*)d_in[5];
    const float* fkW2 = (const float*)d_in[6];
    const float* fkb2 = (const float*)d_in[7];
    const float* fvW1 = (const float*)d_in[8];
    const float* fvb1 = (const float*)d_in[9];
    const float* fvW2 = (const float*)d_in[10];
    const float* fvb2 = (const float*)d_in[11];
    const float* qproj = (const float*)d_in[12];
    const float* kproj = (const float*)d_in[13];
    const float* vproj = (const float*)d_in[14];
    const float* qbias = (const float*)d_in[15];
    const float* kbias = (const float*)d_in[16];
    const float* vbias = (const float*)d_in[17];
    const float* outW  = (const float*)d_in[18];

    static int configured = 0;
    if (!configured) {
        cudaFuncSetAttribute(film_mma_kernel,
                             cudaFuncAttributeMaxDynamicSharedMemorySize, SMEM_TC);
        configured = 1;
    }

    detect_mask_kernel<<<1, 1>>>(nmask, in_sizes[3]);
    transpose_w_kernel<<<(DM * DM) / 256, 256>>>(outW);
    pack_w_kernel<<<524288 / 256, 256>>>(fkW1, fkW2, kproj, fvW1, fvW2, vproj);
    qproj_kernel<<<ZN / QT, 256>>>(nodes_i, qproj, qbias);
    film_mma_kernel<<<NB, FTH, SMEM_TC>>>(
        edges, nodes_j, fkb1, fkb2, kbias, fvb1, fvb2, vbias);
    attn_kernel<<<ZN, 128>>>(nmask);
    outproj_kernel<<<ZN / TILE, 256>>>((float*)d_out);
}

// round 8
// speedup vs baseline: 5.3910x; 1.2844x over previous
#include <cuda_runtime.h>
#include <cuda_fp16.h>
#include <cstdint>

#define DM 256
#define KI 32
#define HN 4
#define DK 64
#define ZN 4096             /* Z*N   */
#define ETOT 131072         /* edges */
#define TILE 32
#define QT 16
#define MB 64               /* rows per film block */
#define NB (ETOT/MB)        /* 2048 film blocks */
#define FTH 512             /* film threads */

// film smem layout (bytes)
#define X_HI 0
#define X_LO 32768
#define Y_HI 65536
#define Y_LO 98304
#define WB0  131072         /* W slice double buffer: 2 x 32KB */
#define SMEM_TC 196608

// packed W: 32 schedule-ordered 32KB slices (16 per path: s0 0-3, s1 4-11, s2 12-15)
#define SLICE 32768
#define NSLICES 32

// ---------------- device scratch --------------------------------------------
__device__ float g_Q[(size_t)ZN * DM];
__device__ float g_K[(size_t)ETOT * DM];
__device__ float g_V[(size_t)ETOT * DM];
__device__ float g_attn[(size_t)ZN * DM];
__device__ float g_WoT[DM * DM];
__device__ int   g_mflag;
__device__ unsigned char g_Wp[NSLICES * SLICE];   // 1MB packed fp16 weights

// ---------------- asm helpers -----------------------------------------------
__device__ __forceinline__ uint32_t smem_u32(const void* p) {
    uint32_t a;
    asm("{ .reg .u64 t; cvta.to.shared.u64 t, %1; cvt.u32.u64 %0, t; }" : "=r"(a) : "l"(p));
    return a;
}
__device__ __forceinline__ void cpasync16(uint32_t d, const void* s) {
    asm volatile("cp.async.cg.shared.global [%0], [%1], 16;" :: "r"(d), "l"(s) : "memory");
}
#define CP_COMMIT() asm volatile("cp.async.commit_group;" ::: "memory")
#define CP_WAIT0()  asm volatile("cp.async.wait_group 0;" ::: "memory")
__device__ __forceinline__ void ldsm4(uint32_t* r, uint32_t addr) {
    asm volatile("ldmatrix.sync.aligned.m8n8.x4.shared.b16 {%0,%1,%2,%3}, [%4];"
        : "=r"(r[0]), "=r"(r[1]), "=r"(r[2]), "=r"(r[3]) : "r"(addr));
}
__device__ __forceinline__ void ldsm4t(uint32_t* r, uint32_t addr) {
    asm volatile("ldmatrix.sync.aligned.m8n8.x4.trans.shared.b16 {%0,%1,%2,%3}, [%4];"
        : "=r"(r[0]), "=r"(r[1]), "=r"(r[2]), "=r"(r[3]) : "r"(addr));
}
__device__ __forceinline__ void mma16816(float* d, const uint32_t* a, const uint32_t* b) {
    asm volatile("mma.sync.aligned.m16n8k16.row.col.f32.f16.f16.f32 "
        "{%0,%1,%2,%3}, {%4,%5,%6,%7}, {%8,%9}, {%0,%1,%2,%3};"
        : "+f"(d[0]), "+f"(d[1]), "+f"(d[2]), "+f"(d[3])
        : "r"(a[0]), "r"(a[1]), "r"(a[2]), "r"(a[3]), "r"(b[0]), "r"(b[1]));
}
// A smem: [r<64][c<256] fp16, row 512B, XOR bits[6:4] with r&7
__device__ __forceinline__ uint32_t a_off(int r, int c) {
    uint32_t o = ((uint32_t)r << 9) + ((uint32_t)c << 1);
    return o ^ (((uint32_t)r & 7u) << 4);
}
__device__ __forceinline__ uint32_t wsw(uint32_t o, int k) {
    return o ^ (((uint32_t)k & 7u) << 4);
}
__device__ __forceinline__ void split2h(char* smem, int hib, int lob,
                                        int r, int c, float x0, float x1) {
    __half h0 = __float2half(x0), h1 = __float2half(x1);
    __half l0 = __float2half(x0 - __half2float(h0));
    __half l1 = __float2half(x1 - __half2float(h1));
    uint32_t off = a_off(r, c);
    *(uint32_t*)(smem + hib + off) =
        ((uint32_t)__half_as_ushort(h1) << 16) | __half_as_ushort(h0);
    *(uint32_t*)(smem + lob + off) =
        ((uint32_t)__half_as_ushort(l1) << 16) | __half_as_ushort(l0);
}

// ---------------- setup kernels ---------------------------------------------
__global__ void detect_mask_kernel(const void* mask, int count) {
    if (threadIdx.x != 0 || blockIdx.x != 0) return;
    const unsigned int* u  = (const unsigned int*)mask;
    const float*        fp = (const float*)mask;
    int words = count / 4;
    int lim = words < 1024 ? words : 1024;
    bool int_ok = true, int_one = false, flt_ok = true, flt_one = false;
    for (int i = 0; i < lim; i++) {
        unsigned int v = u[i];
        if (v > 1u)  int_ok = false;
        if (v == 1u) int_one = true;
        float fv = fp[i];
        if (fv != 0.0f && fv != 1.0f) flt_ok = false;
        if (fv == 1.0f) flt_one = true;
    }
    g_mflag = (int_ok && int_one) ? 1 : (flt_ok && flt_one) ? 0 : 2;
}
__global__ void transpose_w_kernel(const float* __restrict__ W) {
    int idx = blockIdx.x * blockDim.x + threadIdx.x;
    if (idx < DM * DM) g_WoT[(idx & 255) * DM + (idx >> 8)] = W[idx];
}

// pack weights: 32 schedule-ordered 32KB fp16 slice images.
// per path: t<4: s0 (k-slice 64, N=256, row 512B); t<12: s1 (k-slice 32, N=512,
// row 1024B, gamma/beta interleaved); else s2 (head proj, like s0).
__global__ __launch_bounds__(256) void pack_w_kernel(
    const float* __restrict__ fkW1, const float* __restrict__ fkW2,
    const float* __restrict__ kproj,
    const float* __restrict__ fvW1, const float* __restrict__ fvW2,
    const float* __restrict__ vproj)
{
    int idx = blockIdx.x * 256 + threadIdx.x;   // 524288 total
    int sc = idx >> 14;
    int e  = idx & 16383;
    int f = sc >> 4, t = sc & 15;
    float w;
    uint32_t off;
    if (t < 4) {
        int kk = e >> 8, n = e & 255;
        int k = t * 64 + kk;
        const float* W1 = f ? fvW1 : fkW1;
        w = W1[k * 256 + n];
        off = wsw((uint32_t)kk * 512 + (uint32_t)n * 2, kk);
    } else if (t < 12) {
        int kk = e >> 9, n = e & 511;
        int k = (t - 4) * 32 + kk;
        int wg = n >> 6, j = n & 63;
        int gc = wg * 32 + ((j >> 4) << 3) + (j & 7);
        int src = ((j >> 3) & 1) ? 256 + gc : gc;
        const float* W2 = f ? fvW2 : fkW2;
        w = W2[k * 512 + src];
        off = wsw((uint32_t)kk * 1024 + (uint32_t)n * 2, kk);
    } else {
        int kk = e >> 8, n = e & 255;
        int k = (t - 12) * 64 + kk;
        const float* P = f ? vproj : kproj;
        w = P[(n >> 6) * 16384 + k * 64 + (n & 63)];
        off = wsw((uint32_t)kk * 512 + (uint32_t)n * 2, kk);
    }
    *(unsigned short*)(g_Wp + (size_t)sc * SLICE + off) =
        __half_as_ushort(__float2half(w));
}

// ---------------- warp-MMA FiLM + K/V (fp16 2-term, 512 threads) ------------
__global__ __launch_bounds__(FTH, 1) void film_mma_kernel(
    const float* __restrict__ edges, const float* __restrict__ nodesj,
    const float* __restrict__ fkb1, const float* __restrict__ fkb2,
    const float* __restrict__ kbias,
    const float* __restrict__ fvb1, const float* __restrict__ fvb2,
    const float* __restrict__ vbias)
{
    extern __shared__ char smem[];
    const uint32_t sb = smem_u32(smem);
    const int tid  = threadIdx.x;
    const int wid  = tid >> 5, lane = tid & 31;
    const int mw   = wid & 1, nw = wid >> 1;     // 2 M-groups x 8 N-groups
    const int g    = lane >> 2, tig = lane & 3;
    const size_t ebase = (size_t)blockIdx.x * MB;

    const int amr = lane & 15;
    const int akb = (lane >> 4) << 3;
    const int bkr = lane & 15;
    const int bnb = (lane >> 4) << 3;

    // prefetch slice sc into buffer sc&1
    auto pf = [&](int sc) {
        const unsigned char* src = g_Wp + (size_t)sc * SLICE;
        uint32_t dst = sb + WB0 + (uint32_t)(sc & 1) * SLICE;
        #pragma unroll
        for (int i = 0; i < 4; i++)
            cpasync16(dst + tid * 16 + i * 8192, src + tid * 16 + i * 8192);
        CP_COMMIT();
    };
    // split edges tile into X (fp16 hi/lo)
    auto split_edges = [&]() {
        const float* asrc = edges + ebase * DM;
        #pragma unroll 1
        for (int i = 0; i < 8; i++) {
            int fi = tid + i * FTH;
            int rr = fi >> 6;
            int cc = (fi & 63) << 2;
            float4 v = *(const float4*)(asrc + ((size_t)fi << 2));
            split2h(smem, X_HI, X_LO, rr, cc,     v.x, v.y);
            split2h(smem, X_HI, X_LO, rr, cc + 2, v.z, v.w);
        }
    };

    pf(0);
    split_edges();
    int sc = 0;

    #pragma unroll 1
    for (int f = 0; f < 2; f++) {
        const float* b1 = f ? fvb1 : fkb1;
        const float* b2 = f ? fvb2 : fkb2;
        const float* bp = f ? vbias : kbias;
        float* gout = f ? g_V : g_K;

        if (f == 1) {            // X free after f=0 s2 MMAs; barrier then refill
            __syncthreads();
            split_edges();
        }

        // ================= stage 0: h = silu(edges @ W1 + b1) =================
        {
            float acc[2][4][4];
            #pragma unroll
            for (int a = 0; a < 2; a++)
                #pragma unroll
                for (int b = 0; b < 4; b++)
                    #pragma unroll
                    for (int c = 0; c < 4; c++) acc[a][b][c] = 0.f;

            #pragma unroll 1
            for (int q = 0; q < 4; q++) {
                CP_WAIT0();
                __syncthreads();
                if (sc + 1 < NSLICES) pf(sc + 1);
                uint32_t wb = sb + WB0 + (uint32_t)(sc & 1) * SLICE;
                #pragma unroll
                for (int ki = 0; ki < 4; ki++) {
                    int kc = q * 64 + ki * 16;
                    int kr = ki * 16 + bkr;
                    uint32_t Ah[2][4], Al[2][4], Bh[2][4];
                    #pragma unroll
                    for (int im = 0; im < 2; im++) {
                        uint32_t off = a_off(mw * 32 + im * 16 + amr, kc + akb);
                        ldsm4(Ah[im], sb + X_HI + off);
                        ldsm4(Al[im], sb + X_LO + off);
                    }
                    #pragma unroll
                    for (int nb = 0; nb < 2; nb++) {
                        uint32_t off = wsw((uint32_t)kr * 512 +
                                           (uint32_t)(nw * 32 + nb * 16 + bnb) * 2, kr);
                        ldsm4t(Bh[nb], wb + off);
                    }
                    #pragma unroll
                    for (int im = 0; im < 2; im++)
                        #pragma unroll
                        for (int jn = 0; jn < 4; jn++)
                            mma16816(acc[im][jn], Ah[im], &Bh[jn >> 1][(jn & 1) * 2]);
                    #pragma unroll
                    for (int im = 0; im < 2; im++)
                        #pragma unroll
                        for (int jn = 0; jn < 4; jn++)
                            mma16816(acc[im][jn], Al[im], &Bh[jn >> 1][(jn & 1) * 2]);
                }
                sc++;
            }
            #pragma unroll
            for (int im = 0; im < 2; im++)
                #pragma unroll
                for (int jn = 0; jn < 4; jn++) {
                    int col = nw * 32 + jn * 8 + 2 * tig;
                    float bb0 = b1[col], bb1 = b1[col + 1];
                    #pragma unroll
                    for (int hf = 0; hf < 2; hf++) {
                        int rr = mw * 32 + im * 16 + g + hf * 8;
                        float x0 = acc[im][jn][hf * 2]     + bb0;
                        float x1 = acc[im][jn][hf * 2 + 1] + bb1;
                        x0 = x0 / (1.0f + __expf(-x0));
                        x1 = x1 / (1.0f + __expf(-x1));
                        split2h(smem, Y_HI, Y_LO, rr, col, x0, x1);
                    }
                }
        }

        // ================= stage 1: gb = h @ W2; film -> X =====================
        {
            float acc[2][8][4];
            #pragma unroll
            for (int a = 0; a < 2; a++)
                #pragma unroll
                for (int b = 0; b < 8; b++)
                    #pragma unroll
                    for (int c = 0; c < 4; c++) acc[a][b][c] = 0.f;

            #pragma unroll 1
            for (int q = 0; q < 8; q++) {
                CP_WAIT0();
                __syncthreads();
                if (sc + 1 < NSLICES) pf(sc + 1);
                uint32_t wb = sb + WB0 + (uint32_t)(sc & 1) * SLICE;
                #pragma unroll
                for (int ki = 0; ki < 2; ki++) {
                    int kc = q * 32 + ki * 16;
                    int kr = ki * 16 + bkr;
                    uint32_t Ah[2][4], Al[2][4];
                    #pragma unroll
                    for (int im = 0; im < 2; im++) {
                        uint32_t off = a_off(mw * 32 + im * 16 + amr, kc + akb);
                        ldsm4(Ah[im], sb + Y_HI + off);
                        ldsm4(Al[im], sb + Y_LO + off);
                    }
                    #pragma unroll
                    for (int jg = 0; jg < 4; jg++) {
                        uint32_t Bh[4];
                        uint32_t off = wsw((uint32_t)kr * 1024 +
                                           (uint32_t)(nw * 64 + jg * 16 + bnb) * 2, kr);
                        ldsm4t(Bh, wb + off);
                        #pragma unroll
                        for (int im = 0; im < 2; im++) {
                            mma16816(acc[im][jg * 2],     Ah[im], &Bh[0]);
                            mma16816(acc[im][jg * 2 + 1], Ah[im], &Bh[2]);
                        }
                        #pragma unroll
                        for (int im = 0; im < 2; im++) {
                            mma16816(acc[im][jg * 2],     Al[im], &Bh[0]);
                            mma16816(acc[im][jg * 2 + 1], Al[im], &Bh[2]);
                        }
                    }
                }
                sc++;
            }
            #pragma unroll
            for (int im = 0; im < 2; im++)
                #pragma unroll
                for (int t = 0; t < 4; t++) {
                    int gc = nw * 32 + t * 8 + 2 * tig;
                    float bg0 = b2[gc],       bg1 = b2[gc + 1];
                    float bb0 = b2[256 + gc], bb1 = b2[256 + gc + 1];
                    #pragma unroll
                    for (int hf = 0; hf < 2; hf++) {
                        int rr = mw * 32 + im * 16 + g + hf * 8;
                        float2 nj = *(const float2*)(nodesj + (ebase + rr) * DM + gc);
                        float ga0 = acc[im][t * 2][hf * 2]         + bg0;
                        float ga1 = acc[im][t * 2][hf * 2 + 1]     + bg1;
                        float be0 = acc[im][t * 2 + 1][hf * 2]     + bb0;
                        float be1 = acc[im][t * 2 + 1][hf * 2 + 1] + bb1;
                        split2h(smem, X_HI, X_LO, rr, gc,
                                ga0 * nj.x + be0, ga1 * nj.y + be1);
                    }
                }
        }

        // ================= stage 2: KV = k_in @ proj + bias -> global =========
        {
            float acc[2][4][4];
            #pragma unroll
            for (int a = 0; a < 2; a++)
                #pragma unroll
                for (int b = 0; b < 4; b++)
                    #pragma unroll
                    for (int c = 0; c < 4; c++) acc[a][b][c] = 0.f;

            #pragma unroll 1
            for (int q = 0; q < 4; q++) {
                CP_WAIT0();
                __syncthreads();
                if (sc + 1 < NSLICES) pf(sc + 1);
                uint32_t wb = sb + WB0 + (uint32_t)(sc & 1) * SLICE;
                #pragma unroll
                for (int ki = 0; ki < 4; ki++) {
                    int kc = q * 64 + ki * 16;
                    int kr = ki * 16 + bkr;
                    uint32_t Ah[2][4], Al[2][4], Bh[2][4];
                    #pragma unroll
                    for (int im = 0; im < 2; im++) {
                        uint32_t off = a_off(mw * 32 + im * 16 + amr, kc + akb);
                        ldsm4(Ah[im], sb + X_HI + off);
                        ldsm4(Al[im], sb + X_LO + off);
                    }
                    #pragma unroll
                    for (int nb = 0; nb < 2; nb++) {
                        uint32_t off = wsw((uint32_t)kr * 512 +
                                           (uint32_t)(nw * 32 + nb * 16 + bnb) * 2, kr);
                        ldsm4t(Bh[nb], wb + off);
                    }
                    #pragma unroll
                    for (int im = 0; im < 2; im++)
                        #pragma unroll
                        for (int jn = 0; jn < 4; jn++)
                            mma16816(acc[im][jn], Ah[im], &Bh[jn >> 1][(jn & 1) * 2]);
                    #pragma unroll
                    for (int im = 0; im < 2; im++)
                        #pragma unroll
                        for (int jn = 0; jn < 4; jn++)
                            mma16816(acc[im][jn], Al[im], &Bh[jn >> 1][(jn & 1) * 2]);
                }
                sc++;
            }
            #pragma unroll
            for (int im = 0; im < 2; im++)
                #pragma unroll
                for (int jn = 0; jn < 4; jn++) {
                    int col = nw * 32 + jn * 8 + 2 * tig;
                    float bb0 = bp[col], bb1 = bp[col + 1];
                    #pragma unroll
                    for (int hf = 0; hf < 2; hf++) {
                        size_t row = ebase + mw * 32 + im * 16 + g + hf * 8;
                        *(float2*)(gout + row * DM + col) =
                            make_float2(acc[im][jn][hf * 2]     + bb0,
                                        acc[im][jn][hf * 2 + 1] + bb1);
                    }
                }
        }
    }
}

// ---------------- Q projection ----------------------------------------------
__global__ __launch_bounds__(256) void qproj_kernel(
    const float* __restrict__ x, const float* __restrict__ qp,
    const float* __restrict__ qb)
{
    __shared__ float s_x[QT * DM];
    const int tid = threadIdx.x;
    const size_t rbase = (size_t)blockIdx.x * QT;
    {
        const float4* xg = (const float4*)(x + rbase * DM);
        float4* sx = (float4*)s_x;
        #pragma unroll
        for (int i = 0; i < 4; i++) sx[tid + i * 256] = xg[tid + i * 256];
    }
    __syncthreads();
    const int c = tid;
    const int h = c >> 6, e = c & 63;
    const float* W = qp + (size_t)h * DM * DK + e;
    float acc[QT];
    #pragma unroll
    for (int r = 0; r < QT; r++) acc[r] = 0.f;
    #pragma unroll 2
    for (int k = 0; k < DM; k += 4) {
        float w0 = W[(size_t)(k + 0) * DK];
        float w1 = W[(size_t)(k + 1) * DK];
        float w2 = W[(size_t)(k + 2) * DK];
        float w3 = W[(size_t)(k + 3) * DK];
        #pragma unroll
        for (int r = 0; r < QT; r++) {
            float4 xv = *(const float4*)(s_x + r * DM + k);
            acc[r] += xv.x * w0 + xv.y * w1 + xv.z * w2 + xv.w * w3;
        }
    }
    float bb = qb[c];
    #pragma unroll
    for (int r = 0; r < QT; r++)
        g_Q[(rbase + r) * DM + c] = acc[r] + bb;
}

// ---------------- attention over 32 neighbors, one warp per head ------------
__global__ __launch_bounds__(128) void attn_kernel(const void* __restrict__ mask) {
    const int zn = blockIdx.x;
    const int tid = threadIdx.x;
    const int h = tid >> 5;
    const int lane = tid & 31;
    __shared__ float q_s[DM];
    q_s[tid]       = g_Q[(size_t)zn * DM + tid];
    q_s[tid + 128] = g_Q[(size_t)zn * DM + tid + 128];
    __syncthreads();

    const float* krow = g_K + ((size_t)zn * KI + lane) * DM + h * DK;
    float s = 0.f;
    #pragma unroll
    for (int e = 0; e < DK; e += 4) {
        float4 kv = *(const float4*)(krow + e);
        s += q_s[h * DK + e]     * kv.x + q_s[h * DK + e + 1] * kv.y
           + q_s[h * DK + e + 2] * kv.z + q_s[h * DK + e + 3] * kv.w;
    }
    s *= 0.125f;

    int flag = g_mflag;
    size_t midx = (size_t)zn * KI + lane;
    bool mv;
    if (flag == 2)      mv = ((const unsigned char*)mask)[midx] != 0;
    else if (flag == 1) mv = ((const int*)mask)[midx] != 0;
    else                mv = ((const float*)mask)[midx] != 0.0f;
    bool inv = !mv;
    unsigned bal = __ballot_sync(0xffffffffu, inv);
    if (inv && bal != 0xffffffffu) s = __int_as_float(0xff800000);

    float mx = s;
    #pragma unroll
    for (int o = 16; o > 0; o >>= 1)
        mx = fmaxf(mx, __shfl_xor_sync(0xffffffffu, mx, o));
    float p = __expf(s - mx);
    float ps = p;
    #pragma unroll
    for (int o = 16; o > 0; o >>= 1)
        ps += __shfl_xor_sync(0xffffffffu, ps, o);
    p /= ps;

    const float* vbase = g_V + (size_t)zn * KI * DM + h * DK;
    float o0 = 0.f, o1 = 0.f;
    const int e = lane * 2;
    #pragma unroll 8
    for (int l2 = 0; l2 < KI; l2++) {
        float pv = __shfl_sync(0xffffffffu, p, l2);
        float2 vv = *(const float2*)(vbase + l2 * DM + e);
        o0 += pv * vv.x;
        o1 += pv * vv.y;
    }
    g_attn[(size_t)zn * DM + (e    ) * HN + h] = o0;
    g_attn[(size_t)zn * DM + (e + 1) * HN + h] = o1;
}

// ---------------- final projection ------------------------------------------
#define FMA_ROW(ACCI, A, W0, W1) \
    do { \
        (ACCI)[0] += (A)*(W0).x; (ACCI)[1] += (A)*(W0).y; \
        (ACCI)[2] += (A)*(W0).z; (ACCI)[3] += (A)*(W0).w; \
        (ACCI)[4] += (A)*(W1).x; (ACCI)[5] += (A)*(W1).y; \
        (ACCI)[6] += (A)*(W1).z; (ACCI)[7] += (A)*(W1).w; \
    } while (0)

__global__ __launch_bounds__(256) void outproj_kernel(float* __restrict__ out) {
    __shared__ float s_x[TILE * DM];
    const int tid = threadIdx.x;
    const int tx = tid & 31, ty = tid >> 5;
    const int c0 = tx * 8, r0 = ty * 4;
    const size_t rbase = (size_t)blockIdx.x * TILE;
    {
        const float4* xg = (const float4*)(g_attn + rbase * DM);
        float4* sx = (float4*)s_x;
        #pragma unroll
        for (int i = 0; i < 8; i++) sx[tid + i * 256] = xg[tid + i * 256];
    }
    __syncthreads();
    float acc[4][8];
    #pragma unroll
    for (int i = 0; i < 4; i++)
        #pragma unroll
        for (int j = 0; j < 8; j++) acc[i][j] = 0.f;
    for (int k = 0; k < DM; k += 4) {
        float4 av[4];
        #pragma unroll
        for (int i = 0; i < 4; i++)
            av[i] = *(const float4*)(s_x + (r0 + i) * DM + k);
        #pragma unroll
        for (int kk = 0; kk < 4; kk++) {
            float4 w0 = *(const float4*)(g_WoT + (size_t)(k + kk) * DM + c0);
            float4 w1 = *(const float4*)(g_WoT + (size_t)(k + kk) * DM + c0 + 4);
            #pragma unroll
            for (int i = 0; i < 4; i++) {
                float a = (&av[i].x)[kk];
                FMA_ROW(acc[i], a, w0, w1);
            }
        }
    }
    #pragma unroll
    for (int i = 0; i < 4; i++) {
        *(float4*)(out + (rbase + r0 + i) * DM + c0) =
            make_float4(acc[i][0], acc[i][1], acc[i][2], acc[i][3]);
        *(float4*)(out + (rbase + r0 + i) * DM + c0 + 4) =
            make_float4(acc[i][4], acc[i][5], acc[i][6], acc[i][7]);
    }
}

// ---------------------------------------------------------------------------
extern "C" void kernel_launch(void* const* d_in, const int* in_sizes, int n_in,
                              void* d_out, int out_size)
{
    const float* nodes_i = (const float*)d_in[0];
    const float* edges   = (const float*)d_in[1];
    const float* nodes_j = (const float*)d_in[2];
    const void*  nmask   = d_in[3];
    const float* fkW1 = (const float*)d_in[4];
    const float* fkb1 = (const float*)d_in[5];
    const float* fkW2 = (const float*)d_in[6];
    const float* fkb2 = (const float*)d_in[7];
    const float* fvW1 = (const float*)d_in[8];
    const float* fvb1 = (const float*)d_in[9];
    const float* fvW2 = (const float*)d_in[10];
    const float* fvb2 = (const float*)d_in[11];
    const float* qproj = (const float*)d_in[12];
    const float* kproj = (const float*)d_in[13];
    const float* vproj = (const float*)d_in[14];
    const float* qbias = (const float*)d_in[15];
    const float* kbias = (const float*)d_in[16];
    const float* vbias = (const float*)d_in[17];
    const float* outW  = (const float*)d_in[18];

    static int configured = 0;
    if (!configured) {
        cudaFuncSetAttribute(film_mma_kernel,
                             cudaFuncAttributeMaxDynamicSharedMemorySize, SMEM_TC);
        configured = 1;
    }

    detect_mask_kernel<<<1, 1>>>(nmask, in_sizes[3]);
    transpose_w_kernel<<<(DM * DM) / 256, 256>>>(outW);
    pack_w_kernel<<<524288 / 256, 256>>>(fkW1, fkW2, kproj, fvW1, fvW2, vproj);
    qproj_kernel<<<ZN / QT, 256>>>(nodes_i, qproj, qbias);
    film_mma_kernel<<<NB, FTH, SMEM_TC>>>(
        edges, nodes_j, fkb1, fkb2, kbias, fvb1, fvb2, vbias);
    attn_kernel<<<ZN, 128>>>(nmask);
    outproj_kernel<<<ZN / TILE, 256>>>((float*)d_out);
}

// round 9
// speedup vs baseline: 7.8369x; 1.4537x over previous
#include <cuda_runtime.h>
#include <cuda_fp16.h>
#include <cstdint>

#define DM 256
#define KI 32
#define HN 4
#define DK 64
#define ZN 4096             /* Z*N   */
#define ETOT 131072         /* edges */
#define TILE 32
#define QT 16
#define MB 64               /* rows per film block */
#define NB (ETOT/MB)        /* 2048 film blocks */
#define FTH 512             /* film threads */

// film smem layout (bytes): pure fp16 A buffers
#define X_HI 0
#define Y_HI 32768
#define WB0  65536          /* W slice double buffer: 2 x 32KB */
#define SMEM_TC 131072

// packed W: 32 schedule-ordered 32KB slices (16 per path: s0 0-3, s1 4-11, s2 12-15)
#define SLICE 32768
#define NSLICES 32

// ---------------- device scratch --------------------------------------------
__device__ float g_Q[(size_t)ZN * DM];
__device__ float g_K[(size_t)ETOT * DM];
__device__ float g_V[(size_t)ETOT * DM];
__device__ float g_attn[(size_t)ZN * DM];
__device__ float g_WoT[DM * DM];
__device__ int   g_mflag;
__device__ unsigned char g_Wp[NSLICES * SLICE];   // 1MB packed fp16 weights

// ---------------- asm helpers -----------------------------------------------
__device__ __forceinline__ uint32_t smem_u32(const void* p) {
    uint32_t a;
    asm("{ .reg .u64 t; cvta.to.shared.u64 t, %1; cvt.u32.u64 %0, t; }" : "=r"(a) : "l"(p));
    return a;
}
__device__ __forceinline__ void cpasync16(uint32_t d, const void* s) {
    asm volatile("cp.async.cg.shared.global [%0], [%1], 16;" :: "r"(d), "l"(s) : "memory");
}
#define CP_COMMIT() asm volatile("cp.async.commit_group;" ::: "memory")
#define CP_WAIT0()  asm volatile("cp.async.wait_group 0;" ::: "memory")
__device__ __forceinline__ void ldsm4(uint32_t* r, uint32_t addr) {
    asm volatile("ldmatrix.sync.aligned.m8n8.x4.shared.b16 {%0,%1,%2,%3}, [%4];"
        : "=r"(r[0]), "=r"(r[1]), "=r"(r[2]), "=r"(r[3]) : "r"(addr));
}
__device__ __forceinline__ void ldsm4t(uint32_t* r, uint32_t addr) {
    asm volatile("ldmatrix.sync.aligned.m8n8.x4.trans.shared.b16 {%0,%1,%2,%3}, [%4];"
        : "=r"(r[0]), "=r"(r[1]), "=r"(r[2]), "=r"(r[3]) : "r"(addr));
}
__device__ __forceinline__ void mma16816(float* d, const uint32_t* a, const uint32_t* b) {
    asm volatile("mma.sync.aligned.m16n8k16.row.col.f32.f16.f16.f32 "
        "{%0,%1,%2,%3}, {%4,%5,%6,%7}, {%8,%9}, {%0,%1,%2,%3};"
        : "+f"(d[0]), "+f"(d[1]), "+f"(d[2]), "+f"(d[3])
        : "r"(a[0]), "r"(a[1]), "r"(a[2]), "r"(a[3]), "r"(b[0]), "r"(b[1]));
}
// A smem: [r<64][c<256] fp16, row 512B, XOR bits[6:4] with r&7
__device__ __forceinline__ uint32_t a_off(int r, int c) {
    uint32_t o = ((uint32_t)r << 9) + ((uint32_t)c << 1);
    return o ^ (((uint32_t)r & 7u) << 4);
}
__device__ __forceinline__ uint32_t wsw(uint32_t o, int k) {
    return o ^ (((uint32_t)k & 7u) << 4);
}
__device__ __forceinline__ void st2h(char* smem, int base, int r, int c,
                                     float x0, float x1) {
    uint32_t off = a_off(r, c);
    *(uint32_t*)(smem + base + off) =
        ((uint32_t)__half_as_ushort(__float2half(x1)) << 16)
        | __half_as_ushort(__float2half(x0));
}

// ---------------- setup kernels ---------------------------------------------
__global__ __launch_bounds__(256) void detect_mask_kernel(const void* mask, int count) {
    __shared__ int s_intbad, s_intone, s_fltbad, s_fltone;
    const int tid = threadIdx.x;
    if (tid == 0) { s_intbad = 0; s_intone = 0; s_fltbad = 0; s_fltone = 0; }
    __syncthreads();
    const unsigned int* u  = (const unsigned int*)mask;
    const float*        fp = (const float*)mask;
    int words = count / 4;
    int lim = words < 1024 ? words : 1024;
    int ib = 0, io = 0, fb = 0, fo = 0;
    for (int i = tid; i < lim; i += 256) {
        unsigned int v = u[i];
        if (v > 1u)  ib = 1;
        if (v == 1u) io = 1;
        float fv = fp[i];
        if (fv != 0.0f && fv != 1.0f) fb = 1;
        if (fv == 1.0f) fo = 1;
    }
    if (ib) atomicOr(&s_intbad, 1);
    if (io) atomicOr(&s_intone, 1);
    if (fb) atomicOr(&s_fltbad, 1);
    if (fo) atomicOr(&s_fltone, 1);
    __syncthreads();
    if (tid == 0) {
        g_mflag = (!s_intbad && s_intone) ? 1 : (!s_fltbad && s_fltone) ? 0 : 2;
    }
}
__global__ void transpose_w_kernel(const float* __restrict__ W) {
    int idx = blockIdx.x * blockDim.x + threadIdx.x;
    if (idx < DM * DM) g_WoT[(idx & 255) * DM + (idx >> 8)] = W[idx];
}

// pack weights: 32 schedule-ordered 32KB fp16 slice images.
__global__ __launch_bounds__(256) void pack_w_kernel(
    const float* __restrict__ fkW1, const float* __restrict__ fkW2,
    const float* __restrict__ kproj,
    const float* __restrict__ fvW1, const float* __restrict__ fvW2,
    const float* __restrict__ vproj)
{
    int idx = blockIdx.x * 256 + threadIdx.x;   // 524288 total
    int sc = idx >> 14;
    int e  = idx & 16383;
    int f = sc >> 4, t = sc & 15;
    float w;
    uint32_t off;
    if (t < 4) {
        int kk = e >> 8, n = e & 255;
        int k = t * 64 + kk;
        const float* W1 = f ? fvW1 : fkW1;
        w = W1[k * 256 + n];
        off = wsw((uint32_t)kk * 512 + (uint32_t)n * 2, kk);
    } else if (t < 12) {
        int kk = e >> 9, n = e & 511;
        int k = (t - 4) * 32 + kk;
        int wg = n >> 6, j = n & 63;
        int gc = wg * 32 + ((j >> 4) << 3) + (j & 7);
        int src = ((j >> 3) & 1) ? 256 + gc : gc;
        const float* W2 = f ? fvW2 : fkW2;
        w = W2[k * 512 + src];
        off = wsw((uint32_t)kk * 1024 + (uint32_t)n * 2, kk);
    } else {
        int kk = e >> 8, n = e & 255;
        int k = (t - 12) * 64 + kk;
        const float* P = f ? vproj : kproj;
        w = P[(n >> 6) * 16384 + k * 64 + (n & 63)];
        off = wsw((uint32_t)kk * 512 + (uint32_t)n * 2, kk);
    }
    *(unsigned short*)(g_Wp + (size_t)sc * SLICE + off) =
        __half_as_ushort(__float2half(w));
}

// ---------------- warp-MMA FiLM + K/V (pure fp16, 512 threads) --------------
__global__ __launch_bounds__(FTH, 1) void film_mma_kernel(
    const float* __restrict__ edges, const float* __restrict__ nodesj,
    const float* __restrict__ fkb1, const float* __restrict__ fkb2,
    const float* __restrict__ kbias,
    const float* __restrict__ fvb1, const float* __restrict__ fvb2,
    const float* __restrict__ vbias)
{
    extern __shared__ char smem[];
    const uint32_t sb = smem_u32(smem);
    const int tid  = threadIdx.x;
    const int wid  = tid >> 5, lane = tid & 31;
    const int mw   = wid & 1, nw = wid >> 1;     // 2 M-groups x 8 N-groups
    const int g    = lane >> 2, tig = lane & 3;
    const size_t ebase = (size_t)blockIdx.x * MB;

    const int amr = lane & 15;
    const int akb = (lane >> 4) << 3;
    const int bkr = lane & 15;
    const int bnb = (lane >> 4) << 3;

    auto pf = [&](int sc) {
        const unsigned char* src = g_Wp + (size_t)sc * SLICE;
        uint32_t dst = sb + WB0 + (uint32_t)(sc & 1) * SLICE;
        #pragma unroll
        for (int i = 0; i < 4; i++)
            cpasync16(dst + tid * 16 + i * 8192, src + tid * 16 + i * 8192);
        CP_COMMIT();
    };
    auto split_edges = [&]() {
        const float* asrc = edges + ebase * DM;
        #pragma unroll 1
        for (int i = 0; i < 8; i++) {
            int fi = tid + i * FTH;
            int rr = fi >> 6;
            int cc = (fi & 63) << 2;
            float4 v = *(const float4*)(asrc + ((size_t)fi << 2));
            st2h(smem, X_HI, rr, cc,     v.x, v.y);
            st2h(smem, X_HI, rr, cc + 2, v.z, v.w);
        }
    };

    pf(0);
    split_edges();
    int sc = 0;

    #pragma unroll 1
    for (int f = 0; f < 2; f++) {
        const float* b1 = f ? fvb1 : fkb1;
        const float* b2 = f ? fvb2 : fkb2;
        const float* bp = f ? vbias : kbias;
        float* gout = f ? g_V : g_K;

        if (f == 1) {
            __syncthreads();
            split_edges();
        }

        // ================= stage 0: h = silu(edges @ W1 + b1) =================
        {
            float acc[2][4][4];
            #pragma unroll
            for (int a = 0; a < 2; a++)
                #pragma unroll
                for (int b = 0; b < 4; b++)
                    #pragma unroll
                    for (int c = 0; c < 4; c++) acc[a][b][c] = 0.f;

            #pragma unroll 1
            for (int q = 0; q < 4; q++) {
                CP_WAIT0();
                __syncthreads();
                if (sc + 1 < NSLICES) pf(sc + 1);
                uint32_t wb = sb + WB0 + (uint32_t)(sc & 1) * SLICE;
                #pragma unroll
                for (int ki = 0; ki < 4; ki++) {
                    int kc = q * 64 + ki * 16;
                    int kr = ki * 16 + bkr;
                    uint32_t Ah[2][4], Bh[2][4];
                    #pragma unroll
                    for (int im = 0; im < 2; im++) {
                        uint32_t off = a_off(mw * 32 + im * 16 + amr, kc + akb);
                        ldsm4(Ah[im], sb + X_HI + off);
                    }
                    #pragma unroll
                    for (int nb = 0; nb < 2; nb++) {
                        uint32_t off = wsw((uint32_t)kr * 512 +
                                           (uint32_t)(nw * 32 + nb * 16 + bnb) * 2, kr);
                        ldsm4t(Bh[nb], wb + off);
                    }
                    #pragma unroll
                    for (int im = 0; im < 2; im++)
                        #pragma unroll
                        for (int jn = 0; jn < 4; jn++)
                            mma16816(acc[im][jn], Ah[im], &Bh[jn >> 1][(jn & 1) * 2]);
                }
                sc++;
            }
            #pragma unroll
            for (int im = 0; im < 2; im++)
                #pragma unroll
                for (int jn = 0; jn < 4; jn++) {
                    int col = nw * 32 + jn * 8 + 2 * tig;
                    float bb0 = b1[col], bb1 = b1[col + 1];
                    #pragma unroll
                    for (int hf = 0; hf < 2; hf++) {
                        int rr = mw * 32 + im * 16 + g + hf * 8;
                        float x0 = acc[im][jn][hf * 2]     + bb0;
                        float x1 = acc[im][jn][hf * 2 + 1] + bb1;
                        x0 = x0 / (1.0f + __expf(-x0));
                        x1 = x1 / (1.0f + __expf(-x1));
                        st2h(smem, Y_HI, rr, col, x0, x1);
                    }
                }
        }

        // ================= stage 1: gb = h @ W2; film -> X =====================
        {
            float acc[2][8][4];
            #pragma unroll
            for (int a = 0; a < 2; a++)
                #pragma unroll
                for (int b = 0; b < 8; b++)
                    #pragma unroll
                    for (int c = 0; c < 4; c++) acc[a][b][c] = 0.f;

            #pragma unroll 1
            for (int q = 0; q < 8; q++) {
                CP_WAIT0();
                __syncthreads();
                if (sc + 1 < NSLICES) pf(sc + 1);
                uint32_t wb = sb + WB0 + (uint32_t)(sc & 1) * SLICE;
                #pragma unroll
                for (int ki = 0; ki < 2; ki++) {
                    int kc = q * 32 + ki * 16;
                    int kr = ki * 16 + bkr;
                    uint32_t Ah[2][4];
                    #pragma unroll
                    for (int im = 0; im < 2; im++) {
                        uint32_t off = a_off(mw * 32 + im * 16 + amr, kc + akb);
                        ldsm4(Ah[im], sb + Y_HI + off);
                    }
                    #pragma unroll
                    for (int jg = 0; jg < 4; jg++) {
                        uint32_t Bh[4];
                        uint32_t off = wsw((uint32_t)kr * 1024 +
                                           (uint32_t)(nw * 64 + jg * 16 + bnb) * 2, kr);
                        ldsm4t(Bh, wb + off);
                        #pragma unroll
                        for (int im = 0; im < 2; im++) {
                            mma16816(acc[im][jg * 2],     Ah[im], &Bh[0]);
                            mma16816(acc[im][jg * 2 + 1], Ah[im], &Bh[2]);
                        }
                    }
                }
                sc++;
            }
            #pragma unroll
            for (int im = 0; im < 2; im++)
                #pragma unroll
                for (int t = 0; t < 4; t++) {
                    int gc = nw * 32 + t * 8 + 2 * tig;
                    float bg0 = b2[gc],       bg1 = b2[gc + 1];
                    float bb0 = b2[256 + gc], bb1 = b2[256 + gc + 1];
                    #pragma unroll
                    for (int hf = 0; hf < 2; hf++) {
                        int rr = mw * 32 + im * 16 + g + hf * 8;
                        float2 nj = *(const float2*)(nodesj + (ebase + rr) * DM + gc);
                        float ga0 = acc[im][t * 2][hf * 2]         + bg0;
                        float ga1 = acc[im][t * 2][hf * 2 + 1]     + bg1;
                        float be0 = acc[im][t * 2 + 1][hf * 2]     + bb0;
                        float be1 = acc[im][t * 2 + 1][hf * 2 + 1] + bb1;
                        st2h(smem, X_HI, rr, gc,
                             ga0 * nj.x + be0, ga1 * nj.y + be1);
                    }
                }
        }

        // ================= stage 2: KV = k_in @ proj + bias -> global =========
        {
            float acc[2][4][4];
            #pragma unroll
            for (int a = 0; a < 2; a++)
                #pragma unroll
                for (int b = 0; b < 4; b++)
                    #pragma unroll
                    for (int c = 0; c < 4; c++) acc[a][b][c] = 0.f;

            #pragma unroll 1
            for (int q = 0; q < 4; q++) {
                CP_WAIT0();
                __syncthreads();
                if (sc + 1 < NSLICES) pf(sc + 1);
                uint32_t wb = sb + WB0 + (uint32_t)(sc & 1) * SLICE;
                #pragma unroll
                for (int ki = 0; ki < 4; ki++) {
                    int kc = q * 64 + ki * 16;
                    int kr = ki * 16 + bkr;
                    uint32_t Ah[2][4], Bh[2][4];
                    #pragma unroll
                    for (int im = 0; im < 2; im++) {
                        uint32_t off = a_off(mw * 32 + im * 16 + amr, kc + akb);
                        ldsm4(Ah[im], sb + X_HI + off);
                    }
                    #pragma unroll
                    for (int nb = 0; nb < 2; nb++) {
                        uint32_t off = wsw((uint32_t)kr * 512 +
                                           (uint32_t)(nw * 32 + nb * 16 + bnb) * 2, kr);
                        ldsm4t(Bh[nb], wb + off);
                    }
                    #pragma unroll
                    for (int im = 0; im < 2; im++)
                        #pragma unroll
                        for (int jn = 0; jn < 4; jn++)
                            mma16816(acc[im][jn], Ah[im], &Bh[jn >> 1][(jn & 1) * 2]);
                }
                sc++;
            }
            #pragma unroll
            for (int im = 0; im < 2; im++)
                #pragma unroll
                for (int jn = 0; jn < 4; jn++) {
                    int col = nw * 32 + jn * 8 + 2 * tig;
                    float bb0 = bp[col], bb1 = bp[col + 1];
                    #pragma unroll
                    for (int hf = 0; hf < 2; hf++) {
                        size_t row = ebase + mw * 32 + im * 16 + g + hf * 8;
                        *(float2*)(gout + row * DM + col) =
                            make_float2(acc[im][jn][hf * 2]     + bb0,
                                        acc[im][jn][hf * 2 + 1] + bb1);
                    }
                }
        }
    }
}

// ---------------- Q projection ----------------------------------------------
__global__ __launch_bounds__(256) void qproj_kernel(
    const float* __restrict__ x, const float* __restrict__ qp,
    const float* __restrict__ qb)
{
    __shared__ float s_x[QT * DM];
    const int tid = threadIdx.x;
    const size_t rbase = (size_t)blockIdx.x * QT;
    {
        const float4* xg = (const float4*)(x + rbase * DM);
        float4* sx = (float4*)s_x;
        #pragma unroll
        for (int i = 0; i < 4; i++) sx[tid + i * 256] = xg[tid + i * 256];
    }
    __syncthreads();
    const int c = tid;
    const int h = c >> 6, e = c & 63;
    const float* W = qp + (size_t)h * DM * DK + e;
    float acc[QT];
    #pragma unroll
    for (int r = 0; r < QT; r++) acc[r] = 0.f;
    #pragma unroll 2
    for (int k = 0; k < DM; k += 4) {
        float w0 = W[(size_t)(k + 0) * DK];
        float w1 = W[(size_t)(k + 1) * DK];
        float w2 = W[(size_t)(k + 2) * DK];
        float w3 = W[(size_t)(k + 3) * DK];
        #pragma unroll
        for (int r = 0; r < QT; r++) {
            float4 xv = *(const float4*)(s_x + r * DM + k);
            acc[r] += xv.x * w0 + xv.y * w1 + xv.z * w2 + xv.w * w3;
        }
    }
    float bb = qb[c];
    #pragma unroll
    for (int r = 0; r < QT; r++)
        g_Q[(rbase + r) * DM + c] = acc[r] + bb;
}

// ---------------- attention over 32 neighbors, one warp per head ------------
__global__ __launch_bounds__(128) void attn_kernel(const void* __restrict__ mask) {
    const int zn = blockIdx.x;
    const int tid = threadIdx.x;
    const int h = tid >> 5;
    const int lane = tid & 31;
    __shared__ float q_s[DM];
    q_s[tid]       = g_Q[(size_t)zn * DM + tid];
    q_s[tid + 128] = g_Q[(size_t)zn * DM + tid + 128];
    __syncthreads();

    const float* krow = g_K + ((size_t)zn * KI + lane) * DM + h * DK;
    float s = 0.f;
    #pragma unroll
    for (int e = 0; e < DK; e += 4) {
        float4 kv = *(const float4*)(krow + e);
        s += q_s[h * DK + e]     * kv.x + q_s[h * DK + e + 1] * kv.y
           + q_s[h * DK + e + 2] * kv.z + q_s[h * DK + e + 3] * kv.w;
    }
    s *= 0.125f;

    int flag = g_mflag;
    size_t midx = (size_t)zn * KI + lane;
    bool mv;
    if (flag == 2)      mv = ((const unsigned char*)mask)[midx] != 0;
    else if (flag == 1) mv = ((const int*)mask)[midx] != 0;
    else                mv = ((const float*)mask)[midx] != 0.0f;
    bool inv = !mv;
    unsigned bal = __ballot_sync(0xffffffffu, inv);
    if (inv && bal != 0xffffffffu) s = __int_as_float(0xff800000);

    float mx = s;
    #pragma unroll
    for (int o = 16; o > 0; o >>= 1)
        mx = fmaxf(mx, __shfl_xor_sync(0xffffffffu, mx, o));
    float p = __expf(s - mx);
    float ps = p;
    #pragma unroll
    for (int o = 16; o > 0; o >>= 1)
        ps += __shfl_xor_sync(0xffffffffu, ps, o);
    p /= ps;

    const float* vbase = g_V + (size_t)zn * KI * DM + h * DK;
    float o0 = 0.f, o1 = 0.f;
    const int e = lane * 2;
    #pragma unroll 8
    for (int l2 = 0; l2 < KI; l2++) {
        float pv = __shfl_sync(0xffffffffu, p, l2);
        float2 vv = *(const float2*)(vbase + l2 * DM + e);
        o0 += pv * vv.x;
        o1 += pv * vv.y;
    }
    g_attn[(size_t)zn * DM + (e    ) * HN + h] = o0;
    g_attn[(size_t)zn * DM + (e + 1) * HN + h] = o1;
}

// ---------------- final projection (col-per-thread) --------------------------
__global__ __launch_bounds__(256) void outproj_kernel(float* __restrict__ out) {
    __shared__ float s_x[QT * DM];
    const int tid = threadIdx.x;
    const size_t rbase = (size_t)blockIdx.x * QT;
    {
        const float4* xg = (const float4*)(g_attn + rbase * DM);
        float4* sx = (float4*)s_x;
        #pragma unroll
        for (int i = 0; i < 4; i++) sx[tid + i * 256] = xg[tid + i * 256];
    }
    __syncthreads();
    const int c = tid;
    float acc[QT];
    #pragma unroll
    for (int r = 0; r < QT; r++) acc[r] = 0.f;
    #pragma unroll 2
    for (int k = 0; k < DM; k += 4) {
        float w0 = g_WoT[(size_t)(k + 0) * DM + c];
        float w1 = g_WoT[(size_t)(k + 1) * DM + c];
        float w2 = g_WoT[(size_t)(k + 2) * DM + c];
        float w3 = g_WoT[(size_t)(k + 3) * DM + c];
        #pragma unroll
        for (int r = 0; r < QT; r++) {
            float4 xv = *(const float4*)(s_x + r * DM + k);
            acc[r] += xv.x * w0 + xv.y * w1 + xv.z * w2 + xv.w * w3;
        }
    }
    #pragma unroll
    for (int r = 0; r < QT; r++)
        out[(rbase + r) * DM + c] = acc[r];
}

// ---------------------------------------------------------------------------
extern "C" void kernel_launch(void* const* d_in, const int* in_sizes, int n_in,
                              void* d_out, int out_size)
{
    const float* nodes_i = (const float*)d_in[0];
    const float* edges   = (const float*)d_in[1];
    const float* nodes_j = (const float*)d_in[2];
    const void*  nmask   = d_in[3];
    const float* fkW1 = (const float*)d_in[4];
    const float* fkb1 = (const float*)d_in[5];
    const float* fkW2 = (const float*)d_in[6];
    const float* fkb2 = (const float*)d_in[7];
    const float* fvW1 = (const float*)d_in[8];
    const float* fvb1 = (const float*)d_in[9];
    const float* fvW2 = (const float*)d_in[10];
    const float* fvb2 = (const float*)d_in[11];
    const float* qproj = (const float*)d_in[12];
    const float* kproj = (const float*)d_in[13];
    const float* vproj = (const float*)d_in[14];
    const float* qbias = (const float*)d_in[15];
    const float* kbias = (const float*)d_in[16];
    const float* vbias = (const float*)d_in[17];
    const float* outW  = (const float*)d_in[18];

    static int configured = 0;
    if (!configured) {
        cudaFuncSetAttribute(film_mma_kernel,
                             cudaFuncAttributeMaxDynamicSharedMemorySize, SMEM_TC);
        configured = 1;
    }

    detect_mask_kernel<<<1, 256>>>(nmask, in_sizes[3]);
    transpose_w_kernel<<<(DM * DM) / 256, 256>>>(outW);
    pack_w_kernel<<<524288 / 256, 256>>>(fkW1, fkW2, kproj, fvW1, fvW2, vproj);
    qproj_kernel<<<ZN / QT, 256>>>(nodes_i, qproj, qbias);
    film_mma_kernel<<<NB, FTH, SMEM_TC>>>(
        edges, nodes_j, fkb1, fkb2, kbias, fvb1, fvb2, vbias);
    attn_kernel<<<ZN, 128>>>(nmask);
    outproj_kernel<<<ZN / QT, 256>>>((float*)d_out);
}

// round 10
// speedup vs baseline: 8.0395x; 1.0259x over previous
#include <cuda_runtime.h>
#include <cuda_fp16.h>
#include <cstdint>

#define DM 256
#define KI 32
#define HN 4
#define DK 64
#define ZN 4096             /* Z*N   */
#define ETOT 131072         /* edges */
#define NT 8                /* nodes per tail block */
#define MB 64               /* rows per film block */
#define NB (ETOT/MB)        /* 2048 film blocks */
#define FTH 512             /* film threads */

// film smem layout (bytes): Y (hidden), X (film out), E (edges, persistent), W dbl-buf
#define Y_HI 0
#define X_HI 32768
#define E_HI 65536
#define WB0  98304
#define SMEM_TC 163840

// packed W: 32 schedule-ordered 32KB slices (16 per path: s0 0-3, s1 4-11, s2 12-15)
#define SLICE 32768
#define NSLICES 32

// ---------------- device scratch --------------------------------------------
__device__ float g_K[(size_t)ETOT * DM];
__device__ float g_V[(size_t)ETOT * DM];
__device__ float g_WoT[DM * DM];
__device__ int   g_mflag;
__device__ unsigned char g_Wp[NSLICES * SLICE];   // 1MB packed fp16 weights

// ---------------- asm helpers -----------------------------------------------
__device__ __forceinline__ uint32_t smem_u32(const void* p) {
    uint32_t a;
    asm("{ .reg .u64 t; cvta.to.shared.u64 t, %1; cvt.u32.u64 %0, t; }" : "=r"(a) : "l"(p));
    return a;
}
__device__ __forceinline__ void cpasync16(uint32_t d, const void* s) {
    asm volatile("cp.async.cg.shared.global [%0], [%1], 16;" :: "r"(d), "l"(s) : "memory");
}
#define CP_COMMIT() asm volatile("cp.async.commit_group;" ::: "memory")
#define CP_WAIT0()  asm volatile("cp.async.wait_group 0;" ::: "memory")
__device__ __forceinline__ void ldsm4(uint32_t* r, uint32_t addr) {
    asm volatile("ldmatrix.sync.aligned.m8n8.x4.shared.b16 {%0,%1,%2,%3}, [%4];"
        : "=r"(r[0]), "=r"(r[1]), "=r"(r[2]), "=r"(r[3]) : "r"(addr));
}
__device__ __forceinline__ void ldsm4t(uint32_t* r, uint32_t addr) {
    asm volatile("ldmatrix.sync.aligned.m8n8.x4.trans.shared.b16 {%0,%1,%2,%3}, [%4];"
        : "=r"(r[0]), "=r"(r[1]), "=r"(r[2]), "=r"(r[3]) : "r"(addr));
}
__device__ __forceinline__ void mma16816(float* d, const uint32_t* a, const uint32_t* b) {
    asm volatile("mma.sync.aligned.m16n8k16.row.col.f32.f16.f16.f32 "
        "{%0,%1,%2,%3}, {%4,%5,%6,%7}, {%8,%9}, {%0,%1,%2,%3};"
        : "+f"(d[0]), "+f"(d[1]), "+f"(d[2]), "+f"(d[3])
        : "r"(a[0]), "r"(a[1]), "r"(a[2]), "r"(a[3]), "r"(b[0]), "r"(b[1]));
}
// A smem: [r<64][c<256] fp16, row 512B, XOR bits[6:4] with r&7
__device__ __forceinline__ uint32_t a_off(int r, int c) {
    uint32_t o = ((uint32_t)r << 9) + ((uint32_t)c << 1);
    return o ^ (((uint32_t)r & 7u) << 4);
}
__device__ __forceinline__ uint32_t wsw(uint32_t o, int k) {
    return o ^ (((uint32_t)k & 7u) << 4);
}
__device__ __forceinline__ void st2h(char* smem, int base, int r, int c,
                                     float x0, float x1) {
    uint32_t off = a_off(r, c);
    *(uint32_t*)(smem + base + off) =
        ((uint32_t)__half_as_ushort(__float2half(x1)) << 16)
        | __half_as_ushort(__float2half(x0));
}

// ---------------- setup kernels ---------------------------------------------
__global__ __launch_bounds__(256) void detect_mask_kernel(const void* mask, int count) {
    __shared__ int s_intbad, s_intone, s_fltbad, s_fltone;
    const int tid = threadIdx.x;
    if (tid == 0) { s_intbad = 0; s_intone = 0; s_fltbad = 0; s_fltone = 0; }
    __syncthreads();
    const unsigned int* u  = (const unsigned int*)mask;
    const float*        fp = (const float*)mask;
    int words = count / 4;
    int lim = words < 1024 ? words : 1024;
    int ib = 0, io = 0, fb = 0, fo = 0;
    for (int i = tid; i < lim; i += 256) {
        unsigned int v = u[i];
        if (v > 1u)  ib = 1;
        if (v == 1u) io = 1;
        float fv = fp[i];
        if (fv != 0.0f && fv != 1.0f) fb = 1;
        if (fv == 1.0f) fo = 1;
    }
    if (ib) atomicOr(&s_intbad, 1);
    if (io) atomicOr(&s_intone, 1);
    if (fb) atomicOr(&s_fltbad, 1);
    if (fo) atomicOr(&s_fltone, 1);
    __syncthreads();
    if (tid == 0) {
        g_mflag = (!s_intbad && s_intone) ? 1 : (!s_fltbad && s_fltone) ? 0 : 2;
    }
}
__global__ void transpose_w_kernel(const float* __restrict__ W) {
    int idx = blockIdx.x * blockDim.x + threadIdx.x;
    if (idx < DM * DM) g_WoT[(idx & 255) * DM + (idx >> 8)] = W[idx];
}

// pack weights: 32 schedule-ordered 32KB fp16 slice images.
__global__ __launch_bounds__(256) void pack_w_kernel(
    const float* __restrict__ fkW1, const float* __restrict__ fkW2,
    const float* __restrict__ kproj,
    const float* __restrict__ fvW1, const float* __restrict__ fvW2,
    const float* __restrict__ vproj)
{
    int idx = blockIdx.x * 256 + threadIdx.x;   // 524288 total
    int sc = idx >> 14;
    int e  = idx & 16383;
    int f = sc >> 4, t = sc & 15;
    float w;
    uint32_t off;
    if (t < 4) {
        int kk = e >> 8, n = e & 255;
        int k = t * 64 + kk;
        const float* W1 = f ? fvW1 : fkW1;
        w = W1[k * 256 + n];
        off = wsw((uint32_t)kk * 512 + (uint32_t)n * 2, kk);
    } else if (t < 12) {
        int kk = e >> 9, n = e & 511;
        int k = (t - 4) * 32 + kk;
        int wg = n >> 6, j = n & 63;
        int gc = wg * 32 + ((j >> 4) << 3) + (j & 7);
        int src = ((j >> 3) & 1) ? 256 + gc : gc;
        const float* W2 = f ? fvW2 : fkW2;
        w = W2[k * 512 + src];
        off = wsw((uint32_t)kk * 1024 + (uint32_t)n * 2, kk);
    } else {
        int kk = e >> 8, n = e & 255;
        int k = (t - 12) * 64 + kk;
        const float* P = f ? vproj : kproj;
        w = P[(n >> 6) * 16384 + k * 64 + (n & 63)];
        off = wsw((uint32_t)kk * 512 + (uint32_t)n * 2, kk);
    }
    *(unsigned short*)(g_Wp + (size_t)sc * SLICE + off) =
        __half_as_ushort(__float2half(w));
}

// ---------------- warp-MMA FiLM + K/V (pure fp16, persistent E buffer) ------
__global__ __launch_bounds__(FTH, 1) void film_mma_kernel(
    const float* __restrict__ edges, const float* __restrict__ nodesj,
    const float* __restrict__ fkb1, const float* __restrict__ fkb2,
    const float* __restrict__ kbias,
    const float* __restrict__ fvb1, const float* __restrict__ fvb2,
    const float* __restrict__ vbias)
{
    extern __shared__ char smem[];
    const uint32_t sb = smem_u32(smem);
    const int tid  = threadIdx.x;
    const int wid  = tid >> 5, lane = tid & 31;
    const int mw   = wid & 1, nw = wid >> 1;     // 2 M-groups x 8 N-groups
    const int g    = lane >> 2, tig = lane & 3;
    const size_t ebase = (size_t)blockIdx.x * MB;

    const int amr = lane & 15;
    const int akb = (lane >> 4) << 3;
    const int bkr = lane & 15;
    const int bnb = (lane >> 4) << 3;

    auto pf = [&](int sc) {
        const unsigned char* src = g_Wp + (size_t)sc * SLICE;
        uint32_t dst = sb + WB0 + (uint32_t)(sc & 1) * SLICE;
        #pragma unroll
        for (int i = 0; i < 4; i++)
            cpasync16(dst + tid * 16 + i * 8192, src + tid * 16 + i * 8192);
        CP_COMMIT();
    };

    pf(0);
    {   // split edges once into persistent E buffer
        const float* asrc = edges + ebase * DM;
        #pragma unroll 1
        for (int i = 0; i < 8; i++) {
            int fi = tid + i * FTH;
            int rr = fi >> 6;
            int cc = (fi & 63) << 2;
            float4 v = *(const float4*)(asrc + ((size_t)fi << 2));
            st2h(smem, E_HI, rr, cc,     v.x, v.y);
            st2h(smem, E_HI, rr, cc + 2, v.z, v.w);
        }
    }
    int sc = 0;

    #pragma unroll 1
    for (int f = 0; f < 2; f++) {
        const float* b1 = f ? fvb1 : fkb1;
        const float* b2 = f ? fvb2 : fkb2;
        const float* bp = f ? vbias : kbias;
        float* gout = f ? g_V : g_K;

        // ================= stage 0: h = silu(E @ W1 + b1) -> Y ================
        {
            float acc[2][4][4];
            #pragma unroll
            for (int a = 0; a < 2; a++)
                #pragma unroll
                for (int b = 0; b < 4; b++)
                    #pragma unroll
                    for (int c = 0; c < 4; c++) acc[a][b][c] = 0.f;

            #pragma unroll 1
            for (int q = 0; q < 4; q++) {
                CP_WAIT0();
                __syncthreads();
                if (sc + 1 < NSLICES) pf(sc + 1);
                uint32_t wb = sb + WB0 + (uint32_t)(sc & 1) * SLICE;
                #pragma unroll
                for (int ki = 0; ki < 4; ki++) {
                    int kc = q * 64 + ki * 16;
                    int kr = ki * 16 + bkr;
                    uint32_t Ah[2][4], Bh[2][4];
                    #pragma unroll
                    for (int im = 0; im < 2; im++) {
                        uint32_t off = a_off(mw * 32 + im * 16 + amr, kc + akb);
                        ldsm4(Ah[im], sb + E_HI + off);
                    }
                    #pragma unroll
                    for (int nb = 0; nb < 2; nb++) {
                        uint32_t off = wsw((uint32_t)kr * 512 +
                                           (uint32_t)(nw * 32 + nb * 16 + bnb) * 2, kr);
                        ldsm4t(Bh[nb], wb + off);
                    }
                    #pragma unroll
                    for (int im = 0; im < 2; im++)
                        #pragma unroll
                        for (int jn = 0; jn < 4; jn++)
                            mma16816(acc[im][jn], Ah[im], &Bh[jn >> 1][(jn & 1) * 2]);
                }
                sc++;
            }
            #pragma unroll
            for (int im = 0; im < 2; im++)
                #pragma unroll
                for (int jn = 0; jn < 4; jn++) {
                    int col = nw * 32 + jn * 8 + 2 * tig;
                    float bb0 = b1[col], bb1 = b1[col + 1];
                    #pragma unroll
                    for (int hf = 0; hf < 2; hf++) {
                        int rr = mw * 32 + im * 16 + g + hf * 8;
                        float x0 = acc[im][jn][hf * 2]     + bb0;
                        float x1 = acc[im][jn][hf * 2 + 1] + bb1;
                        x0 = x0 / (1.0f + __expf(-x0));
                        x1 = x1 / (1.0f + __expf(-x1));
                        st2h(smem, Y_HI, rr, col, x0, x1);
                    }
                }
        }

        // ================= stage 1: gb = Y @ W2; film -> X =====================
        {
            float acc[2][8][4];
            #pragma unroll
            for (int a = 0; a < 2; a++)
                #pragma unroll
                for (int b = 0; b < 8; b++)
                    #pragma unroll
                    for (int c = 0; c < 4; c++) acc[a][b][c] = 0.f;

            #pragma unroll 1
            for (int q = 0; q < 8; q++) {
                CP_WAIT0();
                __syncthreads();
                if (sc + 1 < NSLICES) pf(sc + 1);
                uint32_t wb = sb + WB0 + (uint32_t)(sc & 1) * SLICE;
                #pragma unroll
                for (int ki = 0; ki < 2; ki++) {
                    int kc = q * 32 + ki * 16;
                    int kr = ki * 16 + bkr;
                    uint32_t Ah[2][4];
                    #pragma unroll
                    for (int im = 0; im < 2; im++) {
                        uint32_t off = a_off(mw * 32 + im * 16 + amr, kc + akb);
                        ldsm4(Ah[im], sb + Y_HI + off);
                    }
                    #pragma unroll
                    for (int jg = 0; jg < 4; jg++) {
                        uint32_t Bh[4];
                        uint32_t off = wsw((uint32_t)kr * 1024 +
                                           (uint32_t)(nw * 64 + jg * 16 + bnb) * 2, kr);
                        ldsm4t(Bh, wb + off);
                        #pragma unroll
                        for (int im = 0; im < 2; im++) {
                            mma16816(acc[im][jg * 2],     Ah[im], &Bh[0]);
                            mma16816(acc[im][jg * 2 + 1], Ah[im], &Bh[2]);
                        }
                    }
                }
                sc++;
            }
            #pragma unroll
            for (int im = 0; im < 2; im++)
                #pragma unroll
                for (int t = 0; t < 4; t++) {
                    int gc = nw * 32 + t * 8 + 2 * tig;
                    float bg0 = b2[gc],       bg1 = b2[gc + 1];
                    float bb0 = b2[256 + gc], bb1 = b2[256 + gc + 1];
                    #pragma unroll
                    for (int hf = 0; hf < 2; hf++) {
                        int rr = mw * 32 + im * 16 + g + hf * 8;
                        float2 nj = *(const float2*)(nodesj + (ebase + rr) * DM + gc);
                        float ga0 = acc[im][t * 2][hf * 2]         + bg0;
                        float ga1 = acc[im][t * 2][hf * 2 + 1]     + bg1;
                        float be0 = acc[im][t * 2 + 1][hf * 2]     + bb0;
                        float be1 = acc[im][t * 2 + 1][hf * 2 + 1] + bb1;
                        st2h(smem, X_HI, rr, gc,
                             ga0 * nj.x + be0, ga1 * nj.y + be1);
                    }
                }
        }

        // ================= stage 2: KV = X @ proj + bias -> global ============
        {
            float acc[2][4][4];
            #pragma unroll
            for (int a = 0; a < 2; a++)
                #pragma unroll
                for (int b = 0; b < 4; b++)
                    #pragma unroll
                    for (int c = 0; c < 4; c++) acc[a][b][c] = 0.f;

            #pragma unroll 1
            for (int q = 0; q < 4; q++) {
                CP_WAIT0();
                __syncthreads();
                if (sc + 1 < NSLICES) pf(sc + 1);
                uint32_t wb = sb + WB0 + (uint32_t)(sc & 1) * SLICE;
                #pragma unroll
                for (int ki = 0; ki < 4; ki++) {
                    int kc = q * 64 + ki * 16;
                    int kr = ki * 16 + bkr;
                    uint32_t Ah[2][4], Bh[2][4];
                    #pragma unroll
                    for (int im = 0; im < 2; im++) {
                        uint32_t off = a_off(mw * 32 + im * 16 + amr, kc + akb);
                        ldsm4(Ah[im], sb + X_HI + off);
                    }
                    #pragma unroll
                    for (int nb = 0; nb < 2; nb++) {
                        uint32_t off = wsw((uint32_t)kr * 512 +
                                           (uint32_t)(nw * 32 + nb * 16 + bnb) * 2, kr);
                        ldsm4t(Bh[nb], wb + off);
                    }
                    #pragma unroll
                    for (int im = 0; im < 2; im++)
                        #pragma unroll
                        for (int jn = 0; jn < 4; jn++)
                            mma16816(acc[im][jn], Ah[im], &Bh[jn >> 1][(jn & 1) * 2]);
                }
                sc++;
            }
            #pragma unroll
            for (int im = 0; im < 2; im++)
                #pragma unroll
                for (int jn = 0; jn < 4; jn++) {
                    int col = nw * 32 + jn * 8 + 2 * tig;
                    float bb0 = bp[col], bb1 = bp[col + 1];
                    #pragma unroll
                    for (int hf = 0; hf < 2; hf++) {
                        size_t row = ebase + mw * 32 + im * 16 + g + hf * 8;
                        *(float2*)(gout + row * DM + col) =
                            make_float2(acc[im][jn][hf * 2]     + bb0,
                                        acc[im][jn][hf * 2 + 1] + bb1);
                    }
                }
        }
    }
}

// ---------------- fused tail: Q proj + attention + out proj -----------------
__global__ __launch_bounds__(256) void tail_kernel(
    const float* __restrict__ nodes_i, const float* __restrict__ qp,
    const float* __restrict__ qb, const void* __restrict__ mask,
    float* __restrict__ out)
{
    __shared__ float s_x[NT * DM];     // nodes_i, later reused for attn output
    __shared__ float s_q[NT * DM];     // Q
    const int tid = threadIdx.x;
    const size_t nb = (size_t)blockIdx.x * NT;

    {   // load nodes_i tile
        const float4* xg = (const float4*)(nodes_i + nb * DM);
        float4* sx = (float4*)s_x;
        sx[tid]       = xg[tid];
        sx[tid + 256] = xg[tid + 256];
    }
    __syncthreads();

    // ---- Q projection, col-per-thread ----
    {
        const int c = tid;
        const int h = c >> 6, e = c & 63;
        const float* W = qp + (size_t)h * DM * DK + e;
        float acc[NT];
        #pragma unroll
        for (int r = 0; r < NT; r++) acc[r] = 0.f;
        #pragma unroll 2
        for (int k = 0; k < DM; k += 4) {
            float w0 = W[(size_t)(k + 0) * DK];
            float w1 = W[(size_t)(k + 1) * DK];
            float w2 = W[(size_t)(k + 2) * DK];
            float w3 = W[(size_t)(k + 3) * DK];
            #pragma unroll
            for (int r = 0; r < NT; r++) {
                float4 xv = *(const float4*)(s_x + r * DM + k);
                acc[r] += xv.x * w0 + xv.y * w1 + xv.z * w2 + xv.w * w3;
            }
        }
        float bb = qb[c];
        #pragma unroll
        for (int r = 0; r < NT; r++)
            s_q[r * DM + c] = acc[r] + bb;
    }
    __syncthreads();

    // ---- attention: warp w handles node w, 4 heads sequentially ----
    {
        const int wid = tid >> 5, lane = tid & 31;
        const size_t zn = nb + wid;

        int flag = g_mflag;
        size_t midx = zn * KI + lane;
        bool mv;
        if (flag == 2)      mv = ((const unsigned char*)mask)[midx] != 0;
        else if (flag == 1) mv = ((const int*)mask)[midx] != 0;
        else                mv = ((const float*)mask)[midx] != 0.0f;
        bool inv = !mv;
        unsigned bal = __ballot_sync(0xffffffffu, inv);
        bool kill = inv && (bal != 0xffffffffu);

        const float* krow  = g_K + (zn * KI + lane) * DM;
        const float* vbase = g_V + zn * KI * DM;
        const int e2 = lane * 2;

        #pragma unroll 1
        for (int h = 0; h < HN; h++) {
            const float* qrow = s_q + wid * DM + h * DK;
            const float* kh = krow + h * DK;
            float s = 0.f;
            #pragma unroll
            for (int e = 0; e < DK; e += 4) {
                float4 kv = *(const float4*)(kh + e);
                s += qrow[e] * kv.x + qrow[e + 1] * kv.y
                   + qrow[e + 2] * kv.z + qrow[e + 3] * kv.w;
            }
            s *= 0.125f;
            if (kill) s = __int_as_float(0xff800000);

            float mx = s;
            #pragma unroll
            for (int o = 16; o > 0; o >>= 1)
                mx = fmaxf(mx, __shfl_xor_sync(0xffffffffu, mx, o));
            float p = __expf(s - mx);
            float ps = p;
            #pragma unroll
            for (int o = 16; o > 0; o >>= 1)
                ps += __shfl_xor_sync(0xffffffffu, ps, o);
            p /= ps;

            const float* vh = vbase + h * DK;
            float o0 = 0.f, o1 = 0.f;
            #pragma unroll 8
            for (int l2 = 0; l2 < KI; l2++) {
                float pv = __shfl_sync(0xffffffffu, p, l2);
                float2 vv = *(const float2*)(vh + l2 * DM + e2);
                o0 += pv * vv.x;
                o1 += pv * vv.y;
            }
            // permuted layout: index = dk*H + h
            s_x[wid * DM + (e2    ) * HN + h] = o0;
            s_x[wid * DM + (e2 + 1) * HN + h] = o1;
        }
    }
    __syncthreads();

    // ---- out projection, col-per-thread ----
    {
        const int c = tid;
        float acc[NT];
        #pragma unroll
        for (int r = 0; r < NT; r++) acc[r] = 0.f;
        #pragma unroll 2
        for (int k = 0; k < DM; k += 4) {
            float w0 = g_WoT[(size_t)(k + 0) * DM + c];
            float w1 = g_WoT[(size_t)(k + 1) * DM + c];
            float w2 = g_WoT[(size_t)(k + 2) * DM + c];
            float w3 = g_WoT[(size_t)(k + 3) * DM + c];
            #pragma unroll
            for (int r = 0; r < NT; r++) {
                float4 xv = *(const float4*)(s_x + r * DM + k);
                acc[r] += xv.x * w0 + xv.y * w1 + xv.z * w2 + xv.w * w3;
            }
        }
        #pragma unroll
        for (int r = 0; r < NT; r++)
            out[(nb + r) * DM + c] = acc[r];
    }
}

// ---------------------------------------------------------------------------
extern "C" void kernel_launch(void* const* d_in, const int* in_sizes, int n_in,
                              void* d_out, int out_size)
{
    const float* nodes_i = (const float*)d_in[0];
    const float* edges   = (const float*)d_in[1];
    const float* nodes_j = (const float*)d_in[2];
    const void*  nmask   = d_in[3];
    const float* fkW1 = (const float*)d_in[4];
    const float* fkb1 = (const float*)d_in[5];
    const float* fkW2 = (const float*)d_in[6];
    const float* fkb2 = (const float*)d_in[7];
    const float* fvW1 = (const float*)d_in[8];
    const float* fvb1 = (const float*)d_in[9];
    const float* fvW2 = (const float*)d_in[10];
    const float* fvb2 = (const float*)d_in[11];
    const float* qproj = (const float*)d_in[12];
    const float* kproj = (const float*)d_in[13];
    const float* vproj = (const float*)d_in[14];
    const float* qbias = (const float*)d_in[15];
    const float* kbias = (const float*)d_in[16];
    const float* vbias = (const float*)d_in[17];
    const float* outW  = (const float*)d_in[18];

    static int configured = 0;
    if (!configured) {
        cudaFuncSetAttribute(film_mma_kernel,
                             cudaFuncAttributeMaxDynamicSharedMemorySize, SMEM_TC);
        configured = 1;
    }

    detect_mask_kernel<<<1, 256>>>(nmask, in_sizes[3]);
    transpose_w_kernel<<<(DM * DM) / 256, 256>>>(outW);
    pack_w_kernel<<<524288 / 256, 256>>>(fkW1, fkW2, kproj, fvW1, fvW2, vproj);
    film_mma_kernel<<<NB, FTH, SMEM_TC>>>(
        edges, nodes_j, fkb1, fkb2, kbias, fvb1, fvb2, vbias);
    tail_kernel<<<ZN / NT, 256>>>(nodes_i, qproj, qbias, nmask, (float*)d_out);
}

// round 11
// speedup vs baseline: 8.5431x; 1.0626x over previous
#include <cuda_runtime.h>
#include <cuda_fp16.h>
#include <cstdint>

#define DM 256
#define KI 32
#define HN 4
#define DK 64
#define ZN 4096             /* Z*N   */
#define ETOT 131072         /* edges */
#define NT 8                /* nodes per tail block */
#define MB 32               /* rows per film block */
#define NB (ETOT/MB)        /* 4096 film blocks */
#define FTH 256             /* film threads (8 warps), 2 CTAs/SM */

// film smem layout (bytes): Y (hidden), X (film out), E (edges), W dbl-buf
#define Y_HI 0
#define X_HI 16384
#define E_HI 32768
#define WB0  49152
#define SMEM_TC 114688

// packed W: 32 schedule-ordered 32KB slices (16 per path: s0 0-3, s1 4-11, s2 12-15)
#define SLICE 32768
#define NSLICES 32

// ---------------- device scratch --------------------------------------------
__device__ float g_K[(size_t)ETOT * DM];
__device__ float g_V[(size_t)ETOT * DM];
__device__ float g_WoT[DM * DM];
__device__ int   g_mflag;
__device__ unsigned char g_Wp[NSLICES * SLICE];   // 1MB packed fp16 weights

// ---------------- asm helpers -----------------------------------------------
__device__ __forceinline__ uint32_t smem_u32(const void* p) {
    uint32_t a;
    asm("{ .reg .u64 t; cvta.to.shared.u64 t, %1; cvt.u32.u64 %0, t; }" : "=r"(a) : "l"(p));
    return a;
}
__device__ __forceinline__ void cpasync16(uint32_t d, const void* s) {
    asm volatile("cp.async.cg.shared.global [%0], [%1], 16;" :: "r"(d), "l"(s) : "memory");
}
#define CP_COMMIT() asm volatile("cp.async.commit_group;" ::: "memory")
#define CP_WAIT0()  asm volatile("cp.async.wait_group 0;" ::: "memory")
__device__ __forceinline__ void ldsm4(uint32_t* r, uint32_t addr) {
    asm volatile("ldmatrix.sync.aligned.m8n8.x4.shared.b16 {%0,%1,%2,%3}, [%4];"
        : "=r"(r[0]), "=r"(r[1]), "=r"(r[2]), "=r"(r[3]) : "r"(addr));
}
__device__ __forceinline__ void ldsm4t(uint32_t* r, uint32_t addr) {
    asm volatile("ldmatrix.sync.aligned.m8n8.x4.trans.shared.b16 {%0,%1,%2,%3}, [%4];"
        : "=r"(r[0]), "=r"(r[1]), "=r"(r[2]), "=r"(r[3]) : "r"(addr));
}
__device__ __forceinline__ void mma16816(float* d, const uint32_t* a, const uint32_t* b) {
    asm volatile("mma.sync.aligned.m16n8k16.row.col.f32.f16.f16.f32 "
        "{%0,%1,%2,%3}, {%4,%5,%6,%7}, {%8,%9}, {%0,%1,%2,%3};"
        : "+f"(d[0]), "+f"(d[1]), "+f"(d[2]), "+f"(d[3])
        : "r"(a[0]), "r"(a[1]), "r"(a[2]), "r"(a[3]), "r"(b[0]), "r"(b[1]));
}
// A smem: [r<32][c<256] fp16, row 512B, XOR bits[6:4] with r&7
__device__ __forceinline__ uint32_t a_off(int r, int c) {
    uint32_t o = ((uint32_t)r << 9) + ((uint32_t)c << 1);
    return o ^ (((uint32_t)r & 7u) << 4);
}
__device__ __forceinline__ uint32_t wsw(uint32_t o, int k) {
    return o ^ (((uint32_t)k & 7u) << 4);
}
__device__ __forceinline__ void st2h(char* smem, int base, int r, int c,
                                     float x0, float x1) {
    uint32_t off = a_off(r, c);
    *(uint32_t*)(smem + base + off) =
        ((uint32_t)__half_as_ushort(__float2half(x1)) << 16)
        | __half_as_ushort(__float2half(x0));
}

// ---------------- setup kernels ---------------------------------------------
__global__ __launch_bounds__(256) void detect_mask_kernel(const void* mask, int count) {
    __shared__ int s_intbad, s_intone, s_fltbad, s_fltone;
    const int tid = threadIdx.x;
    if (tid == 0) { s_intbad = 0; s_intone = 0; s_fltbad = 0; s_fltone = 0; }
    __syncthreads();
    const unsigned int* u  = (const unsigned int*)mask;
    const float*        fp = (const float*)mask;
    int words = count / 4;
    int lim = words < 1024 ? words : 1024;
    int ib = 0, io = 0, fb = 0, fo = 0;
    for (int i = tid; i < lim; i += 256) {
        unsigned int v = u[i];
        if (v > 1u)  ib = 1;
        if (v == 1u) io = 1;
        float fv = fp[i];
        if (fv != 0.0f && fv != 1.0f) fb = 1;
        if (fv == 1.0f) fo = 1;
    }
    if (ib) atomicOr(&s_intbad, 1);
    if (io) atomicOr(&s_intone, 1);
    if (fb) atomicOr(&s_fltbad, 1);
    if (fo) atomicOr(&s_fltone, 1);
    __syncthreads();
    if (tid == 0) {
        g_mflag = (!s_intbad && s_intone) ? 1 : (!s_fltbad && s_fltone) ? 0 : 2;
    }
}
__global__ void transpose_w_kernel(const float* __restrict__ W) {
    int idx = blockIdx.x * blockDim.x + threadIdx.x;
    if (idx < DM * DM) g_WoT[(idx & 255) * DM + (idx >> 8)] = W[idx];
}

// pack weights: 32 schedule-ordered 32KB fp16 slice images.
__global__ __launch_bounds__(256) void pack_w_kernel(
    const float* __restrict__ fkW1, const float* __restrict__ fkW2,
    const float* __restrict__ kproj,
    const float* __restrict__ fvW1, const float* __restrict__ fvW2,
    const float* __restrict__ vproj)
{
    int idx = blockIdx.x * 256 + threadIdx.x;   // 524288 total
    int sc = idx >> 14;
    int e  = idx & 16383;
    int f = sc >> 4, t = sc & 15;
    float w;
    uint32_t off;
    if (t < 4) {
        int kk = e >> 8, n = e & 255;
        int k = t * 64 + kk;
        const float* W1 = f ? fvW1 : fkW1;
        w = W1[k * 256 + n];
        off = wsw((uint32_t)kk * 512 + (uint32_t)n * 2, kk);
    } else if (t < 12) {
        int kk = e >> 9, n = e & 511;
        int k = (t - 4) * 32 + kk;
        int wg = n >> 6, j = n & 63;
        int gc = wg * 32 + ((j >> 4) << 3) + (j & 7);
        int src = ((j >> 3) & 1) ? 256 + gc : gc;
        const float* W2 = f ? fvW2 : fkW2;
        w = W2[k * 512 + src];
        off = wsw((uint32_t)kk * 1024 + (uint32_t)n * 2, kk);
    } else {
        int kk = e >> 8, n = e & 255;
        int k = (t - 12) * 64 + kk;
        const float* P = f ? vproj : kproj;
        w = P[(n >> 6) * 16384 + k * 64 + (n & 63)];
        off = wsw((uint32_t)kk * 512 + (uint32_t)n * 2, kk);
    }
    *(unsigned short*)(g_Wp + (size_t)sc * SLICE + off) =
        __half_as_ushort(__float2half(w));
}

// ---------------- warp-MMA FiLM + K/V (fp16, MB=32, 2 CTAs/SM) --------------
__global__ __launch_bounds__(FTH, 2) void film_mma_kernel(
    const float* __restrict__ edges, const float* __restrict__ nodesj,
    const float* __restrict__ fkb1, const float* __restrict__ fkb2,
    const float* __restrict__ kbias,
    const float* __restrict__ fvb1, const float* __restrict__ fvb2,
    const float* __restrict__ vbias)
{
    extern __shared__ char smem[];
    const uint32_t sb = smem_u32(smem);
    const int tid  = threadIdx.x;
    const int nw   = tid >> 5, lane = tid & 31;   // 8 N-groups, 1 M-group
    const int g    = lane >> 2, tig = lane & 3;
    const size_t ebase = (size_t)blockIdx.x * MB;

    const int amr = lane & 15;
    const int akb = (lane >> 4) << 3;
    const int bkr = lane & 15;
    const int bnb = (lane >> 4) << 3;

    auto pf = [&](int sc) {
        const unsigned char* src = g_Wp + (size_t)sc * SLICE;
        uint32_t dst = sb + WB0 + (uint32_t)(sc & 1) * SLICE;
        #pragma unroll
        for (int i = 0; i < 8; i++)
            cpasync16(dst + tid * 16 + i * 4096, src + tid * 16 + i * 4096);
        CP_COMMIT();
    };

    pf(0);
    {   // split edges once into persistent E buffer (32 rows x 256 cols)
        const float* asrc = edges + ebase * DM;
        #pragma unroll 1
        for (int i = 0; i < 8; i++) {
            int fi = tid + i * FTH;              // 2048 float4
            int rr = fi >> 6;
            int cc = (fi & 63) << 2;
            float4 v = *(const float4*)(asrc + ((size_t)fi << 2));
            st2h(smem, E_HI, rr, cc,     v.x, v.y);
            st2h(smem, E_HI, rr, cc + 2, v.z, v.w);
        }
    }
    int sc = 0;

    #pragma unroll 1
    for (int f = 0; f < 2; f++) {
        const float* b1 = f ? fvb1 : fkb1;
        const float* b2 = f ? fvb2 : fkb2;
        const float* bp = f ? vbias : kbias;
        float* gout = f ? g_V : g_K;

        // ================= stage 0: h = silu(E @ W1 + b1) -> Y ================
        {
            float acc[2][4][4];
            #pragma unroll
            for (int a = 0; a < 2; a++)
                #pragma unroll
                for (int b = 0; b < 4; b++)
                    #pragma unroll
                    for (int c = 0; c < 4; c++) acc[a][b][c] = 0.f;

            #pragma unroll 1
            for (int q = 0; q < 4; q++) {
                CP_WAIT0();
                __syncthreads();
                if (sc + 1 < NSLICES) pf(sc + 1);
                uint32_t wb = sb + WB0 + (uint32_t)(sc & 1) * SLICE;
                #pragma unroll
                for (int ki = 0; ki < 4; ki++) {
                    int kc = q * 64 + ki * 16;
                    int kr = ki * 16 + bkr;
                    uint32_t Ah[2][4], Bh[2][4];
                    #pragma unroll
                    for (int im = 0; im < 2; im++) {
                        uint32_t off = a_off(im * 16 + amr, kc + akb);
                        ldsm4(Ah[im], sb + E_HI + off);
                    }
                    #pragma unroll
                    for (int nb = 0; nb < 2; nb++) {
                        uint32_t off = wsw((uint32_t)kr * 512 +
                                           (uint32_t)(nw * 32 + nb * 16 + bnb) * 2, kr);
                        ldsm4t(Bh[nb], wb + off);
                    }
                    #pragma unroll
                    for (int im = 0; im < 2; im++)
                        #pragma unroll
                        for (int jn = 0; jn < 4; jn++)
                            mma16816(acc[im][jn], Ah[im], &Bh[jn >> 1][(jn & 1) * 2]);
                }
                sc++;
            }
            #pragma unroll
            for (int im = 0; im < 2; im++)
                #pragma unroll
                for (int jn = 0; jn < 4; jn++) {
                    int col = nw * 32 + jn * 8 + 2 * tig;
                    float bb0 = b1[col], bb1 = b1[col + 1];
                    #pragma unroll
                    for (int hf = 0; hf < 2; hf++) {
                        int rr = im * 16 + g + hf * 8;
                        float x0 = acc[im][jn][hf * 2]     + bb0;
                        float x1 = acc[im][jn][hf * 2 + 1] + bb1;
                        x0 = x0 / (1.0f + __expf(-x0));
                        x1 = x1 / (1.0f + __expf(-x1));
                        st2h(smem, Y_HI, rr, col, x0, x1);
                    }
                }
        }

        // ================= stage 1: gb = Y @ W2; film -> X =====================
        {
            float acc[2][8][4];
            #pragma unroll
            for (int a = 0; a < 2; a++)
                #pragma unroll
                for (int b = 0; b < 8; b++)
                    #pragma unroll
                    for (int c = 0; c < 4; c++) acc[a][b][c] = 0.f;

            #pragma unroll 1
            for (int q = 0; q < 8; q++) {
                CP_WAIT0();
                __syncthreads();
                if (sc + 1 < NSLICES) pf(sc + 1);
                uint32_t wb = sb + WB0 + (uint32_t)(sc & 1) * SLICE;
                #pragma unroll
                for (int ki = 0; ki < 2; ki++) {
                    int kc = q * 32 + ki * 16;
                    int kr = ki * 16 + bkr;
                    uint32_t Ah[2][4];
                    #pragma unroll
                    for (int im = 0; im < 2; im++) {
                        uint32_t off = a_off(im * 16 + amr, kc + akb);
                        ldsm4(Ah[im], sb + Y_HI + off);
                    }
                    #pragma unroll
                    for (int jg = 0; jg < 4; jg++) {
                        uint32_t Bh[4];
                        uint32_t off = wsw((uint32_t)kr * 1024 +
                                           (uint32_t)(nw * 64 + jg * 16 + bnb) * 2, kr);
                        ldsm4t(Bh, wb + off);
                        #pragma unroll
                        for (int im = 0; im < 2; im++) {
                            mma16816(acc[im][jg * 2],     Ah[im], &Bh[0]);
                            mma16816(acc[im][jg * 2 + 1], Ah[im], &Bh[2]);
                        }
                    }
                }
                sc++;
            }
            #pragma unroll
            for (int im = 0; im < 2; im++)
                #pragma unroll
                for (int t = 0; t < 4; t++) {
                    int gc = nw * 32 + t * 8 + 2 * tig;
                    float bg0 = b2[gc],       bg1 = b2[gc + 1];
                    float bb0 = b2[256 + gc], bb1 = b2[256 + gc + 1];
                    #pragma unroll
                    for (int hf = 0; hf < 2; hf++) {
                        int rr = im * 16 + g + hf * 8;
                        float2 nj = *(const float2*)(nodesj + (ebase + rr) * DM + gc);
                        float ga0 = acc[im][t * 2][hf * 2]         + bg0;
                        float ga1 = acc[im][t * 2][hf * 2 + 1]     + bg1;
                        float be0 = acc[im][t * 2 + 1][hf * 2]     + bb0;
                        float be1 = acc[im][t * 2 + 1][hf * 2 + 1] + bb1;
                        st2h(smem, X_HI, rr, gc,
                             ga0 * nj.x + be0, ga1 * nj.y + be1);
                    }
                }
        }

        // ================= stage 2: KV = X @ proj + bias -> global ============
        {
            float acc[2][4][4];
            #pragma unroll
            for (int a = 0; a < 2; a++)
                #pragma unroll
                for (int b = 0; b < 4; b++)
                    #pragma unroll
                    for (int c = 0; c < 4; c++) acc[a][b][c] = 0.f;

            #pragma unroll 1
            for (int q = 0; q < 4; q++) {
                CP_WAIT0();
                __syncthreads();
                if (sc + 1 < NSLICES) pf(sc + 1);
                uint32_t wb = sb + WB0 + (uint32_t)(sc & 1) * SLICE;
                #pragma unroll
                for (int ki = 0; ki < 4; ki++) {
                    int kc = q * 64 + ki * 16;
                    int kr = ki * 16 + bkr;
                    uint32_t Ah[2][4], Bh[2][4];
                    #pragma unroll
                    for (int im = 0; im < 2; im++) {
                        uint32_t off = a_off(im * 16 + amr, kc + akb);
                        ldsm4(Ah[im], sb + X_HI + off);
                    }
                    #pragma unroll
                    for (int nb = 0; nb < 2; nb++) {
                        uint32_t off = wsw((uint32_t)kr * 512 +
                                           (uint32_t)(nw * 32 + nb * 16 + bnb) * 2, kr);
                        ldsm4t(Bh[nb], wb + off);
                    }
                    #pragma unroll
                    for (int im = 0; im < 2; im++)
                        #pragma unroll
                        for (int jn = 0; jn < 4; jn++)
                            mma16816(acc[im][jn], Ah[im], &Bh[jn >> 1][(jn & 1) * 2]);
                }
                sc++;
            }
            #pragma unroll
            for (int im = 0; im < 2; im++)
                #pragma unroll
                for (int jn = 0; jn < 4; jn++) {
                    int col = nw * 32 + jn * 8 + 2 * tig;
                    float bb0 = bp[col], bb1 = bp[col + 1];
                    #pragma unroll
                    for (int hf = 0; hf < 2; hf++) {
                        size_t row = ebase + im * 16 + g + hf * 8;
                        *(float2*)(gout + row * DM + col) =
                            make_float2(acc[im][jn][hf * 2]     + bb0,
                                        acc[im][jn][hf * 2 + 1] + bb1);
                    }
                }
        }
    }
}

// ---------------- fused tail: Q proj + attention + out proj -----------------
__global__ __launch_bounds__(256) void tail_kernel(
    const float* __restrict__ nodes_i, const float* __restrict__ qp,
    const float* __restrict__ qb, const void* __restrict__ mask,
    float* __restrict__ out)
{
    __shared__ float s_x[NT * DM];     // nodes_i, later reused for attn output
    __shared__ float s_q[NT * DM];     // Q
    const int tid = threadIdx.x;
    const size_t nb = (size_t)blockIdx.x * NT;

    {   // load nodes_i tile
        const float4* xg = (const float4*)(nodes_i + nb * DM);
        float4* sx = (float4*)s_x;
        sx[tid]       = xg[tid];
        sx[tid + 256] = xg[tid + 256];
    }
    __syncthreads();

    // ---- Q projection, col-per-thread ----
    {
        const int c = tid;
        const int h = c >> 6, e = c & 63;
        const float* W = qp + (size_t)h * DM * DK + e;
        float acc[NT];
        #pragma unroll
        for (int r = 0; r < NT; r++) acc[r] = 0.f;
        #pragma unroll 2
        for (int k = 0; k < DM; k += 4) {
            float w0 = W[(size_t)(k + 0) * DK];
            float w1 = W[(size_t)(k + 1) * DK];
            float w2 = W[(size_t)(k + 2) * DK];
            float w3 = W[(size_t)(k + 3) * DK];
            #pragma unroll
            for (int r = 0; r < NT; r++) {
                float4 xv = *(const float4*)(s_x + r * DM + k);
                acc[r] += xv.x * w0 + xv.y * w1 + xv.z * w2 + xv.w * w3;
            }
        }
        float bb = qb[c];
        #pragma unroll
        for (int r = 0; r < NT; r++)
            s_q[r * DM + c] = acc[r] + bb;
    }
    __syncthreads();

    // ---- attention: warp w handles node w, 4 heads sequentially ----
    {
        const int wid = tid >> 5, lane = tid & 31;
        const size_t zn = nb + wid;

        int flag = g_mflag;
        size_t midx = zn * KI + lane;
        bool mv;
        if (flag == 2)      mv = ((const unsigned char*)mask)[midx] != 0;
        else if (flag == 1) mv = ((const int*)mask)[midx] != 0;
        else                mv = ((const float*)mask)[midx] != 0.0f;
        bool inv = !mv;
        unsigned bal = __ballot_sync(0xffffffffu, inv);
        bool kill = inv && (bal != 0xffffffffu);

        const float* krow  = g_K + (zn * KI + lane) * DM;
        const float* vbase = g_V + zn * KI * DM;
        const int e2 = lane * 2;

        #pragma unroll 1
        for (int h = 0; h < HN; h++) {
            const float* qrow = s_q + wid * DM + h * DK;
            const float* kh = krow + h * DK;
            float s = 0.f;
            #pragma unroll
            for (int e = 0; e < DK; e += 4) {
                float4 kv = *(const float4*)(kh + e);
                s += qrow[e] * kv.x + qrow[e + 1] * kv.y
                   + qrow[e + 2] * kv.z + qrow[e + 3] * kv.w;
            }
            s *= 0.125f;
            if (kill) s = __int_as_float(0xff800000);

            float mx = s;
            #pragma unroll
            for (int o = 16; o > 0; o >>= 1)
                mx = fmaxf(mx, __shfl_xor_sync(0xffffffffu, mx, o));
            float p = __expf(s - mx);
            float ps = p;
            #pragma unroll
            for (int o = 16; o > 0; o >>= 1)
                ps += __shfl_xor_sync(0xffffffffu, ps, o);
            p /= ps;

            const float* vh = vbase + h * DK;
            float o0 = 0.f, o1 = 0.f;
            #pragma unroll 8
            for (int l2 = 0; l2 < KI; l2++) {
                float pv = __shfl_sync(0xffffffffu, p, l2);
                float2 vv = *(const float2*)(vh + l2 * DM + e2);
                o0 += pv * vv.x;
                o1 += pv * vv.y;
            }
            // permuted layout: index = dk*H + h
            s_x[wid * DM + (e2    ) * HN + h] = o0;
            s_x[wid * DM + (e2 + 1) * HN + h] = o1;
        }
    }
    __syncthreads();

    // ---- out projection, col-per-thread ----
    {
        const int c = tid;
        float acc[NT];
        #pragma unroll
        for (int r = 0; r < NT; r++) acc[r] = 0.f;
        #pragma unroll 2
        for (int k = 0; k < DM; k += 4) {
            float w0 = g_WoT[(size_t)(k + 0) * DM + c];
            float w1 = g_WoT[(size_t)(k + 1) * DM + c];
            float w2 = g_WoT[(size_t)(k + 2) * DM + c];
            float w3 = g_WoT[(size_t)(k + 3) * DM + c];
            #pragma unroll
            for (int r = 0; r < NT; r++) {
                float4 xv = *(const float4*)(s_x + r * DM + k);
                acc[r] += xv.x * w0 + xv.y * w1 + xv.z * w2 + xv.w * w3;
            }
        }
        #pragma unroll
        for (int r = 0; r < NT; r++)
            out[(nb + r) * DM + c] = acc[r];
    }
}

// ---------------------------------------------------------------------------
extern "C" void kernel_launch(void* const* d_in, const int* in_sizes, int n_in,
                              void* d_out, int out_size)
{
    const float* nodes_i = (const float*)d_in[0];
    const float* edges   = (const float*)d_in[1];
    const float* nodes_j = (const float*)d_in[2];
    const void*  nmask   = d_in[3];
    const float* fkW1 = (const float*)d_in[4];
    const float* fkb1 = (const float*)d_in[5];
    const float* fkW2 = (const float*)d_in[6];
    const float* fkb2 = (const float*)d_in[7];
    const float* fvW1 = (const float*)d_in[8];
    const float* fvb1 = (const float*)d_in[9];
    const float* fvW2 = (const float*)d_in[10];
    const float* fvb2 = (const float*)d_in[11];
    const float* qproj = (const float*)d_in[12];
    const float* kproj = (const float*)d_in[13];
    const float* vproj = (const float*)d_in[14];
    const float* qbias = (const float*)d_in[15];
    const float* kbias = (const float*)d_in[16];
    const float* vbias = (const float*)d_in[17];
    const float* outW  = (const float*)d_in[18];

    static int configured = 0;
    if (!configured) {
        cudaFuncSetAttribute(film_mma_kernel,
                             cudaFuncAttributeMaxDynamicSharedMemorySize, SMEM_TC);
        configured = 1;
    }

    detect_mask_kernel<<<1, 256>>>(nmask, in_sizes[3]);
    transpose_w_kernel<<<(DM * DM) / 256, 256>>>(outW);
    pack_w_kernel<<<524288 / 256, 256>>>(fkW1, fkW2, kproj, fvW1, fvW2, vproj);
    film_mma_kernel<<<NB, FTH, SMEM_TC>>>(
        edges, nodes_j, fkb1, fkb2, kbias, fvb1, fvb2, vbias);
    tail_kernel<<<ZN / NT, 256>>>(nodes_i, qproj, qbias, nmask, (float*)d_out);
}